// round 1
// baseline (speedup 1.0000x reference)
#include <cuda_runtime.h>
#include <cuda_bf16.h>
#include <cstddef>

// ---------------- problem geometry (fixed by setup_inputs) ----------------
#define BB    2
#define CC    64
#define HH    256
#define WW    256
#define PP    16
#define STEP  14
#define NHP   19          // patches per dim
#define NPAT  361         // 19*19
#define BN    722         // BB*NPAT
#define LL    256         // tokens per patch
#define NHEAD 4
#define DHEAD 16
#define MLP   128
#define HWSZ  65536

// ---------------- scratch (static device globals; no allocation) ----------
__device__ float g_t [(size_t)BN*LL*CC];   // residual t        47.3 MB
__device__ float g_q [(size_t)BN*LL*CC];
__device__ float g_k [(size_t)BN*LL*CC];
__device__ float g_v [(size_t)BN*LL*CC];
__device__ float g_o [(size_t)BN*LL*CC];   // attn out, then t2 (in place)
__device__ float g_xs[(size_t)BB*HWSZ*CC]; // xs (after patch_reverse+div) 33.5 MB
__device__ float g_h1[(size_t)BB*HWSZ*MLP];// hh (post fc1+gelu)  67 MB
__device__ float g_h2[(size_t)BB*HWSZ*MLP];// hh2 (post conv add) 67 MB

__device__ int   d_cov_cnt[256];
__device__ int   d_cov_p[256][2];
__device__ int   d_cov_o[256][2];
__device__ float d_invdiv[256];

// ---------------- init: coverage tables + exact div replication -----------
__global__ void k_init()
{
    int r = threadIdx.x;
    if (r < 256) {
        int cnt = 0;
        for (int ph = 0; ph < NHP; ph++) {
            int top = min(STEP*ph, HH-PP);
            if (r >= top && r < top + PP && cnt < 2) {
                d_cov_p[r][cnt] = ph;
                d_cov_o[r][cnt] = r - top;
                cnt++;
            }
        }
        d_cov_cnt[r] = cnt;
    }
    if (threadIdx.x == 0) {
        float div[256];
        for (int i = 0; i < 256; i++) div[i] = 1.f;
        for (int i = STEP; i < HH + STEP - PP; i += STEP) {
            int top = (i + PP > HH) ? (HH - PP) : i;
            for (int r2 = top; r2 < i + PP - STEP; ++r2) div[r2] *= 2.f;
        }
        for (int i = 0; i < 256; i++) d_invdiv[i] = 1.f / div[i];
    }
}

// ---------------- K1: gather + LN1 + QKV ----------------------------------
// block = patch (722), 192 threads. smem: token-major patch [256][68]
__global__ __launch_bounds__(192) void k1(const float* __restrict__ x,
                                          const float* __restrict__ g1,
                                          const float* __restrict__ b1,
                                          const float* __restrict__ wq,
                                          const float* __restrict__ wk,
                                          const float* __restrict__ wv)
{
    extern __shared__ float ps[];           // 256*68 floats = 69632 B
    int bn = blockIdx.x;
    int b  = bn / NPAT, n = bn % NPAT;
    int ph = n / NHP,   pw = n % NHP;
    int top  = min(STEP*ph, HH-PP);
    int left = min(STEP*pw, WW-PP);
    const float* xb = x + (size_t)b * CC * HWSZ;

    // gather patch: coalesced along lj
    for (int idx = threadIdx.x; idx < CC*LL; idx += 192) {
        int c = idx >> 8, l = idx & 255;
        int li = l >> 4, lj = l & 15;
        ps[l*68 + c] = xb[(size_t)c*HWSZ + (size_t)(top+li)*WW + (left+lj)];
    }
    __syncthreads();

    // LN1 per token (one warp per token), store t, overwrite smem with h
    int lane = threadIdx.x & 31, warp = threadIdx.x >> 5;   // 6 warps
    float ga = g1[lane], gb = g1[lane+32], ba = b1[lane], bbv = b1[lane+32];
    for (int l = warp; l < LL; l += 6) {
        float v0 = ps[l*68 + lane], v1 = ps[l*68 + lane + 32];
        size_t tb = ((size_t)bn*LL + l) * CC;
        g_t[tb + lane] = v0;  g_t[tb + lane + 32] = v1;
        float s = v0 + v1, ss = v0*v0 + v1*v1;
        #pragma unroll
        for (int o = 16; o; o >>= 1) {
            s  += __shfl_xor_sync(0xffffffffu, s,  o);
            ss += __shfl_xor_sync(0xffffffffu, ss, o);
        }
        float mean = s * (1.f/64.f);
        float var  = ss * (1.f/64.f) - mean*mean;
        float rstd = rsqrtf(var + 1e-5f);
        ps[l*68 + lane]      = (v0 - mean) * rstd * ga + ba;
        ps[l*68 + lane + 32] = (v1 - mean) * rstd * gb + bbv;
    }
    __syncthreads();

    // QKV: thread = (mat, out-col j); weight column in registers
    int mat = threadIdx.x / 64, j = threadIdx.x & 63;
    const float* w = (mat == 0) ? wq : (mat == 1) ? wk : wv;
    float*     out = (mat == 0) ? g_q : (mat == 1) ? g_k : g_v;
    float wr[64];
    #pragma unroll
    for (int c = 0; c < 64; c++) wr[c] = w[c*64 + j];
    for (int tok = 0; tok < LL; tok++) {
        const float4* h4 = (const float4*)&ps[tok*68];
        float acc = 0.f;
        #pragma unroll
        for (int c4 = 0; c4 < 16; c4++) {
            float4 h = h4[c4];
            acc += h.x*wr[c4*4] + h.y*wr[c4*4+1] + h.z*wr[c4*4+2] + h.w*wr[c4*4+3];
        }
        out[((size_t)bn*LL + tok)*CC + j] = acc;
    }
}

// ---------------- K2: attention per (seq, head) ---------------------------
__global__ __launch_bounds__(256) void k2()
{
    __shared__ float4 kk[LL*4];    // 16 KB
    __shared__ float4 vv[LL*4];    // 16 KB
    int bn = blockIdx.x, head = blockIdx.y;
    size_t base = (size_t)bn*LL*CC + head*DHEAD;

    for (int idx = threadIdx.x; idx < LL*4; idx += 256) {
        int tok = idx >> 2, i4 = idx & 3;
        kk[idx] = *(const float4*)&g_k[base + (size_t)tok*CC + i4*4];
        vv[idx] = *(const float4*)&g_v[base + (size_t)tok*CC + i4*4];
    }
    __syncthreads();

    int l = threadIdx.x;
    const float4* qp = (const float4*)&g_q[base + (size_t)l*CC];
    float4 q0 = qp[0], q1 = qp[1], q2 = qp[2], q3 = qp[3];

    float m = -1e30f, denom = 0.f;
    float o[16];
    #pragma unroll
    for (int i = 0; i < 16; i++) o[i] = 0.f;

    #pragma unroll 2
    for (int j = 0; j < LL; j++) {
        float4 k0 = kk[j*4], k1 = kk[j*4+1], k2v = kk[j*4+2], k3 = kk[j*4+3];
        float s = q0.x*k0.x + q0.y*k0.y + q0.z*k0.z + q0.w*k0.w
                + q1.x*k1.x + q1.y*k1.y + q1.z*k1.z + q1.w*k1.w
                + q2.x*k2v.x + q2.y*k2v.y + q2.z*k2v.z + q2.w*k2v.w
                + q3.x*k3.x + q3.y*k3.y + q3.z*k3.z + q3.w*k3.w;
        s *= 0.25f;                              // 1/sqrt(16)
        if (s > m) {
            float corr = __expf(m - s);
            #pragma unroll
            for (int i = 0; i < 16; i++) o[i] *= corr;
            denom *= corr;
            m = s;
        }
        float e = __expf(s - m);
        denom += e;
        float4 v0 = vv[j*4], v1 = vv[j*4+1], v2 = vv[j*4+2], v3 = vv[j*4+3];
        o[0]+=e*v0.x; o[1]+=e*v0.y; o[2]+=e*v0.z; o[3]+=e*v0.w;
        o[4]+=e*v1.x; o[5]+=e*v1.y; o[6]+=e*v1.z; o[7]+=e*v1.w;
        o[8]+=e*v2.x; o[9]+=e*v2.y; o[10]+=e*v2.z; o[11]+=e*v2.w;
        o[12]+=e*v3.x; o[13]+=e*v3.y; o[14]+=e*v3.z; o[15]+=e*v3.w;
    }
    float inv = 1.f / denom;
    float* op = &g_o[base + (size_t)l*CC];
    #pragma unroll
    for (int i = 0; i < 16; i += 4) {
        float4 r; r.x = o[i]*inv; r.y = o[i+1]*inv; r.z = o[i+2]*inv; r.w = o[i+3]*inv;
        *(float4*)&op[i] = r;
    }
}

// ---------------- K3: t2 = o @ wo + t (in place into g_o) ----------------
__global__ __launch_bounds__(256) void k3(const float* __restrict__ wo)
{
    __shared__ float os[32*64];   // 8 KB
    __shared__ float ws[64*64];   // 16 KB
    size_t row0 = (size_t)blockIdx.x * 32;
    for (int idx = threadIdx.x; idx < 4096; idx += 256) ws[idx] = wo[idx];
    for (int idx = threadIdx.x; idx < 2048; idx += 256) os[idx] = g_o[row0*CC + idx];
    __syncthreads();
    int j = threadIdx.x & 63, rg = threadIdx.x >> 6;
    for (int r = rg; r < 32; r += 4) {
        float acc = g_t[(row0 + r)*CC + j];
        const float4* o4 = (const float4*)&os[r*64];
        #pragma unroll
        for (int c4 = 0; c4 < 16; c4++) {
            float4 o = o4[c4];
            acc += o.x*ws[(c4*4  )*64+j] + o.y*ws[(c4*4+1)*64+j]
                 + o.z*ws[(c4*4+2)*64+j] + o.w*ws[(c4*4+3)*64+j];
        }
        g_o[(row0 + r)*CC + j] = acc;
    }
}

// ---------------- K3b: deterministic patch_reverse (gather) + div --------
__global__ __launch_bounds__(256) void k3b()
{
    int e = blockIdx.x * 256 + threadIdx.x;  // over BB*HWSZ*CC = 8388608
    int c   = e & 63;
    int pix = e >> 6;
    int b   = pix >> 16;
    int hw  = pix & 65535;
    int r   = hw >> 8, w = hw & 255;
    float acc = 0.f;
    int hc = d_cov_cnt[r], wc = d_cov_cnt[w];
    for (int i = 0; i < hc; i++) {
        int php = d_cov_p[r][i], li = d_cov_o[r][i];
        for (int k = 0; k < wc; k++) {
            int n = php*NHP + d_cov_p[w][k];
            int l = li*PP  + d_cov_o[w][k];
            acc += g_o[(((size_t)(b*NPAT + n))*LL + l)*CC + c];
        }
    }
    g_xs[e] = acc * d_invdiv[r] * d_invdiv[w];
}

// ---------------- K4: LN2 + fc1 + GELU ------------------------------------
__global__ __launch_bounds__(256) void k4(const float* __restrict__ g2,
                                          const float* __restrict__ b2,
                                          const float* __restrict__ fc1w,
                                          const float* __restrict__ fc1b)
{
    __shared__ float fw[64*MLP];   // 32 KB
    __shared__ float xsm[16*64];
    __shared__ float hsm[16*64];
    __shared__ float mr[16*2];
    size_t pix0 = (size_t)blockIdx.x * 16;
    for (int idx = threadIdx.x; idx < 64*MLP; idx += 256) fw[idx] = fc1w[idx];
    for (int idx = threadIdx.x; idx < 1024;   idx += 256) xsm[idx] = g_xs[pix0*CC + idx];
    __syncthreads();
    int lane = threadIdx.x & 31, warp = threadIdx.x >> 5;
    for (int r = warp; r < 16; r += 8) {
        float v0 = xsm[r*64+lane], v1 = xsm[r*64+lane+32];
        float s = v0+v1, ss = v0*v0+v1*v1;
        #pragma unroll
        for (int o = 16; o; o >>= 1) {
            s  += __shfl_xor_sync(0xffffffffu, s,  o);
            ss += __shfl_xor_sync(0xffffffffu, ss, o);
        }
        if (lane == 0) {
            float mean = s * (1.f/64.f);
            float var  = ss * (1.f/64.f) - mean*mean;
            mr[r*2]   = mean;
            mr[r*2+1] = rsqrtf(var + 1e-5f);
        }
    }
    __syncthreads();
    for (int idx = threadIdx.x; idx < 1024; idx += 256) {
        int r = idx >> 6, c = idx & 63;
        hsm[idx] = (xsm[idx] - mr[r*2]) * mr[r*2+1] * g2[c] + b2[c];
    }
    __syncthreads();
    int j = threadIdx.x & 127, rg = threadIdx.x >> 7;
    float bias = fc1b[j];
    for (int r = rg; r < 16; r += 2) {
        float acc = bias;
        const float4* h4 = (const float4*)&hsm[r*64];
        #pragma unroll
        for (int c4 = 0; c4 < 16; c4++) {
            float4 h = h4[c4];
            acc += h.x*fw[(c4*4  )*MLP+j] + h.y*fw[(c4*4+1)*MLP+j]
                 + h.z*fw[(c4*4+2)*MLP+j] + h.w*fw[(c4*4+3)*MLP+j];
        }
        float ge = 0.5f * acc * (1.f + erff(acc * 0.70710678118654752f));
        g_h1[(pix0 + r)*MLP + j] = ge;
    }
}

// ---------------- K5: depthwise 5x5 + GELU + residual ---------------------
__global__ __launch_bounds__(128) void k5(const float* __restrict__ dww,
                                          const float* __restrict__ dwb)
{
    extern __shared__ float si[];            // 5*20*128 floats = 51200 B
    int ch = threadIdx.x;
    int bx = blockIdx.x;                     // b*256*16 + row*16 + tile
    int cw0 = (bx & 15) * 16;
    int r   = (bx >> 4) & 255;
    int b   = bx >> 12;
    float wreg[25];
    #pragma unroll
    for (int i = 0; i < 25; i++) wreg[i] = dww[ch*25 + i];
    float bias = dwb[ch];
    const float* hp = g_h1 + (size_t)b * HWSZ * MLP;

    for (int slot = 0; slot < 100; slot++) {
        int ry = slot / 20, cx = slot % 20;
        int rr = r + ry - 2, cc = cw0 + cx - 2;
        float v = 0.f;
        if (rr >= 0 && rr < 256 && cc >= 0 && cc < 256)
            v = hp[((size_t)rr*256 + cc)*MLP + ch];
        si[slot*MLP + ch] = v;
    }
    __syncthreads();

    float* op = g_h2 + ((size_t)b*HWSZ + (size_t)r*256 + cw0) * MLP;
    for (int k = 0; k < 16; k++) {
        float acc = 0.f;
        #pragma unroll
        for (int dy = 0; dy < 5; dy++)
            #pragma unroll
            for (int dx = 0; dx < 5; dx++)
                acc += si[(dy*20 + k + dx)*MLP + ch] * wreg[dy*5+dx];
        float center = si[(2*20 + k + 2)*MLP + ch];
        float t = acc + bias;
        float ge = 0.5f * t * (1.f + erff(t * 0.70710678118654752f));
        op[(size_t)k*MLP + ch] = center + ge;
    }
}

// ---------------- K6: fc2 + bias + residual + transpose to NCHW -----------
__global__ __launch_bounds__(256) void k6(const float* __restrict__ fc2w,
                                          const float* __restrict__ fc2b,
                                          float* __restrict__ out)
{
    extern __shared__ float sm[];
    float* hs   = sm;                 // 32*128 = 4096
    float* fw   = sm + 4096;          // 128*64 = 8192
    float* tile = sm + 4096 + 8192;   // 64*33  = 2112
    size_t pix0 = (size_t)blockIdx.x * 32;
    int b   = (int)(pix0 >> 16);
    int hw0 = (int)(pix0 & 65535);
    for (int idx = threadIdx.x; idx < 8192; idx += 256) fw[idx] = fc2w[idx];
    for (int idx = threadIdx.x; idx < 4096; idx += 256) hs[idx] = g_h2[pix0*MLP + idx];
    __syncthreads();
    int c = threadIdx.x & 63, pg = threadIdx.x >> 6;
    float bias = fc2b[c];
    for (int p = pg; p < 32; p += 4) {
        float acc = bias + g_xs[(pix0 + p)*CC + c];
        const float4* h4 = (const float4*)&hs[p*MLP];
        #pragma unroll
        for (int m4 = 0; m4 < 32; m4++) {
            float4 h = h4[m4];
            acc += h.x*fw[(m4*4  )*64+c] + h.y*fw[(m4*4+1)*64+c]
                 + h.z*fw[(m4*4+2)*64+c] + h.w*fw[(m4*4+3)*64+c];
        }
        tile[c*33 + p] = acc;
    }
    __syncthreads();
    for (int idx = threadIdx.x; idx < 2048; idx += 256) {
        int cc = idx >> 5, k = idx & 31;
        out[((size_t)(b*CC + cc))*HWSZ + hw0 + k] = tile[cc*33 + k];
    }
}

// ---------------- launch ---------------------------------------------------
extern "C" void kernel_launch(void* const* d_in, const int* in_sizes, int n_in,
                              void* d_out, int out_size)
{
    const float* x    = (const float*)d_in[0];
    const float* ln1g = (const float*)d_in[1];
    const float* ln1b = (const float*)d_in[2];
    const float* wq   = (const float*)d_in[3];
    const float* wk   = (const float*)d_in[4];
    const float* wv   = (const float*)d_in[5];
    const float* wo   = (const float*)d_in[6];
    const float* ln2g = (const float*)d_in[7];
    const float* ln2b = (const float*)d_in[8];
    const float* fc1w = (const float*)d_in[9];
    const float* fc1b = (const float*)d_in[10];
    const float* dww  = (const float*)d_in[11];
    const float* dwb  = (const float*)d_in[12];
    const float* fc2w = (const float*)d_in[13];
    const float* fc2b = (const float*)d_in[14];
    float* out = (float*)d_out;

    cudaFuncSetAttribute(k1, cudaFuncAttributeMaxDynamicSharedMemorySize, 256*68*4);
    cudaFuncSetAttribute(k5, cudaFuncAttributeMaxDynamicSharedMemorySize, 100*128*4);
    cudaFuncSetAttribute(k6, cudaFuncAttributeMaxDynamicSharedMemorySize, (4096+8192+2112)*4);

    k_init<<<1, 256>>>();
    k1<<<BN, 192, 256*68*4>>>(x, ln1g, ln1b, wq, wk, wv);
    k2<<<dim3(BN, NHEAD), 256>>>();
    k3<<<(BN*LL)/32, 256>>>(wo);
    k3b<<<(BB*HWSZ*CC)/256, 256>>>();
    k4<<<(BB*HWSZ)/16, 256>>>(ln2g, ln2b, fc1w, fc1b);
    k5<<<BB*256*16, 128, 100*128*4>>>(dww, dwb);
    k6<<<(BB*HWSZ)/32, 256, (4096+8192+2112)*4>>>(fc2w, fc2b, out);
}

// round 2
// speedup vs baseline: 1.6298x; 1.6298x over previous
#include <cuda_runtime.h>
#include <cuda_bf16.h>
#include <cstddef>

// ---------------- problem geometry (fixed by setup_inputs) ----------------
#define BB    2
#define CC    64
#define HH    256
#define WW    256
#define PP    16
#define STEP  14
#define NHP   19
#define NPAT  361
#define BN    722
#define LL    256
#define NHEAD 4
#define DHEAD 16
#define MLP   128
#define HWSZ  65536

// ---------------- scratch ----------
__device__ float g_t [(size_t)BN*LL*CC];
__device__ float g_q [(size_t)BN*LL*CC];
__device__ float g_k [(size_t)BN*LL*CC];
__device__ float g_v [(size_t)BN*LL*CC];
__device__ float g_o [(size_t)BN*LL*CC];
__device__ float g_xs[(size_t)BB*HWSZ*CC];
__device__ float g_h1[(size_t)BB*HWSZ*MLP];
__device__ float g_h2[(size_t)BB*HWSZ*MLP];

__device__ int   d_cov_cnt[256];
__device__ int   d_cov_p[256][2];
__device__ int   d_cov_o[256][2];
__device__ float d_invdiv[256];

__global__ void k_init()
{
    int r = threadIdx.x;
    if (r < 256) {
        int cnt = 0;
        for (int ph = 0; ph < NHP; ph++) {
            int top = min(STEP*ph, HH-PP);
            if (r >= top && r < top + PP && cnt < 2) {
                d_cov_p[r][cnt] = ph;
                d_cov_o[r][cnt] = r - top;
                cnt++;
            }
        }
        d_cov_cnt[r] = cnt;
    }
    if (threadIdx.x == 0) {
        float div[256];
        for (int i = 0; i < 256; i++) div[i] = 1.f;
        for (int i = STEP; i < HH + STEP - PP; i += STEP) {
            int top = (i + PP > HH) ? (HH - PP) : i;
            for (int r2 = top; r2 < i + PP - STEP; ++r2) div[r2] *= 2.f;
        }
        for (int i = 0; i < 256; i++) d_invdiv[i] = 1.f / div[i];
    }
}

// ---------------- K1: gather + LN1 + QKV (register-tiled) -----------------
// 256 threads. smem: h [256][68] + weights [3][64][68]
__global__ __launch_bounds__(256) void k1(const float* __restrict__ x,
                                          const float* __restrict__ g1,
                                          const float* __restrict__ b1,
                                          const float* __restrict__ wq,
                                          const float* __restrict__ wk,
                                          const float* __restrict__ wv)
{
    extern __shared__ float sm[];
    float* ps = sm;              // 256*68
    float* ws = sm + 256*68;     // 3*64*68
    int tid = threadIdx.x;
    int bn = blockIdx.x;
    int b  = bn / NPAT, n = bn % NPAT;
    int ph = n / NHP,   pw = n % NHP;
    int top  = min(STEP*ph, HH-PP);
    int left = min(STEP*pw, WW-PP);
    const float* xb = x + (size_t)b * CC * HWSZ;

    // weights -> smem (row-major per mat, stride 68)
    for (int idx = tid; idx < 3*64*64; idx += 256) {
        int mat = idx >> 12; int rem = idx & 4095;
        const float* w = (mat == 0) ? wq : (mat == 1) ? wk : wv;
        ws[mat*64*68 + (rem >> 6)*68 + (rem & 63)] = w[rem];
    }
    // gather patch (coalesced 16-float segments)
    for (int idx = tid; idx < CC*LL; idx += 256) {
        int c = idx >> 8, l = idx & 255;
        int li = l >> 4, lj = l & 15;
        ps[l*68 + c] = xb[(size_t)c*HWSZ + (size_t)(top+li)*WW + (left+lj)];
    }
    __syncthreads();

    // LN1 per token, store residual t, overwrite smem with h
    int lane = tid & 31, warp = tid >> 5;
    float ga = g1[lane], gb = g1[lane+32], ba = b1[lane], bbv = b1[lane+32];
    for (int l = warp; l < LL; l += 8) {
        float v0 = ps[l*68 + lane], v1 = ps[l*68 + lane + 32];
        size_t tb = ((size_t)bn*LL + l) * CC;
        g_t[tb + lane] = v0;  g_t[tb + lane + 32] = v1;
        float s = v0 + v1, ss = v0*v0 + v1*v1;
        #pragma unroll
        for (int o = 16; o; o >>= 1) {
            s  += __shfl_xor_sync(0xffffffffu, s,  o);
            ss += __shfl_xor_sync(0xffffffffu, ss, o);
        }
        float mean = s * (1.f/64.f);
        float var  = ss * (1.f/64.f) - mean*mean;
        float rstd = rsqrtf(var + 1e-5f);
        ps[l*68 + lane]      = (v0 - mean) * rstd * ga + ba;
        ps[l*68 + lane + 32] = (v1 - mean) * rstd * gb + bbv;
    }
    __syncthreads();

    // GEMM: thread = (ty row-set of 16 strided rows, tx col-quad)
    int tx = tid & 15, ty = tid >> 4;
    #pragma unroll 1
    for (int mat = 0; mat < 3; mat++) {
        const float* wm = ws + mat*64*68 + 4*tx;
        float* out = (mat == 0) ? g_q : (mat == 1) ? g_k : g_v;
        float acc[16][4];
        #pragma unroll
        for (int i = 0; i < 16; i++)
            #pragma unroll
            for (int c = 0; c < 4; c++) acc[i][c] = 0.f;
        #pragma unroll 4
        for (int k4 = 0; k4 < 16; k4++) {
            float4 w0 = *(const float4*)&wm[(4*k4  )*68];
            float4 w1 = *(const float4*)&wm[(4*k4+1)*68];
            float4 w2 = *(const float4*)&wm[(4*k4+2)*68];
            float4 w3 = *(const float4*)&wm[(4*k4+3)*68];
            #pragma unroll
            for (int rr = 0; rr < 16; rr++) {
                float4 h = *(const float4*)&ps[(ty + 16*rr)*68 + 4*k4];
                acc[rr][0] += h.x*w0.x + h.y*w1.x + h.z*w2.x + h.w*w3.x;
                acc[rr][1] += h.x*w0.y + h.y*w1.y + h.z*w2.y + h.w*w3.y;
                acc[rr][2] += h.x*w0.z + h.y*w1.z + h.z*w2.z + h.w*w3.z;
                acc[rr][3] += h.x*w0.w + h.y*w1.w + h.z*w2.w + h.w*w3.w;
            }
        }
        #pragma unroll
        for (int rr = 0; rr < 16; rr++) {
            float4 r4; r4.x = acc[rr][0]; r4.y = acc[rr][1];
            r4.z = acc[rr][2]; r4.w = acc[rr][3];
            *(float4*)&out[((size_t)bn*LL + ty + 16*rr)*CC + 4*tx] = r4;
        }
    }
}

// ---------------- K2: attention, chunk-16 online softmax ------------------
__global__ __launch_bounds__(256) void k2()
{
    __shared__ float4 kk[LL*4];
    __shared__ float4 vv[LL*4];
    int bn = blockIdx.x, head = blockIdx.y;
    size_t base = (size_t)bn*LL*CC + head*DHEAD;

    for (int idx = threadIdx.x; idx < LL*4; idx += 256) {
        int tok = idx >> 2, i4 = idx & 3;
        kk[idx] = *(const float4*)&g_k[base + (size_t)tok*CC + i4*4];
        vv[idx] = *(const float4*)&g_v[base + (size_t)tok*CC + i4*4];
    }
    __syncthreads();

    int l = threadIdx.x;
    const float4* qp = (const float4*)&g_q[base + (size_t)l*CC];
    float4 q0 = qp[0], q1 = qp[1], q2 = qp[2], q3 = qp[3];

    float m = -1e30f, denom = 0.f;
    float o[16];
    #pragma unroll
    for (int i = 0; i < 16; i++) o[i] = 0.f;

    for (int jc = 0; jc < 16; jc++) {
        float s[16];
        #pragma unroll
        for (int jj = 0; jj < 16; jj++) {
            int j = jc*16 + jj;
            float4 k0 = kk[j*4], k1 = kk[j*4+1], k2v = kk[j*4+2], k3 = kk[j*4+3];
            s[jj] = (q0.x*k0.x + q0.y*k0.y + q0.z*k0.z + q0.w*k0.w
                   + q1.x*k1.x + q1.y*k1.y + q1.z*k1.z + q1.w*k1.w
                   + q2.x*k2v.x + q2.y*k2v.y + q2.z*k2v.z + q2.w*k2v.w
                   + q3.x*k3.x + q3.y*k3.y + q3.z*k3.z + q3.w*k3.w) * 0.25f;
        }
        float cm = s[0];
        #pragma unroll
        for (int jj = 1; jj < 16; jj++) cm = fmaxf(cm, s[jj]);
        float mnew = fmaxf(m, cm);
        float corr = __expf(m - mnew);
        denom *= corr;
        #pragma unroll
        for (int i = 0; i < 16; i++) o[i] *= corr;
        m = mnew;
        #pragma unroll
        for (int jj = 0; jj < 16; jj++) {
            int j = jc*16 + jj;
            float e = __expf(s[jj] - m);
            denom += e;
            float4 v0 = vv[j*4], v1 = vv[j*4+1], v2 = vv[j*4+2], v3 = vv[j*4+3];
            o[0]+=e*v0.x; o[1]+=e*v0.y; o[2]+=e*v0.z; o[3]+=e*v0.w;
            o[4]+=e*v1.x; o[5]+=e*v1.y; o[6]+=e*v1.z; o[7]+=e*v1.w;
            o[8]+=e*v2.x; o[9]+=e*v2.y; o[10]+=e*v2.z; o[11]+=e*v2.w;
            o[12]+=e*v3.x; o[13]+=e*v3.y; o[14]+=e*v3.z; o[15]+=e*v3.w;
        }
    }
    float inv = 1.f / denom;
    float* op = &g_o[base + (size_t)l*CC];
    #pragma unroll
    for (int i = 0; i < 16; i += 4) {
        float4 r; r.x = o[i]*inv; r.y = o[i+1]*inv; r.z = o[i+2]*inv; r.w = o[i+3]*inv;
        *(float4*)&op[i] = r;
    }
}

// ---------------- K3: t2 = o @ wo + t (register-tiled) --------------------
__global__ __launch_bounds__(256) void k3(const float* __restrict__ wo)
{
    __shared__ float os[64*68];
    __shared__ float ws[64*68];
    size_t row0 = (size_t)blockIdx.x * 64;
    int tid = threadIdx.x;
    for (int idx = tid; idx < 4096; idx += 256) {
        ws[(idx >> 6)*68 + (idx & 63)] = wo[idx];
        os[(idx >> 6)*68 + (idx & 63)] = g_o[row0*CC + idx];
    }
    __syncthreads();
    int tx = tid & 15, ty = tid >> 4;
    const float* wp = ws + 4*tx;
    float acc[4][4];
    #pragma unroll
    for (int r = 0; r < 4; r++)
        #pragma unroll
        for (int c = 0; c < 4; c++) acc[r][c] = 0.f;
    #pragma unroll 4
    for (int k4 = 0; k4 < 16; k4++) {
        float4 w0 = *(const float4*)&wp[(4*k4  )*68];
        float4 w1 = *(const float4*)&wp[(4*k4+1)*68];
        float4 w2 = *(const float4*)&wp[(4*k4+2)*68];
        float4 w3 = *(const float4*)&wp[(4*k4+3)*68];
        #pragma unroll
        for (int rr = 0; rr < 4; rr++) {
            float4 h = *(const float4*)&os[(ty*4 + rr)*68 + 4*k4];
            acc[rr][0] += h.x*w0.x + h.y*w1.x + h.z*w2.x + h.w*w3.x;
            acc[rr][1] += h.x*w0.y + h.y*w1.y + h.z*w2.y + h.w*w3.y;
            acc[rr][2] += h.x*w0.z + h.y*w1.z + h.z*w2.z + h.w*w3.z;
            acc[rr][3] += h.x*w0.w + h.y*w1.w + h.z*w2.w + h.w*w3.w;
        }
    }
    #pragma unroll
    for (int rr = 0; rr < 4; rr++) {
        float4 t4 = *(const float4*)&g_t[(row0 + ty*4 + rr)*CC + 4*tx];
        float4 r4;
        r4.x = acc[rr][0] + t4.x; r4.y = acc[rr][1] + t4.y;
        r4.z = acc[rr][2] + t4.z; r4.w = acc[rr][3] + t4.w;
        *(float4*)&g_o[(row0 + ty*4 + rr)*CC + 4*tx] = r4;
    }
}

// ---------------- K3b: deterministic patch_reverse + div ------------------
__global__ __launch_bounds__(256) void k3b()
{
    int e = blockIdx.x * 256 + threadIdx.x;
    int c   = e & 63;
    int pix = e >> 6;
    int b   = pix >> 16;
    int hw  = pix & 65535;
    int r   = hw >> 8, w = hw & 255;
    float acc = 0.f;
    int hc = d_cov_cnt[r], wc = d_cov_cnt[w];
    for (int i = 0; i < hc; i++) {
        int php = d_cov_p[r][i], li = d_cov_o[r][i];
        for (int k = 0; k < wc; k++) {
            int n = php*NHP + d_cov_p[w][k];
            int l = li*PP  + d_cov_o[w][k];
            acc += g_o[(((size_t)(b*NPAT + n))*LL + l)*CC + c];
        }
    }
    g_xs[e] = acc * d_invdiv[r] * d_invdiv[w];
}

// ---------------- K4: LN2 + fc1 + GELU (register-tiled) -------------------
__global__ __launch_bounds__(256) void k4(const float* __restrict__ g2,
                                          const float* __restrict__ b2,
                                          const float* __restrict__ fc1w,
                                          const float* __restrict__ fc1b)
{
    extern __shared__ float sm4[];
    float* fw  = sm4;                   // 64*132
    float* xsm = sm4 + 64*132;          // 32*68
    float* hsm = xsm + 32*68;           // 32*68
    float* mr  = hsm + 32*68;           // 64
    int tid = threadIdx.x;
    size_t pix0 = (size_t)blockIdx.x * 32;
    for (int idx = tid; idx < 64*MLP; idx += 256)
        fw[(idx >> 7)*132 + (idx & 127)] = fc1w[idx];
    for (int idx = tid; idx < 2048; idx += 256)
        xsm[(idx >> 6)*68 + (idx & 63)] = g_xs[pix0*CC + idx];
    __syncthreads();
    int lane = tid & 31, warp = tid >> 5;
    for (int r = warp; r < 32; r += 8) {
        float v0 = xsm[r*68+lane], v1 = xsm[r*68+lane+32];
        float s = v0+v1, ss = v0*v0+v1*v1;
        #pragma unroll
        for (int o = 16; o; o >>= 1) {
            s  += __shfl_xor_sync(0xffffffffu, s,  o);
            ss += __shfl_xor_sync(0xffffffffu, ss, o);
        }
        if (lane == 0) {
            float mean = s * (1.f/64.f);
            float var  = ss * (1.f/64.f) - mean*mean;
            mr[r*2]   = mean;
            mr[r*2+1] = rsqrtf(var + 1e-5f);
        }
    }
    __syncthreads();
    for (int idx = tid; idx < 2048; idx += 256) {
        int r = idx >> 6, c = idx & 63;
        hsm[r*68 + c] = (xsm[r*68 + c] - mr[r*2]) * mr[r*2+1] * g2[c] + b2[c];
    }
    __syncthreads();
    int tx = tid & 31, ty = tid >> 5;          // tx: col-quad (of 32), ty: row group
    const float* wp = fw + 4*tx;
    float4 bias = *(const float4*)&fc1b[4*tx];
    float acc[4][4];
    #pragma unroll
    for (int r = 0; r < 4; r++) {
        acc[r][0] = bias.x; acc[r][1] = bias.y; acc[r][2] = bias.z; acc[r][3] = bias.w;
    }
    #pragma unroll 4
    for (int k4i = 0; k4i < 16; k4i++) {
        float4 w0 = *(const float4*)&wp[(4*k4i  )*132];
        float4 w1 = *(const float4*)&wp[(4*k4i+1)*132];
        float4 w2 = *(const float4*)&wp[(4*k4i+2)*132];
        float4 w3 = *(const float4*)&wp[(4*k4i+3)*132];
        #pragma unroll
        for (int rr = 0; rr < 4; rr++) {
            float4 h = *(const float4*)&hsm[(ty*4 + rr)*68 + 4*k4i];
            acc[rr][0] += h.x*w0.x + h.y*w1.x + h.z*w2.x + h.w*w3.x;
            acc[rr][1] += h.x*w0.y + h.y*w1.y + h.z*w2.y + h.w*w3.y;
            acc[rr][2] += h.x*w0.z + h.y*w1.z + h.z*w2.z + h.w*w3.z;
            acc[rr][3] += h.x*w0.w + h.y*w1.w + h.z*w2.w + h.w*w3.w;
        }
    }
    #pragma unroll
    for (int rr = 0; rr < 4; rr++) {
        float4 r4;
        r4.x = 0.5f*acc[rr][0]*(1.f + erff(acc[rr][0]*0.70710678118654752f));
        r4.y = 0.5f*acc[rr][1]*(1.f + erff(acc[rr][1]*0.70710678118654752f));
        r4.z = 0.5f*acc[rr][2]*(1.f + erff(acc[rr][2]*0.70710678118654752f));
        r4.w = 0.5f*acc[rr][3]*(1.f + erff(acc[rr][3]*0.70710678118654752f));
        *(float4*)&g_h1[(pix0 + ty*4 + rr)*MLP + 4*tx] = r4;
    }
}

// ---------------- K5: depthwise 5x5 + GELU + residual ---------------------
__global__ __launch_bounds__(128) void k5(const float* __restrict__ dww,
                                          const float* __restrict__ dwb)
{
    extern __shared__ float si[];            // 100*128
    int ch = threadIdx.x;
    int bx = blockIdx.x;
    int cw0 = (bx & 15) * 16;
    int r   = (bx >> 4) & 255;
    int b   = bx >> 12;
    float wreg[25];
    #pragma unroll
    for (int i = 0; i < 25; i++) wreg[i] = dww[ch*25 + i];
    float bias = dwb[ch];
    const float* hp = g_h1 + (size_t)b * HWSZ * MLP;

    for (int slot = 0; slot < 100; slot++) {
        int ry = slot / 20, cx = slot % 20;
        int rr = r + ry - 2, cc = cw0 + cx - 2;
        float v = 0.f;
        if (rr >= 0 && rr < 256 && cc >= 0 && cc < 256)
            v = hp[((size_t)rr*256 + cc)*MLP + ch];
        si[slot*MLP + ch] = v;
    }
    __syncthreads();

    float* op = g_h2 + ((size_t)b*HWSZ + (size_t)r*256 + cw0) * MLP;
    #pragma unroll 1
    for (int half = 0; half < 2; half++) {
        int k0 = half * 8;
        float val[5][12];
        #pragma unroll
        for (int dy = 0; dy < 5; dy++)
            #pragma unroll
            for (int xx = 0; xx < 12; xx++)
                val[dy][xx] = si[(dy*20 + k0 + xx)*MLP + ch];
        #pragma unroll
        for (int k = 0; k < 8; k++) {
            float acc = bias;
            #pragma unroll
            for (int dy = 0; dy < 5; dy++)
                #pragma unroll
                for (int dx = 0; dx < 5; dx++)
                    acc += val[dy][k + dx] * wreg[dy*5 + dx];
            float center = val[2][k + 2];
            float ge = 0.5f * acc * (1.f + erff(acc * 0.70710678118654752f));
            op[(size_t)(k0 + k)*MLP + ch] = center + ge;
        }
    }
}

// ---------------- K6: fc2 + bias + residual + transpose -------------------
__global__ __launch_bounds__(256) void k6(const float* __restrict__ fc2w,
                                          const float* __restrict__ fc2b,
                                          float* __restrict__ out)
{
    extern __shared__ float sm6[];
    float* hs   = sm6;                    // 64*132
    float* fw   = sm6 + 64*132;           // 128*68
    float* tile = fw  + 128*68;           // 64*68
    int tid = threadIdx.x;
    size_t pix0 = (size_t)blockIdx.x * 64;
    int b   = (int)(pix0 >> 16);
    int hw0 = (int)(pix0 & 65535);
    for (int idx = tid; idx < 8192; idx += 256) {
        fw[(idx >> 6)*68  + (idx & 63)]  = fc2w[idx];
        hs[(idx >> 7)*132 + (idx & 127)] = g_h2[pix0*MLP + idx];
    }
    __syncthreads();
    int tx = tid & 15, ty = tid >> 4;
    const float* wp = fw + 4*tx;
    float4 bias = *(const float4*)&fc2b[4*tx];
    float acc[4][4];
    #pragma unroll
    for (int r = 0; r < 4; r++) {
        acc[r][0] = bias.x; acc[r][1] = bias.y; acc[r][2] = bias.z; acc[r][3] = bias.w;
    }
    #pragma unroll 4
    for (int k4i = 0; k4i < 32; k4i++) {
        float4 w0 = *(const float4*)&wp[(4*k4i  )*68];
        float4 w1 = *(const float4*)&wp[(4*k4i+1)*68];
        float4 w2 = *(const float4*)&wp[(4*k4i+2)*68];
        float4 w3 = *(const float4*)&wp[(4*k4i+3)*68];
        #pragma unroll
        for (int rr = 0; rr < 4; rr++) {
            float4 h = *(const float4*)&hs[(ty*4 + rr)*132 + 4*k4i];
            acc[rr][0] += h.x*w0.x + h.y*w1.x + h.z*w2.x + h.w*w3.x;
            acc[rr][1] += h.x*w0.y + h.y*w1.y + h.z*w2.y + h.w*w3.y;
            acc[rr][2] += h.x*w0.z + h.y*w1.z + h.z*w2.z + h.w*w3.z;
            acc[rr][3] += h.x*w0.w + h.y*w1.w + h.z*w2.w + h.w*w3.w;
        }
    }
    #pragma unroll
    for (int rr = 0; rr < 4; rr++) {
        int r = ty*4 + rr;
        float4 x4 = *(const float4*)&g_xs[(pix0 + r)*CC + 4*tx];
        tile[(4*tx  )*68 + r] = acc[rr][0] + x4.x;
        tile[(4*tx+1)*68 + r] = acc[rr][1] + x4.y;
        tile[(4*tx+2)*68 + r] = acc[rr][2] + x4.z;
        tile[(4*tx+3)*68 + r] = acc[rr][3] + x4.w;
    }
    __syncthreads();
    for (int idx = tid; idx < 4096; idx += 256) {
        int c = idx >> 6, p = idx & 63;
        out[((size_t)(b*CC + c))*HWSZ + hw0 + p] = tile[c*68 + p];
    }
}

// ---------------- launch ---------------------------------------------------
extern "C" void kernel_launch(void* const* d_in, const int* in_sizes, int n_in,
                              void* d_out, int out_size)
{
    const float* x    = (const float*)d_in[0];
    const float* ln1g = (const float*)d_in[1];
    const float* ln1b = (const float*)d_in[2];
    const float* wq   = (const float*)d_in[3];
    const float* wk   = (const float*)d_in[4];
    const float* wv   = (const float*)d_in[5];
    const float* wo   = (const float*)d_in[6];
    const float* ln2g = (const float*)d_in[7];
    const float* ln2b = (const float*)d_in[8];
    const float* fc1w = (const float*)d_in[9];
    const float* fc1b = (const float*)d_in[10];
    const float* dww  = (const float*)d_in[11];
    const float* dwb  = (const float*)d_in[12];
    const float* fc2w = (const float*)d_in[13];
    const float* fc2b = (const float*)d_in[14];
    float* out = (float*)d_out;

    static int s_attr = 0;
    if (!s_attr) {
        cudaFuncSetAttribute(k1, cudaFuncAttributeMaxDynamicSharedMemorySize, (256*68 + 3*64*68)*4);
        cudaFuncSetAttribute(k4, cudaFuncAttributeMaxDynamicSharedMemorySize, (64*132 + 2*32*68 + 64)*4);
        cudaFuncSetAttribute(k5, cudaFuncAttributeMaxDynamicSharedMemorySize, 100*128*4);
        cudaFuncSetAttribute(k6, cudaFuncAttributeMaxDynamicSharedMemorySize, (64*132 + 128*68 + 64*68)*4);
        s_attr = 1;
    }

    k_init<<<1, 256>>>();
    k1<<<BN, 256, (256*68 + 3*64*68)*4>>>(x, ln1g, ln1b, wq, wk, wv);
    k2<<<dim3(BN, NHEAD), 256>>>();
    k3<<<(BN*LL)/64, 256>>>(wo);
    k3b<<<(BB*HWSZ*CC)/256, 256>>>();
    k4<<<(BB*HWSZ)/32, 256, (64*132 + 2*32*68 + 64)*4>>>(ln2g, ln2b, fc1w, fc1b);
    k5<<<BB*256*16, 128, 100*128*4>>>(dww, dwb);
    k6<<<(BB*HWSZ)/64, 256, (64*132 + 128*68 + 64*68)*4>>>(fc2w, fc2b, out);
}

// round 3
// speedup vs baseline: 2.1564x; 1.3231x over previous
#include <cuda_runtime.h>
#include <cuda_bf16.h>
#include <cstddef>

// ---------------- problem geometry (fixed by setup_inputs) ----------------
#define BB    2
#define CC    64
#define HH    256
#define WW    256
#define PP    16
#define STEP  14
#define NHP   19
#define NPAT  361
#define BN    722
#define LL    256
#define NHEAD 4
#define DHEAD 16
#define MLP   128
#define HWSZ  65536

#define QSCALE 0.36067376022224085f   // 0.25 * log2(e)

// ---------------- scratch ----------
__device__ float g_t [(size_t)BN*LL*CC];
__device__ float g_q [(size_t)BN*LL*CC];
__device__ float g_k [(size_t)BN*LL*CC];
__device__ float g_v [(size_t)BN*LL*CC];
__device__ float g_o [(size_t)BN*LL*CC];
__device__ float g_xs[(size_t)BB*HWSZ*CC];
__device__ float g_h1[(size_t)BB*HWSZ*MLP];
__device__ float g_h2[(size_t)BB*HWSZ*MLP];

__device__ int   d_cov_cnt[256];
__device__ int   d_cov_p[256][2];
__device__ int   d_cov_o[256][2];
__device__ float d_invdiv[256];

__global__ void k_init()
{
    int r = threadIdx.x;
    if (r < 256) {
        int cnt = 0;
        for (int ph = 0; ph < NHP; ph++) {
            int top = min(STEP*ph, HH-PP);
            if (r >= top && r < top + PP && cnt < 2) {
                d_cov_p[r][cnt] = ph;
                d_cov_o[r][cnt] = r - top;
                cnt++;
            }
        }
        d_cov_cnt[r] = cnt;
    }
    if (threadIdx.x == 0) {
        float div[256];
        for (int i = 0; i < 256; i++) div[i] = 1.f;
        for (int i = STEP; i < HH + STEP - PP; i += STEP) {
            int top = (i + PP > HH) ? (HH - PP) : i;
            for (int r2 = top; r2 < i + PP - STEP; ++r2) div[r2] *= 2.f;
        }
        for (int i = 0; i < 256; i++) d_invdiv[i] = 1.f / div[i];
    }
}

// ---------------- mma helpers ---------------------------------------------
__device__ __forceinline__ unsigned f2tf(float x) {
    unsigned r; asm("cvt.rna.tf32.f32 %0, %1;" : "=r"(r) : "f"(x)); return r;
}
__device__ __forceinline__ float ex2(float x) {
    float r; asm("ex2.approx.ftz.f32 %0, %1;" : "=f"(r) : "f"(x)); return r;
}
__device__ __forceinline__ void mma_tf32(float* d, const unsigned* a,
                                         unsigned b0, unsigned b1) {
    asm volatile("mma.sync.aligned.m16n8k8.row.col.f32.tf32.tf32.f32 "
        "{%0,%1,%2,%3},{%4,%5,%6,%7},{%8,%9},{%0,%1,%2,%3};"
        : "+f"(d[0]), "+f"(d[1]), "+f"(d[2]), "+f"(d[3])
        : "r"(a[0]), "r"(a[1]), "r"(a[2]), "r"(a[3]), "r"(b0), "r"(b1));
}

// ---------------- K1: gather + LN1 + QKV (register-tiled) -----------------
__global__ __launch_bounds__(256) void k1(const float* __restrict__ x,
                                          const float* __restrict__ g1,
                                          const float* __restrict__ b1,
                                          const float* __restrict__ wq,
                                          const float* __restrict__ wk,
                                          const float* __restrict__ wv)
{
    extern __shared__ float sm[];
    float* ps = sm;              // 256*68
    float* ws = sm + 256*68;     // 3*64*68
    int tid = threadIdx.x;
    int bn = blockIdx.x;
    int b  = bn / NPAT, n = bn % NPAT;
    int ph = n / NHP,   pw = n % NHP;
    int top  = min(STEP*ph, HH-PP);
    int left = min(STEP*pw, WW-PP);
    const float* xb = x + (size_t)b * CC * HWSZ;

    for (int idx = tid; idx < 3*64*64; idx += 256) {
        int mat = idx >> 12; int rem = idx & 4095;
        const float* w = (mat == 0) ? wq : (mat == 1) ? wk : wv;
        ws[mat*64*68 + (rem >> 6)*68 + (rem & 63)] = w[rem];
    }
    for (int idx = tid; idx < CC*LL; idx += 256) {
        int c = idx >> 8, l = idx & 255;
        int li = l >> 4, lj = l & 15;
        ps[l*68 + c] = xb[(size_t)c*HWSZ + (size_t)(top+li)*WW + (left+lj)];
    }
    __syncthreads();

    int lane = tid & 31, warp = tid >> 5;
    float ga = g1[lane], gb = g1[lane+32], ba = b1[lane], bbv = b1[lane+32];
    for (int l = warp; l < LL; l += 8) {
        float v0 = ps[l*68 + lane], v1 = ps[l*68 + lane + 32];
        size_t tb = ((size_t)bn*LL + l) * CC;
        g_t[tb + lane] = v0;  g_t[tb + lane + 32] = v1;
        float s = v0 + v1, ss = v0*v0 + v1*v1;
        #pragma unroll
        for (int o = 16; o; o >>= 1) {
            s  += __shfl_xor_sync(0xffffffffu, s,  o);
            ss += __shfl_xor_sync(0xffffffffu, ss, o);
        }
        float mean = s * (1.f/64.f);
        float var  = ss * (1.f/64.f) - mean*mean;
        float rstd = rsqrtf(var + 1e-5f);
        ps[l*68 + lane]      = (v0 - mean) * rstd * ga + ba;
        ps[l*68 + lane + 32] = (v1 - mean) * rstd * gb + bbv;
    }
    __syncthreads();

    int tx = tid & 15, ty = tid >> 4;
    #pragma unroll 1
    for (int mat = 0; mat < 3; mat++) {
        const float* wm = ws + mat*64*68 + 4*tx;
        float* out = (mat == 0) ? g_q : (mat == 1) ? g_k : g_v;
        float acc[16][4];
        #pragma unroll
        for (int i = 0; i < 16; i++)
            #pragma unroll
            for (int c = 0; c < 4; c++) acc[i][c] = 0.f;
        #pragma unroll 4
        for (int k4 = 0; k4 < 16; k4++) {
            float4 w0 = *(const float4*)&wm[(4*k4  )*68];
            float4 w1 = *(const float4*)&wm[(4*k4+1)*68];
            float4 w2 = *(const float4*)&wm[(4*k4+2)*68];
            float4 w3 = *(const float4*)&wm[(4*k4+3)*68];
            #pragma unroll
            for (int rr = 0; rr < 16; rr++) {
                float4 h = *(const float4*)&ps[(ty + 16*rr)*68 + 4*k4];
                acc[rr][0] += h.x*w0.x + h.y*w1.x + h.z*w2.x + h.w*w3.x;
                acc[rr][1] += h.x*w0.y + h.y*w1.y + h.z*w2.y + h.w*w3.y;
                acc[rr][2] += h.x*w0.z + h.y*w1.z + h.z*w2.z + h.w*w3.z;
                acc[rr][3] += h.x*w0.w + h.y*w1.w + h.z*w2.w + h.w*w3.w;
            }
        }
        #pragma unroll
        for (int rr = 0; rr < 16; rr++) {
            float4 r4; r4.x = acc[rr][0]; r4.y = acc[rr][1];
            r4.z = acc[rr][2]; r4.w = acc[rr][3];
            *(float4*)&out[((size_t)bn*LL + ty + 16*rr)*CC + 4*tx] = r4;
        }
    }
}

// ---------------- K2: attention via tf32 mma.sync (flash-style) -----------
// block = (seq, head), 256 thr = 8 warps, each warp 32 Q rows.
// smem: Q/K/V tf32 tiles, 256 rows x 16 cols, row stride 20 (conflict-free)
__global__ __launch_bounds__(256) void k2()
{
    extern __shared__ unsigned sm2[];
    unsigned* qs = sm2;            // 256*20
    unsigned* ks = sm2 + 5120;
    unsigned* vs = sm2 + 10240;
    int tid = threadIdx.x;
    int bn = blockIdx.x, head = blockIdx.y;
    size_t base = (size_t)bn*LL*CC + head*DHEAD;

    for (int idx = tid; idx < 1024; idx += 256) {
        int row = idx >> 2, c4 = (idx & 3) * 4;
        size_t ga = base + (size_t)row*CC + c4;
        float4 q4 = *(const float4*)&g_q[ga];
        float4 k4 = *(const float4*)&g_k[ga];
        float4 v4 = *(const float4*)&g_v[ga];
        uint4 qu = { f2tf(q4.x*QSCALE), f2tf(q4.y*QSCALE),
                     f2tf(q4.z*QSCALE), f2tf(q4.w*QSCALE) };
        uint4 ku = { f2tf(k4.x), f2tf(k4.y), f2tf(k4.z), f2tf(k4.w) };
        uint4 vu = { f2tf(v4.x), f2tf(v4.y), f2tf(v4.z), f2tf(v4.w) };
        *(uint4*)&qs[row*20 + c4] = qu;
        *(uint4*)&ks[row*20 + c4] = ku;
        *(uint4*)&vs[row*20 + c4] = vu;
    }
    __syncthreads();

    int lane = tid & 31, w = tid >> 5, g = lane >> 2, t = lane & 3;

    // Q fragments: [mtile][ktile][4]
    unsigned aq[2][2][4];
    #pragma unroll
    for (int m = 0; m < 2; m++)
        #pragma unroll
        for (int kt = 0; kt < 2; kt++) {
            int r0 = (w*32 + m*16 + g)*20, c0 = kt*8 + t;
            aq[m][kt][0] = qs[r0 + c0];
            aq[m][kt][1] = qs[r0 + 160 + c0];      // row +8
            aq[m][kt][2] = qs[r0 + c0 + 4];
            aq[m][kt][3] = qs[r0 + 160 + c0 + 4];
        }

    float o[2][2][4];
    #pragma unroll
    for (int m = 0; m < 2; m++)
        #pragma unroll
        for (int nd = 0; nd < 2; nd++)
            #pragma unroll
            for (int i = 0; i < 4; i++) o[m][nd][i] = 0.f;
    float mrow[4] = {-1e30f, -1e30f, -1e30f, -1e30f};
    float drow[4] = {0.f, 0.f, 0.f, 0.f};

    #pragma unroll 1
    for (int jt = 0; jt < 8; jt++) {
        // ---- S = Q K^T (log2-scaled) ----
        float s[2][4][4];
        #pragma unroll
        for (int m = 0; m < 2; m++)
            #pragma unroll
            for (int nt = 0; nt < 4; nt++)
                #pragma unroll
                for (int i = 0; i < 4; i++) s[m][nt][i] = 0.f;
        #pragma unroll
        for (int nt = 0; nt < 4; nt++) {
            #pragma unroll
            for (int kt = 0; kt < 2; kt++) {
                int jr = (jt*32 + nt*8 + g)*20 + kt*8 + t;
                unsigned b0 = ks[jr], b1 = ks[jr + 4];
                mma_tf32(s[0][nt], aq[0][kt], b0, b1);
                mma_tf32(s[1][nt], aq[1][kt], b0, b1);
            }
        }
        // ---- online softmax (base-2) ----
        #pragma unroll
        for (int m = 0; m < 2; m++) {
            #pragma unroll
            for (int h = 0; h < 2; h++) {
                int ri = m*2 + h;
                float mx = fmaxf(s[m][0][h*2], s[m][0][h*2+1]);
                #pragma unroll
                for (int nt = 1; nt < 4; nt++)
                    mx = fmaxf(mx, fmaxf(s[m][nt][h*2], s[m][nt][h*2+1]));
                mx = fmaxf(mx, __shfl_xor_sync(0xffffffffu, mx, 1));
                mx = fmaxf(mx, __shfl_xor_sync(0xffffffffu, mx, 2));
                float mn = fmaxf(mrow[ri], mx);
                float scale = ex2(mrow[ri] - mn);
                mrow[ri] = mn;
                drow[ri] *= scale;
                #pragma unroll
                for (int nd = 0; nd < 2; nd++) {
                    o[m][nd][h*2]   *= scale;
                    o[m][nd][h*2+1] *= scale;
                }
                float psum = 0.f;
                #pragma unroll
                for (int nt = 0; nt < 4; nt++) {
                    float e0 = ex2(s[m][nt][h*2]   - mn);
                    float e1 = ex2(s[m][nt][h*2+1] - mn);
                    s[m][nt][h*2] = e0; s[m][nt][h*2+1] = e1;
                    psum += e0 + e1;
                }
                drow[ri] += psum;
            }
        }
        // ---- cvt P to tf32 ----
        unsigned p[2][4][4];
        #pragma unroll
        for (int m = 0; m < 2; m++)
            #pragma unroll
            for (int nt = 0; nt < 4; nt++)
                #pragma unroll
                for (int i = 0; i < 4; i++) p[m][nt][i] = f2tf(s[m][nt][i]);
        // ---- O += P V : shuffle C-layout -> A-layout, then mma ----
        int sl0 = (lane & ~3) + (t >> 1);
        int sl2 = sl0 + 2;
        #pragma unroll
        for (int kt = 0; kt < 4; kt++) {
            unsigned ap[2][4];
            #pragma unroll
            for (int m = 0; m < 2; m++) {
                unsigned r0 = __shfl_sync(0xffffffffu, p[m][kt][0], sl0);
                unsigned r1 = __shfl_sync(0xffffffffu, p[m][kt][1], sl0);
                ap[m][0] = (t & 1) ? r1 : r0;
                r0 = __shfl_sync(0xffffffffu, p[m][kt][0], sl2);
                r1 = __shfl_sync(0xffffffffu, p[m][kt][1], sl2);
                ap[m][2] = (t & 1) ? r1 : r0;
                r0 = __shfl_sync(0xffffffffu, p[m][kt][2], sl0);
                r1 = __shfl_sync(0xffffffffu, p[m][kt][3], sl0);
                ap[m][1] = (t & 1) ? r1 : r0;
                r0 = __shfl_sync(0xffffffffu, p[m][kt][2], sl2);
                r1 = __shfl_sync(0xffffffffu, p[m][kt][3], sl2);
                ap[m][3] = (t & 1) ? r1 : r0;
            }
            #pragma unroll
            for (int nd = 0; nd < 2; nd++) {
                int vr = (jt*32 + kt*8 + t)*20 + nd*8 + g;
                unsigned b0 = vs[vr], b1 = vs[vr + 80];   // rows t, t+4
                mma_tf32(o[0][nd], ap[0], b0, b1);
                mma_tf32(o[1][nd], ap[1], b0, b1);
            }
        }
    }
    // ---- finalize: denom reduce + write ----
    float inv[4];
    #pragma unroll
    for (int ri = 0; ri < 4; ri++) {
        float d = drow[ri];
        d += __shfl_xor_sync(0xffffffffu, d, 1);
        d += __shfl_xor_sync(0xffffffffu, d, 2);
        inv[ri] = 1.f / d;
    }
    #pragma unroll
    for (int m = 0; m < 2; m++)
        #pragma unroll
        for (int nd = 0; nd < 2; nd++) {
            int r0 = w*32 + m*16 + g, col = nd*8 + 2*t;
            float2 w0; w0.x = o[m][nd][0]*inv[m*2];   w0.y = o[m][nd][1]*inv[m*2];
            float2 w1; w1.x = o[m][nd][2]*inv[m*2+1]; w1.y = o[m][nd][3]*inv[m*2+1];
            *(float2*)&g_o[base + (size_t)r0*CC + col]     = w0;
            *(float2*)&g_o[base + (size_t)(r0+8)*CC + col] = w1;
        }
}

// ---------------- K3: t2 = o @ wo + t (register-tiled) --------------------
__global__ __launch_bounds__(256) void k3(const float* __restrict__ wo)
{
    __shared__ float os[64*68];
    __shared__ float ws[64*68];
    size_t row0 = (size_t)blockIdx.x * 64;
    int tid = threadIdx.x;
    for (int idx = tid; idx < 4096; idx += 256) {
        ws[(idx >> 6)*68 + (idx & 63)] = wo[idx];
        os[(idx >> 6)*68 + (idx & 63)] = g_o[row0*CC + idx];
    }
    __syncthreads();
    int tx = tid & 15, ty = tid >> 4;
    const float* wp = ws + 4*tx;
    float acc[4][4];
    #pragma unroll
    for (int r = 0; r < 4; r++)
        #pragma unroll
        for (int c = 0; c < 4; c++) acc[r][c] = 0.f;
    #pragma unroll 4
    for (int k4 = 0; k4 < 16; k4++) {
        float4 w0 = *(const float4*)&wp[(4*k4  )*68];
        float4 w1 = *(const float4*)&wp[(4*k4+1)*68];
        float4 w2 = *(const float4*)&wp[(4*k4+2)*68];
        float4 w3 = *(const float4*)&wp[(4*k4+3)*68];
        #pragma unroll
        for (int rr = 0; rr < 4; rr++) {
            float4 h = *(const float4*)&os[(ty*4 + rr)*68 + 4*k4];
            acc[rr][0] += h.x*w0.x + h.y*w1.x + h.z*w2.x + h.w*w3.x;
            acc[rr][1] += h.x*w0.y + h.y*w1.y + h.z*w2.y + h.w*w3.y;
            acc[rr][2] += h.x*w0.z + h.y*w1.z + h.z*w2.z + h.w*w3.z;
            acc[rr][3] += h.x*w0.w + h.y*w1.w + h.z*w2.w + h.w*w3.w;
        }
    }
    #pragma unroll
    for (int rr = 0; rr < 4; rr++) {
        float4 t4 = *(const float4*)&g_t[(row0 + ty*4 + rr)*CC + 4*tx];
        float4 r4;
        r4.x = acc[rr][0] + t4.x; r4.y = acc[rr][1] + t4.y;
        r4.z = acc[rr][2] + t4.z; r4.w = acc[rr][3] + t4.w;
        *(float4*)&g_o[(row0 + ty*4 + rr)*CC + 4*tx] = r4;
    }
}

// ---------------- K3b: deterministic patch_reverse + div ------------------
__global__ __launch_bounds__(256) void k3b()
{
    int e = blockIdx.x * 256 + threadIdx.x;
    int c   = e & 63;
    int pix = e >> 6;
    int b   = pix >> 16;
    int hw  = pix & 65535;
    int r   = hw >> 8, w = hw & 255;
    float acc = 0.f;
    int hc = d_cov_cnt[r], wc = d_cov_cnt[w];
    for (int i = 0; i < hc; i++) {
        int php = d_cov_p[r][i], li = d_cov_o[r][i];
        for (int k = 0; k < wc; k++) {
            int n = php*NHP + d_cov_p[w][k];
            int l = li*PP  + d_cov_o[w][k];
            acc += g_o[(((size_t)(b*NPAT + n))*LL + l)*CC + c];
        }
    }
    g_xs[e] = acc * d_invdiv[r] * d_invdiv[w];
}

// ---------------- K4: LN2 + fc1 + GELU (register-tiled) -------------------
__global__ __launch_bounds__(256) void k4(const float* __restrict__ g2,
                                          const float* __restrict__ b2,
                                          const float* __restrict__ fc1w,
                                          const float* __restrict__ fc1b)
{
    extern __shared__ float sm4[];
    float* fw  = sm4;                   // 64*132
    float* xsm = sm4 + 64*132;          // 32*68
    float* hsm = xsm + 32*68;           // 32*68
    float* mr  = hsm + 32*68;           // 64
    int tid = threadIdx.x;
    size_t pix0 = (size_t)blockIdx.x * 32;
    for (int idx = tid; idx < 64*MLP; idx += 256)
        fw[(idx >> 7)*132 + (idx & 127)] = fc1w[idx];
    for (int idx = tid; idx < 2048; idx += 256)
        xsm[(idx >> 6)*68 + (idx & 63)] = g_xs[pix0*CC + idx];
    __syncthreads();
    int lane = tid & 31, warp = tid >> 5;
    for (int r = warp; r < 32; r += 8) {
        float v0 = xsm[r*68+lane], v1 = xsm[r*68+lane+32];
        float s = v0+v1, ss = v0*v0+v1*v1;
        #pragma unroll
        for (int o = 16; o; o >>= 1) {
            s  += __shfl_xor_sync(0xffffffffu, s,  o);
            ss += __shfl_xor_sync(0xffffffffu, ss, o);
        }
        if (lane == 0) {
            float mean = s * (1.f/64.f);
            float var  = ss * (1.f/64.f) - mean*mean;
            mr[r*2]   = mean;
            mr[r*2+1] = rsqrtf(var + 1e-5f);
        }
    }
    __syncthreads();
    for (int idx = tid; idx < 2048; idx += 256) {
        int r = idx >> 6, c = idx & 63;
        hsm[r*68 + c] = (xsm[r*68 + c] - mr[r*2]) * mr[r*2+1] * g2[c] + b2[c];
    }
    __syncthreads();
    int tx = tid & 31, ty = tid >> 5;
    const float* wp = fw + 4*tx;
    float4 bias = *(const float4*)&fc1b[4*tx];
    float acc[4][4];
    #pragma unroll
    for (int r = 0; r < 4; r++) {
        acc[r][0] = bias.x; acc[r][1] = bias.y; acc[r][2] = bias.z; acc[r][3] = bias.w;
    }
    #pragma unroll 4
    for (int k4i = 0; k4i < 16; k4i++) {
        float4 w0 = *(const float4*)&wp[(4*k4i  )*132];
        float4 w1 = *(const float4*)&wp[(4*k4i+1)*132];
        float4 w2 = *(const float4*)&wp[(4*k4i+2)*132];
        float4 w3 = *(const float4*)&wp[(4*k4i+3)*132];
        #pragma unroll
        for (int rr = 0; rr < 4; rr++) {
            float4 h = *(const float4*)&hsm[(ty*4 + rr)*68 + 4*k4i];
            acc[rr][0] += h.x*w0.x + h.y*w1.x + h.z*w2.x + h.w*w3.x;
            acc[rr][1] += h.x*w0.y + h.y*w1.y + h.z*w2.y + h.w*w3.y;
            acc[rr][2] += h.x*w0.z + h.y*w1.z + h.z*w2.z + h.w*w3.z;
            acc[rr][3] += h.x*w0.w + h.y*w1.w + h.z*w2.w + h.w*w3.w;
        }
    }
    #pragma unroll
    for (int rr = 0; rr < 4; rr++) {
        float4 r4;
        r4.x = 0.5f*acc[rr][0]*(1.f + erff(acc[rr][0]*0.70710678118654752f));
        r4.y = 0.5f*acc[rr][1]*(1.f + erff(acc[rr][1]*0.70710678118654752f));
        r4.z = 0.5f*acc[rr][2]*(1.f + erff(acc[rr][2]*0.70710678118654752f));
        r4.w = 0.5f*acc[rr][3]*(1.f + erff(acc[rr][3]*0.70710678118654752f));
        *(float4*)&g_h1[(pix0 + ty*4 + rr)*MLP + 4*tx] = r4;
    }
}

// ---------------- K5: depthwise 5x5 + GELU + residual ---------------------
__global__ __launch_bounds__(128) void k5(const float* __restrict__ dww,
                                          const float* __restrict__ dwb)
{
    extern __shared__ float si[];            // 100*128
    int ch = threadIdx.x;
    int bx = blockIdx.x;
    int cw0 = (bx & 15) * 16;
    int r   = (bx >> 4) & 255;
    int b   = bx >> 12;
    float wreg[25];
    #pragma unroll
    for (int i = 0; i < 25; i++) wreg[i] = dww[ch*25 + i];
    float bias = dwb[ch];
    const float* hp = g_h1 + (size_t)b * HWSZ * MLP;

    for (int slot = 0; slot < 100; slot++) {
        int ry = slot / 20, cx = slot % 20;
        int rr = r + ry - 2, cc = cw0 + cx - 2;
        float v = 0.f;
        if (rr >= 0 && rr < 256 && cc >= 0 && cc < 256)
            v = hp[((size_t)rr*256 + cc)*MLP + ch];
        si[slot*MLP + ch] = v;
    }
    __syncthreads();

    float* op = g_h2 + ((size_t)b*HWSZ + (size_t)r*256 + cw0) * MLP;
    #pragma unroll 1
    for (int half = 0; half < 2; half++) {
        int k0 = half * 8;
        float val[5][12];
        #pragma unroll
        for (int dy = 0; dy < 5; dy++)
            #pragma unroll
            for (int xx = 0; xx < 12; xx++)
                val[dy][xx] = si[(dy*20 + k0 + xx)*MLP + ch];
        #pragma unroll
        for (int k = 0; k < 8; k++) {
            float acc = bias;
            #pragma unroll
            for (int dy = 0; dy < 5; dy++)
                #pragma unroll
                for (int dx = 0; dx < 5; dx++)
                    acc += val[dy][k + dx] * wreg[dy*5 + dx];
            float center = val[2][k + 2];
            float ge = 0.5f * acc * (1.f + erff(acc * 0.70710678118654752f));
            op[(size_t)(k0 + k)*MLP + ch] = center + ge;
        }
    }
}

// ---------------- K6: fc2 + bias + residual + transpose -------------------
__global__ __launch_bounds__(256) void k6(const float* __restrict__ fc2w,
                                          const float* __restrict__ fc2b,
                                          float* __restrict__ out)
{
    extern __shared__ float sm6[];
    float* hs   = sm6;                    // 64*132
    float* fw   = sm6 + 64*132;           // 128*68
    float* tile = fw  + 128*68;           // 64*68
    int tid = threadIdx.x;
    size_t pix0 = (size_t)blockIdx.x * 64;
    int b   = (int)(pix0 >> 16);
    int hw0 = (int)(pix0 & 65535);
    for (int idx = tid; idx < 8192; idx += 256) {
        fw[(idx >> 6)*68  + (idx & 63)]  = fc2w[idx];
        hs[(idx >> 7)*132 + (idx & 127)] = g_h2[pix0*MLP + idx];
    }
    __syncthreads();
    int tx = tid & 15, ty = tid >> 4;
    const float* wp = fw + 4*tx;
    float4 bias = *(const float4*)&fc2b[4*tx];
    float acc[4][4];
    #pragma unroll
    for (int r = 0; r < 4; r++) {
        acc[r][0] = bias.x; acc[r][1] = bias.y; acc[r][2] = bias.z; acc[r][3] = bias.w;
    }
    #pragma unroll 4
    for (int k4i = 0; k4i < 32; k4i++) {
        float4 w0 = *(const float4*)&wp[(4*k4i  )*68];
        float4 w1 = *(const float4*)&wp[(4*k4i+1)*68];
        float4 w2 = *(const float4*)&wp[(4*k4i+2)*68];
        float4 w3 = *(const float4*)&wp[(4*k4i+3)*68];
        #pragma unroll
        for (int rr = 0; rr < 4; rr++) {
            float4 h = *(const float4*)&hs[(ty*4 + rr)*132 + 4*k4i];
            acc[rr][0] += h.x*w0.x + h.y*w1.x + h.z*w2.x + h.w*w3.x;
            acc[rr][1] += h.x*w0.y + h.y*w1.y + h.z*w2.y + h.w*w3.y;
            acc[rr][2] += h.x*w0.z + h.y*w1.z + h.z*w2.z + h.w*w3.z;
            acc[rr][3] += h.x*w0.w + h.y*w1.w + h.z*w2.w + h.w*w3.w;
        }
    }
    #pragma unroll
    for (int rr = 0; rr < 4; rr++) {
        int r = ty*4 + rr;
        float4 x4 = *(const float4*)&g_xs[(pix0 + r)*CC + 4*tx];
        tile[(4*tx  )*68 + r] = acc[rr][0] + x4.x;
        tile[(4*tx+1)*68 + r] = acc[rr][1] + x4.y;
        tile[(4*tx+2)*68 + r] = acc[rr][2] + x4.z;
        tile[(4*tx+3)*68 + r] = acc[rr][3] + x4.w;
    }
    __syncthreads();
    for (int idx = tid; idx < 4096; idx += 256) {
        int c = idx >> 6, p = idx & 63;
        out[((size_t)(b*CC + c))*HWSZ + hw0 + p] = tile[c*68 + p];
    }
}

// ---------------- launch ---------------------------------------------------
extern "C" void kernel_launch(void* const* d_in, const int* in_sizes, int n_in,
                              void* d_out, int out_size)
{
    const float* x    = (const float*)d_in[0];
    const float* ln1g = (const float*)d_in[1];
    const float* ln1b = (const float*)d_in[2];
    const float* wq   = (const float*)d_in[3];
    const float* wk   = (const float*)d_in[4];
    const float* wv   = (const float*)d_in[5];
    const float* wo   = (const float*)d_in[6];
    const float* ln2g = (const float*)d_in[7];
    const float* ln2b = (const float*)d_in[8];
    const float* fc1w = (const float*)d_in[9];
    const float* fc1b = (const float*)d_in[10];
    const float* dww  = (const float*)d_in[11];
    const float* dwb  = (const float*)d_in[12];
    const float* fc2w = (const float*)d_in[13];
    const float* fc2b = (const float*)d_in[14];
    float* out = (float*)d_out;

    static int s_attr = 0;
    if (!s_attr) {
        cudaFuncSetAttribute(k1, cudaFuncAttributeMaxDynamicSharedMemorySize, (256*68 + 3*64*68)*4);
        cudaFuncSetAttribute(k2, cudaFuncAttributeMaxDynamicSharedMemorySize, 3*256*20*4);
        cudaFuncSetAttribute(k4, cudaFuncAttributeMaxDynamicSharedMemorySize, (64*132 + 2*32*68 + 64)*4);
        cudaFuncSetAttribute(k5, cudaFuncAttributeMaxDynamicSharedMemorySize, 100*128*4);
        cudaFuncSetAttribute(k6, cudaFuncAttributeMaxDynamicSharedMemorySize, (64*132 + 128*68 + 64*68)*4);
        s_attr = 1;
    }

    k_init<<<1, 256>>>();
    k1<<<BN, 256, (256*68 + 3*64*68)*4>>>(x, ln1g, ln1b, wq, wk, wv);
    k2<<<dim3(BN, NHEAD), 256, 3*256*20*4>>>();
    k3<<<(BN*LL)/64, 256>>>(wo);
    k3b<<<(BB*HWSZ*CC)/256, 256>>>();
    k4<<<(BB*HWSZ)/32, 256, (64*132 + 2*32*68 + 64)*4>>>(ln2g, ln2b, fc1w, fc1b);
    k5<<<BB*256*16, 128, 100*128*4>>>(dww, dwb);
    k6<<<(BB*HWSZ)/64, 256, (64*132 + 128*68 + 64*68)*4>>>(fc2w, fc2b, out);
}

// round 4
// speedup vs baseline: 2.6701x; 1.2382x over previous
#include <cuda_runtime.h>
#include <cuda_bf16.h>
#include <cstddef>

// ---------------- problem geometry (fixed by setup_inputs) ----------------
#define BB    2
#define CC    64
#define HH    256
#define WW    256
#define PP    16
#define STEP  14
#define NHP   19
#define NPAT  361
#define BN    722
#define LL    256
#define NHEAD 4
#define DHEAD 16
#define MLP   128
#define HWSZ  65536

#define QSCALE 0.36067376022224085f   // 0.25 * log2(e)

// ---------------- scratch ----------
__device__ float g_t [(size_t)BN*LL*CC];
__device__ float g_q [(size_t)BN*LL*CC];
__device__ float g_k [(size_t)BN*LL*CC];
__device__ float g_v [(size_t)BN*LL*CC];
__device__ float g_o [(size_t)BN*LL*CC];
__device__ float g_xs[(size_t)BB*HWSZ*CC];
__device__ float g_h1[(size_t)BB*HWSZ*MLP];
__device__ float g_h2[(size_t)BB*HWSZ*MLP];

__device__ int   d_cov_cnt[256];
__device__ int   d_cov_p[256][2];
__device__ int   d_cov_o[256][2];
__device__ float d_invdiv[256];

__global__ void k_init()
{
    int r = threadIdx.x;
    if (r < 256) {
        int cnt = 0;
        for (int ph = 0; ph < NHP; ph++) {
            int top = min(STEP*ph, HH-PP);
            if (r >= top && r < top + PP && cnt < 2) {
                d_cov_p[r][cnt] = ph;
                d_cov_o[r][cnt] = r - top;
                cnt++;
            }
        }
        d_cov_cnt[r] = cnt;
    }
    if (threadIdx.x == 0) {
        float div[256];
        for (int i = 0; i < 256; i++) div[i] = 1.f;
        for (int i = STEP; i < HH + STEP - PP; i += STEP) {
            int top = (i + PP > HH) ? (HH - PP) : i;
            for (int r2 = top; r2 < i + PP - STEP; ++r2) div[r2] *= 2.f;
        }
        for (int i = 0; i < 256; i++) d_invdiv[i] = 1.f / div[i];
    }
}

// ---------------- mma helpers ---------------------------------------------
__device__ __forceinline__ unsigned f2tf(float x) {
    unsigned r; asm("cvt.rna.tf32.f32 %0, %1;" : "=r"(r) : "f"(x)); return r;
}
__device__ __forceinline__ float ex2(float x) {
    float r; asm("ex2.approx.ftz.f32 %0, %1;" : "=f"(r) : "f"(x)); return r;
}
__device__ __forceinline__ void mma_tf32(float* d, const unsigned* a,
                                         unsigned b0, unsigned b1) {
    asm volatile("mma.sync.aligned.m16n8k8.row.col.f32.tf32.tf32.f32 "
        "{%0,%1,%2,%3},{%4,%5,%6,%7},{%8,%9},{%0,%1,%2,%3};"
        : "+f"(d[0]), "+f"(d[1]), "+f"(d[2]), "+f"(d[3])
        : "r"(a[0]), "r"(a[1]), "r"(a[2]), "r"(a[3]), "r"(b0), "r"(b1));
}
__device__ __forceinline__ float gelu(float x) {
    return 0.5f * x * (1.f + erff(x * 0.70710678118654752f));
}

// ---------------- K1: gather + LN1 + QKV via tf32 mma ---------------------
// block = patch (722), 256 thr = 8 warps. smem: h tf32 [256][68] + wT [3][64][68]
__global__ __launch_bounds__(256) void k1(const float* __restrict__ x,
                                          const float* __restrict__ g1,
                                          const float* __restrict__ b1,
                                          const float* __restrict__ wq,
                                          const float* __restrict__ wk,
                                          const float* __restrict__ wv)
{
    extern __shared__ float sm[];
    float*    ps = sm;                         // 256*68 (fp32 -> tf32 bits)
    unsigned* ws = (unsigned*)(sm + 256*68);   // 3*64*68 transposed tf32
    int tid = threadIdx.x;
    int bn = blockIdx.x;
    int b  = bn / NPAT, n = bn % NPAT;
    int ph = n / NHP,   pw = n % NHP;
    int top  = min(STEP*ph, HH-PP);
    int left = min(STEP*pw, WW-PP);
    const float* xb = x + (size_t)b * CC * HWSZ;

    // weights: transpose + cvt. wT[j][c] = w[c][j]
    for (int idx = tid; idx < 3*64*64; idx += 256) {
        int mat = idx >> 12; int rem = idx & 4095;
        int c = rem >> 6, j = rem & 63;
        const float* w = (mat == 0) ? wq : (mat == 1) ? wk : wv;
        ws[mat*64*68 + j*68 + c] = f2tf(w[rem]);
    }
    // gather patch
    for (int idx = tid; idx < CC*LL; idx += 256) {
        int c = idx >> 8, l = idx & 255;
        int li = l >> 4, lj = l & 15;
        ps[l*68 + c] = xb[(size_t)c*HWSZ + (size_t)(top+li)*WW + (left+lj)];
    }
    __syncthreads();

    // LN1 per token; store residual t (fp32); write normalized h as tf32 bits
    int lane = tid & 31, warp = tid >> 5;
    float ga = g1[lane], gb = g1[lane+32], ba = b1[lane], bbv = b1[lane+32];
    for (int l = warp; l < LL; l += 8) {
        float v0 = ps[l*68 + lane], v1 = ps[l*68 + lane + 32];
        size_t tb = ((size_t)bn*LL + l) * CC;
        g_t[tb + lane] = v0;  g_t[tb + lane + 32] = v1;
        float s = v0 + v1, ss = v0*v0 + v1*v1;
        #pragma unroll
        for (int o = 16; o; o >>= 1) {
            s  += __shfl_xor_sync(0xffffffffu, s,  o);
            ss += __shfl_xor_sync(0xffffffffu, ss, o);
        }
        float mean = s * (1.f/64.f);
        float var  = ss * (1.f/64.f) - mean*mean;
        float rstd = rsqrtf(var + 1e-5f);
        ps[l*68 + lane]      = __uint_as_float(f2tf((v0 - mean) * rstd * ga + ba));
        ps[l*68 + lane + 32] = __uint_as_float(f2tf((v1 - mean) * rstd * gb + bbv));
    }
    __syncthreads();

    // GEMM: warp = 32 rows (2 m-tiles) x 64 cols per mat
    const unsigned* hs = (const unsigned*)ps;
    int g = lane >> 2, t = lane & 3;
    int r0 = (warp*32 + g)*68;
    unsigned aq[2][8][4];
    #pragma unroll
    for (int m = 0; m < 2; m++)
        #pragma unroll
        for (int kt = 0; kt < 8; kt++) {
            int rb = r0 + m*16*68, c0 = kt*8 + t;
            aq[m][kt][0] = hs[rb + c0];
            aq[m][kt][1] = hs[rb + 544 + c0];
            aq[m][kt][2] = hs[rb + c0 + 4];
            aq[m][kt][3] = hs[rb + 544 + c0 + 4];
        }
    #pragma unroll 1
    for (int mat = 0; mat < 3; mat++) {
        const unsigned* wm = ws + mat*64*68;
        float* out = (mat == 0) ? g_q : (mat == 1) ? g_k : g_v;
        float acc[2][8][4];
        #pragma unroll
        for (int m = 0; m < 2; m++)
            #pragma unroll
            for (int nt = 0; nt < 8; nt++)
                #pragma unroll
                for (int i = 0; i < 4; i++) acc[m][nt][i] = 0.f;
        #pragma unroll
        for (int nt = 0; nt < 8; nt++)
            #pragma unroll
            for (int kt = 0; kt < 8; kt++) {
                int jr = (nt*8 + g)*68 + kt*8 + t;
                unsigned b0 = wm[jr], b1 = wm[jr + 4];
                mma_tf32(acc[0][nt], aq[0][kt], b0, b1);
                mma_tf32(acc[1][nt], aq[1][kt], b0, b1);
            }
        #pragma unroll
        for (int m = 0; m < 2; m++)
            #pragma unroll
            for (int nt = 0; nt < 8; nt++) {
                int row = warp*32 + m*16 + g, col = nt*8 + 2*t;
                float2 w0; w0.x = acc[m][nt][0]; w0.y = acc[m][nt][1];
                float2 w1; w1.x = acc[m][nt][2]; w1.y = acc[m][nt][3];
                *(float2*)&out[((size_t)bn*LL + row)*CC + col]     = w0;
                *(float2*)&out[((size_t)bn*LL + row + 8)*CC + col] = w1;
            }
    }
}

// ---------------- K2: attention via tf32 mma.sync (flash-style) -----------
__global__ __launch_bounds__(256) void k2()
{
    extern __shared__ unsigned sm2[];
    unsigned* qs = sm2;            // 256*20
    unsigned* ks = sm2 + 5120;
    unsigned* vs = sm2 + 10240;
    int tid = threadIdx.x;
    int bn = blockIdx.x, head = blockIdx.y;
    size_t base = (size_t)bn*LL*CC + head*DHEAD;

    for (int idx = tid; idx < 1024; idx += 256) {
        int row = idx >> 2, c4 = (idx & 3) * 4;
        size_t ga = base + (size_t)row*CC + c4;
        float4 q4 = *(const float4*)&g_q[ga];
        float4 k4 = *(const float4*)&g_k[ga];
        float4 v4 = *(const float4*)&g_v[ga];
        uint4 qu = { f2tf(q4.x*QSCALE), f2tf(q4.y*QSCALE),
                     f2tf(q4.z*QSCALE), f2tf(q4.w*QSCALE) };
        uint4 ku = { f2tf(k4.x), f2tf(k4.y), f2tf(k4.z), f2tf(k4.w) };
        uint4 vu = { f2tf(v4.x), f2tf(v4.y), f2tf(v4.z), f2tf(v4.w) };
        *(uint4*)&qs[row*20 + c4] = qu;
        *(uint4*)&ks[row*20 + c4] = ku;
        *(uint4*)&vs[row*20 + c4] = vu;
    }
    __syncthreads();

    int lane = tid & 31, w = tid >> 5, g = lane >> 2, t = lane & 3;

    unsigned aq[2][2][4];
    #pragma unroll
    for (int m = 0; m < 2; m++)
        #pragma unroll
        for (int kt = 0; kt < 2; kt++) {
            int r0 = (w*32 + m*16 + g)*20, c0 = kt*8 + t;
            aq[m][kt][0] = qs[r0 + c0];
            aq[m][kt][1] = qs[r0 + 160 + c0];
            aq[m][kt][2] = qs[r0 + c0 + 4];
            aq[m][kt][3] = qs[r0 + 160 + c0 + 4];
        }

    float o[2][2][4];
    #pragma unroll
    for (int m = 0; m < 2; m++)
        #pragma unroll
        for (int nd = 0; nd < 2; nd++)
            #pragma unroll
            for (int i = 0; i < 4; i++) o[m][nd][i] = 0.f;
    float mrow[4] = {-1e30f, -1e30f, -1e30f, -1e30f};
    float drow[4] = {0.f, 0.f, 0.f, 0.f};

    #pragma unroll 1
    for (int jt = 0; jt < 8; jt++) {
        float s[2][4][4];
        #pragma unroll
        for (int m = 0; m < 2; m++)
            #pragma unroll
            for (int nt = 0; nt < 4; nt++)
                #pragma unroll
                for (int i = 0; i < 4; i++) s[m][nt][i] = 0.f;
        #pragma unroll
        for (int nt = 0; nt < 4; nt++) {
            #pragma unroll
            for (int kt = 0; kt < 2; kt++) {
                int jr = (jt*32 + nt*8 + g)*20 + kt*8 + t;
                unsigned b0 = ks[jr], b1 = ks[jr + 4];
                mma_tf32(s[0][nt], aq[0][kt], b0, b1);
                mma_tf32(s[1][nt], aq[1][kt], b0, b1);
            }
        }
        #pragma unroll
        for (int m = 0; m < 2; m++) {
            #pragma unroll
            for (int h = 0; h < 2; h++) {
                int ri = m*2 + h;
                float mx = fmaxf(s[m][0][h*2], s[m][0][h*2+1]);
                #pragma unroll
                for (int nt = 1; nt < 4; nt++)
                    mx = fmaxf(mx, fmaxf(s[m][nt][h*2], s[m][nt][h*2+1]));
                mx = fmaxf(mx, __shfl_xor_sync(0xffffffffu, mx, 1));
                mx = fmaxf(mx, __shfl_xor_sync(0xffffffffu, mx, 2));
                float mn = fmaxf(mrow[ri], mx);
                float scale = ex2(mrow[ri] - mn);
                mrow[ri] = mn;
                drow[ri] *= scale;
                #pragma unroll
                for (int nd = 0; nd < 2; nd++) {
                    o[m][nd][h*2]   *= scale;
                    o[m][nd][h*2+1] *= scale;
                }
                float psum = 0.f;
                #pragma unroll
                for (int nt = 0; nt < 4; nt++) {
                    float e0 = ex2(s[m][nt][h*2]   - mn);
                    float e1 = ex2(s[m][nt][h*2+1] - mn);
                    s[m][nt][h*2] = e0; s[m][nt][h*2+1] = e1;
                    psum += e0 + e1;
                }
                drow[ri] += psum;
            }
        }
        unsigned p[2][4][4];
        #pragma unroll
        for (int m = 0; m < 2; m++)
            #pragma unroll
            for (int nt = 0; nt < 4; nt++)
                #pragma unroll
                for (int i = 0; i < 4; i++) p[m][nt][i] = f2tf(s[m][nt][i]);
        int sl0 = (lane & ~3) + (t >> 1);
        int sl2 = sl0 + 2;
        #pragma unroll
        for (int kt = 0; kt < 4; kt++) {
            unsigned ap[2][4];
            #pragma unroll
            for (int m = 0; m < 2; m++) {
                unsigned r0 = __shfl_sync(0xffffffffu, p[m][kt][0], sl0);
                unsigned r1 = __shfl_sync(0xffffffffu, p[m][kt][1], sl0);
                ap[m][0] = (t & 1) ? r1 : r0;
                r0 = __shfl_sync(0xffffffffu, p[m][kt][0], sl2);
                r1 = __shfl_sync(0xffffffffu, p[m][kt][1], sl2);
                ap[m][2] = (t & 1) ? r1 : r0;
                r0 = __shfl_sync(0xffffffffu, p[m][kt][2], sl0);
                r1 = __shfl_sync(0xffffffffu, p[m][kt][3], sl0);
                ap[m][1] = (t & 1) ? r1 : r0;
                r0 = __shfl_sync(0xffffffffu, p[m][kt][2], sl2);
                r1 = __shfl_sync(0xffffffffu, p[m][kt][3], sl2);
                ap[m][3] = (t & 1) ? r1 : r0;
            }
            #pragma unroll
            for (int nd = 0; nd < 2; nd++) {
                int vr = (jt*32 + kt*8 + t)*20 + nd*8 + g;
                unsigned b0 = vs[vr], b1 = vs[vr + 80];
                mma_tf32(o[0][nd], ap[0], b0, b1);
                mma_tf32(o[1][nd], ap[1], b0, b1);
            }
        }
    }
    float inv[4];
    #pragma unroll
    for (int ri = 0; ri < 4; ri++) {
        float d = drow[ri];
        d += __shfl_xor_sync(0xffffffffu, d, 1);
        d += __shfl_xor_sync(0xffffffffu, d, 2);
        inv[ri] = 1.f / d;
    }
    #pragma unroll
    for (int m = 0; m < 2; m++)
        #pragma unroll
        for (int nd = 0; nd < 2; nd++) {
            int r0 = w*32 + m*16 + g, col = nd*8 + 2*t;
            float2 w0; w0.x = o[m][nd][0]*inv[m*2];   w0.y = o[m][nd][1]*inv[m*2];
            float2 w1; w1.x = o[m][nd][2]*inv[m*2+1]; w1.y = o[m][nd][3]*inv[m*2+1];
            *(float2*)&g_o[base + (size_t)r0*CC + col]     = w0;
            *(float2*)&g_o[base + (size_t)(r0+8)*CC + col] = w1;
        }
}

// ---------------- K3: t2 = o @ wo + t via tf32 mma ------------------------
// block: 256 rows x 64 cols, 8 warps (warp = 32 rows)
__global__ __launch_bounds__(256) void k3(const float* __restrict__ wo)
{
    extern __shared__ unsigned sm3[];
    unsigned* os = sm3;              // 256*68
    unsigned* ws = sm3 + 256*68;     // 64*68 transposed
    size_t row0 = (size_t)blockIdx.x * 256;
    int tid = threadIdx.x;
    for (int idx = tid; idx < 4096; idx += 256) {
        int row = idx >> 4, c4 = (idx & 15) * 4;
        float4 v = *(const float4*)&g_o[(row0 + row)*CC + c4];
        uint4 u = { f2tf(v.x), f2tf(v.y), f2tf(v.z), f2tf(v.w) };
        *(uint4*)&os[row*68 + c4] = u;
    }
    for (int idx = tid; idx < 4096; idx += 256) {
        int c = idx >> 6, j = idx & 63;
        ws[j*68 + c] = f2tf(wo[idx]);
    }
    __syncthreads();

    int lane = tid & 31, w = tid >> 5, g = lane >> 2, t = lane & 3;
    int r0 = (w*32 + g)*68;
    unsigned aq[2][8][4];
    #pragma unroll
    for (int m = 0; m < 2; m++)
        #pragma unroll
        for (int kt = 0; kt < 8; kt++) {
            int rb = r0 + m*16*68, c0 = kt*8 + t;
            aq[m][kt][0] = os[rb + c0];
            aq[m][kt][1] = os[rb + 544 + c0];
            aq[m][kt][2] = os[rb + c0 + 4];
            aq[m][kt][3] = os[rb + 544 + c0 + 4];
        }
    float acc[2][8][4];
    #pragma unroll
    for (int m = 0; m < 2; m++)
        #pragma unroll
        for (int nt = 0; nt < 8; nt++)
            #pragma unroll
            for (int i = 0; i < 4; i++) acc[m][nt][i] = 0.f;
    #pragma unroll
    for (int nt = 0; nt < 8; nt++)
        #pragma unroll
        for (int kt = 0; kt < 8; kt++) {
            int jr = (nt*8 + g)*68 + kt*8 + t;
            unsigned b0 = ws[jr], b1 = ws[jr + 4];
            mma_tf32(acc[0][nt], aq[0][kt], b0, b1);
            mma_tf32(acc[1][nt], aq[1][kt], b0, b1);
        }
    #pragma unroll
    for (int m = 0; m < 2; m++)
        #pragma unroll
        for (int nt = 0; nt < 8; nt++) {
            int row = w*32 + m*16 + g, col = nt*8 + 2*t;
            size_t a0 = (row0 + row)*CC + col;
            size_t a1 = (row0 + row + 8)*CC + col;
            float2 t0 = *(const float2*)&g_t[a0];
            float2 t1 = *(const float2*)&g_t[a1];
            float2 w0; w0.x = acc[m][nt][0] + t0.x; w0.y = acc[m][nt][1] + t0.y;
            float2 w1; w1.x = acc[m][nt][2] + t1.x; w1.y = acc[m][nt][3] + t1.y;
            *(float2*)&g_o[a0] = w0;
            *(float2*)&g_o[a1] = w1;
        }
}

// ---------------- K3b: deterministic patch_reverse + div ------------------
__global__ __launch_bounds__(256) void k3b()
{
    int e = blockIdx.x * 256 + threadIdx.x;
    int c   = e & 63;
    int pix = e >> 6;
    int b   = pix >> 16;
    int hw  = pix & 65535;
    int r   = hw >> 8, w = hw & 255;
    float acc = 0.f;
    int hc = d_cov_cnt[r], wc = d_cov_cnt[w];
    for (int i = 0; i < hc; i++) {
        int php = d_cov_p[r][i], li = d_cov_o[r][i];
        for (int k = 0; k < wc; k++) {
            int n = php*NHP + d_cov_p[w][k];
            int l = li*PP  + d_cov_o[w][k];
            acc += g_o[(((size_t)(b*NPAT + n))*LL + l)*CC + c];
        }
    }
    g_xs[e] = acc * d_invdiv[r] * d_invdiv[w];
}

// ---------------- K4: LN2 + fc1 + GELU via tf32 mma -----------------------
// block: 128 rows x 128 cols, 8 warps (warp = 16 rows)
__global__ __launch_bounds__(256) void k4(const float* __restrict__ g2,
                                          const float* __restrict__ b2,
                                          const float* __restrict__ fc1w,
                                          const float* __restrict__ fc1b)
{
    extern __shared__ float sm4[];
    float*    xsm = sm4;                        // 128*68 fp32 -> tf32 bits
    unsigned* fw  = (unsigned*)(sm4 + 128*68);  // 128*68 transposed tf32
    int tid = threadIdx.x;
    size_t pix0 = (size_t)blockIdx.x * 128;
    for (int idx = tid; idx < 2048; idx += 256) {
        int row = idx >> 4, c4 = (idx & 15) * 4;
        *(float4*)&xsm[row*68 + c4] = *(const float4*)&g_xs[(pix0 + row)*CC + row*0 + c4];
    }
    for (int idx = tid; idx < 8192; idx += 256) {
        int c = idx >> 7, j = idx & 127;
        fw[j*68 + c] = f2tf(fc1w[idx]);
    }
    __syncthreads();

    int lane = tid & 31, warp = tid >> 5;
    float ga = g2[lane], gb = g2[lane+32], ba = b2[lane], bbv = b2[lane+32];
    for (int r = warp; r < 128; r += 8) {
        float v0 = xsm[r*68+lane], v1 = xsm[r*68+lane+32];
        float s = v0+v1, ss = v0*v0+v1*v1;
        #pragma unroll
        for (int o = 16; o; o >>= 1) {
            s  += __shfl_xor_sync(0xffffffffu, s,  o);
            ss += __shfl_xor_sync(0xffffffffu, ss, o);
        }
        float mean = s * (1.f/64.f);
        float var  = ss * (1.f/64.f) - mean*mean;
        float rstd = rsqrtf(var + 1e-5f);
        xsm[r*68+lane]    = __uint_as_float(f2tf((v0 - mean) * rstd * ga + ba));
        xsm[r*68+lane+32] = __uint_as_float(f2tf((v1 - mean) * rstd * gb + bbv));
    }
    __syncthreads();

    const unsigned* hs = (const unsigned*)xsm;
    int g = lane >> 2, t = lane & 3;
    int r0 = (warp*16 + g)*68;
    unsigned aq[8][4];
    #pragma unroll
    for (int kt = 0; kt < 8; kt++) {
        int c0 = kt*8 + t;
        aq[kt][0] = hs[r0 + c0];
        aq[kt][1] = hs[r0 + 544 + c0];
        aq[kt][2] = hs[r0 + c0 + 4];
        aq[kt][3] = hs[r0 + 544 + c0 + 4];
    }
    float acc[16][4];
    #pragma unroll
    for (int nt = 0; nt < 16; nt++) {
        float2 bb = *(const float2*)&fc1b[nt*8 + 2*t];
        acc[nt][0] = bb.x; acc[nt][1] = bb.y; acc[nt][2] = bb.x; acc[nt][3] = bb.y;
    }
    #pragma unroll
    for (int nt = 0; nt < 16; nt++)
        #pragma unroll
        for (int kt = 0; kt < 8; kt++) {
            int jr = (nt*8 + g)*68 + kt*8 + t;
            unsigned b0 = fw[jr], b1 = fw[jr + 4];
            mma_tf32(acc[nt], aq[kt], b0, b1);
        }
    #pragma unroll
    for (int nt = 0; nt < 16; nt++) {
        int row = warp*16 + g, col = nt*8 + 2*t;
        float2 w0; w0.x = gelu(acc[nt][0]); w0.y = gelu(acc[nt][1]);
        float2 w1; w1.x = gelu(acc[nt][2]); w1.y = gelu(acc[nt][3]);
        *(float2*)&g_h1[(pix0 + row)*MLP + col]     = w0;
        *(float2*)&g_h1[(pix0 + row + 8)*MLP + col] = w1;
    }
}

// ---------------- K5: depthwise 5x5 + GELU + residual ---------------------
__global__ __launch_bounds__(128) void k5(const float* __restrict__ dww,
                                          const float* __restrict__ dwb)
{
    extern __shared__ float si[];            // 100*128
    int ch = threadIdx.x;
    int bx = blockIdx.x;
    int cw0 = (bx & 15) * 16;
    int r   = (bx >> 4) & 255;
    int b   = bx >> 12;
    float wreg[25];
    #pragma unroll
    for (int i = 0; i < 25; i++) wreg[i] = dww[ch*25 + i];
    float bias = dwb[ch];
    const float* hp = g_h1 + (size_t)b * HWSZ * MLP;

    for (int slot = 0; slot < 100; slot++) {
        int ry = slot / 20, cx = slot % 20;
        int rr = r + ry - 2, cc = cw0 + cx - 2;
        float v = 0.f;
        if (rr >= 0 && rr < 256 && cc >= 0 && cc < 256)
            v = hp[((size_t)rr*256 + cc)*MLP + ch];
        si[slot*MLP + ch] = v;
    }
    __syncthreads();

    float* op = g_h2 + ((size_t)b*HWSZ + (size_t)r*256 + cw0) * MLP;
    #pragma unroll 1
    for (int half = 0; half < 2; half++) {
        int k0 = half * 8;
        float val[5][12];
        #pragma unroll
        for (int dy = 0; dy < 5; dy++)
            #pragma unroll
            for (int xx = 0; xx < 12; xx++)
                val[dy][xx] = si[(dy*20 + k0 + xx)*MLP + ch];
        #pragma unroll
        for (int k = 0; k < 8; k++) {
            float acc = bias;
            #pragma unroll
            for (int dy = 0; dy < 5; dy++)
                #pragma unroll
                for (int dx = 0; dx < 5; dx++)
                    acc += val[dy][k + dx] * wreg[dy*5 + dx];
            float center = val[2][k + 2];
            op[(size_t)(k0 + k)*MLP + ch] = center + gelu(acc);
        }
    }
}

// ---------------- K6: fc2 + bias + residual + transpose via tf32 mma ------
// block: 128 pixels x 64 cols, K=128. 8 warps (warp = 16 rows)
__global__ __launch_bounds__(256) void k6(const float* __restrict__ fc2w,
                                          const float* __restrict__ fc2b,
                                          float* __restrict__ out)
{
    extern __shared__ unsigned sm6[];
    unsigned* hs = sm6;              // 128*132 tf32
    unsigned* fw = sm6 + 128*132;    // 64*132 transposed tf32 (reused as out tile)
    float*  tile = (float*)fw;
    int tid = threadIdx.x;
    size_t pix0 = (size_t)blockIdx.x * 128;
    int b   = (int)(pix0 >> 16);
    int hw0 = (int)(pix0 & 65535);
    for (int idx = tid; idx < 4096; idx += 256) {
        int row = idx >> 5, c4 = (idx & 31) * 4;
        float4 v = *(const float4*)&g_h2[(pix0 + row)*MLP + c4];
        uint4 u = { f2tf(v.x), f2tf(v.y), f2tf(v.z), f2tf(v.w) };
        *(uint4*)&hs[row*132 + c4] = u;
    }
    for (int idx = tid; idx < 8192; idx += 256) {
        int c = idx >> 6, j = idx & 63;
        fw[j*132 + c] = f2tf(fc2w[idx]);
    }
    __syncthreads();

    int lane = tid & 31, w = tid >> 5, g = lane >> 2, t = lane & 3;
    int r0 = (w*16 + g)*132;
    unsigned aq[16][4];
    #pragma unroll
    for (int kt = 0; kt < 16; kt++) {
        int c0 = kt*8 + t;
        aq[kt][0] = hs[r0 + c0];
        aq[kt][1] = hs[r0 + 8*132 + c0];
        aq[kt][2] = hs[r0 + c0 + 4];
        aq[kt][3] = hs[r0 + 8*132 + c0 + 4];
    }
    float acc[8][4];
    #pragma unroll
    for (int nt = 0; nt < 8; nt++)
        #pragma unroll
        for (int i = 0; i < 4; i++) acc[nt][i] = 0.f;
    #pragma unroll
    for (int nt = 0; nt < 8; nt++)
        #pragma unroll
        for (int kt = 0; kt < 16; kt++) {
            int jr = (nt*8 + g)*132 + kt*8 + t;
            unsigned b0 = fw[jr], b1 = fw[jr + 4];
            mma_tf32(acc[nt], aq[kt], b0, b1);
        }
    __syncthreads();   // weights fully consumed; reuse fw as transpose tile
    #pragma unroll
    for (int nt = 0; nt < 8; nt++) {
        int row = w*16 + g, col = nt*8 + 2*t;
        float2 bb = *(const float2*)&fc2b[col];
        float2 x0 = *(const float2*)&g_xs[(pix0 + row)*CC + col];
        float2 x1 = *(const float2*)&g_xs[(pix0 + row + 8)*CC + col];
        tile[(col  )*132 + row]     = acc[nt][0] + bb.x + x0.x;
        tile[(col+1)*132 + row]     = acc[nt][1] + bb.y + x0.y;
        tile[(col  )*132 + row + 8] = acc[nt][2] + bb.x + x1.x;
        tile[(col+1)*132 + row + 8] = acc[nt][3] + bb.y + x1.y;
    }
    __syncthreads();
    for (int idx = tid; idx < 2048; idx += 256) {
        int c = idx >> 5, p4 = (idx & 31) * 4;
        *(float4*)&out[((size_t)(b*CC + c))*HWSZ + hw0 + p4] = *(const float4*)&tile[c*132 + p4];
    }
}

// ---------------- launch ---------------------------------------------------
extern "C" void kernel_launch(void* const* d_in, const int* in_sizes, int n_in,
                              void* d_out, int out_size)
{
    const float* x    = (const float*)d_in[0];
    const float* ln1g = (const float*)d_in[1];
    const float* ln1b = (const float*)d_in[2];
    const float* wq   = (const float*)d_in[3];
    const float* wk   = (const float*)d_in[4];
    const float* wv   = (const float*)d_in[5];
    const float* wo   = (const float*)d_in[6];
    const float* ln2g = (const float*)d_in[7];
    const float* ln2b = (const float*)d_in[8];
    const float* fc1w = (const float*)d_in[9];
    const float* fc1b = (const float*)d_in[10];
    const float* dww  = (const float*)d_in[11];
    const float* dwb  = (const float*)d_in[12];
    const float* fc2w = (const float*)d_in[13];
    const float* fc2b = (const float*)d_in[14];
    float* out = (float*)d_out;

    static int s_attr = 0;
    if (!s_attr) {
        cudaFuncSetAttribute(k1, cudaFuncAttributeMaxDynamicSharedMemorySize, (256*68 + 3*64*68)*4);
        cudaFuncSetAttribute(k2, cudaFuncAttributeMaxDynamicSharedMemorySize, 3*256*20*4);
        cudaFuncSetAttribute(k3, cudaFuncAttributeMaxDynamicSharedMemorySize, (256*68 + 64*68)*4);
        cudaFuncSetAttribute(k4, cudaFuncAttributeMaxDynamicSharedMemorySize, (128*68 + 128*68)*4);
        cudaFuncSetAttribute(k5, cudaFuncAttributeMaxDynamicSharedMemorySize, 100*128*4);
        cudaFuncSetAttribute(k6, cudaFuncAttributeMaxDynamicSharedMemorySize, (128*132 + 64*132)*4);
        s_attr = 1;
    }

    k_init<<<1, 256>>>();
    k1<<<BN, 256, (256*68 + 3*64*68)*4>>>(x, ln1g, ln1b, wq, wk, wv);
    k2<<<dim3(BN, NHEAD), 256, 3*256*20*4>>>();
    k3<<<(BN*LL)/256, 256, (256*68 + 64*68)*4>>>(wo);
    k3b<<<(BB*HWSZ*CC)/256, 256>>>();
    k4<<<(BB*HWSZ)/128, 256, (128*68 + 128*68)*4>>>(ln2g, ln2b, fc1w, fc1b);
    k5<<<BB*256*16, 128, 100*128*4>>>(dww, dwb);
    k6<<<(BB*HWSZ)/128, 256, (128*132 + 64*132)*4>>>(fc2w, fc2b, out);
}

// round 5
// speedup vs baseline: 2.8605x; 1.0713x over previous
#include <cuda_runtime.h>
#include <cuda_bf16.h>
#include <cstddef>

// ---------------- problem geometry (fixed by setup_inputs) ----------------
#define BB    2
#define CC    64
#define HH    256
#define WW    256
#define PP    16
#define STEP  14
#define NHP   19
#define NPAT  361
#define BN    722
#define LL    256
#define NHEAD 4
#define DHEAD 16
#define MLP   128
#define HWSZ  65536

#define QSCALE 0.36067376022224085f   // 0.25 * log2(e)

#define KSTR 264   // K^T row stride (words): 264 % 32 == 8  -> conflict-free loads
#define VSTR 268   // V^T row stride (words): 268 % 32 == 12 -> conflict-free both ways

// ---------------- scratch ----------
__device__ float g_t [(size_t)BN*LL*CC];
__device__ float g_o [(size_t)BN*LL*CC];
__device__ float g_xs[(size_t)BB*HWSZ*CC];
__device__ float g_h1[(size_t)BB*HWSZ*MLP];
__device__ float g_h2[(size_t)BB*HWSZ*MLP];

__device__ int   d_cov_cnt[256];
__device__ int   d_cov_p[256][2];
__device__ int   d_cov_o[256][2];
__device__ float d_invdiv[256];

__global__ void k_init()
{
    int r = threadIdx.x;
    if (r < 256) {
        int cnt = 0;
        for (int ph = 0; ph < NHP; ph++) {
            int top = min(STEP*ph, HH-PP);
            if (r >= top && r < top + PP && cnt < 2) {
                d_cov_p[r][cnt] = ph;
                d_cov_o[r][cnt] = r - top;
                cnt++;
            }
        }
        d_cov_cnt[r] = cnt;
    }
    if (threadIdx.x == 0) {
        float div[256];
        for (int i = 0; i < 256; i++) div[i] = 1.f;
        for (int i = STEP; i < HH + STEP - PP; i += STEP) {
            int top = (i + PP > HH) ? (HH - PP) : i;
            for (int r2 = top; r2 < i + PP - STEP; ++r2) div[r2] *= 2.f;
        }
        for (int i = 0; i < 256; i++) d_invdiv[i] = 1.f / div[i];
    }
}

// ---------------- mma helpers ---------------------------------------------
__device__ __forceinline__ unsigned f2tf(float x) {
    unsigned r; asm("cvt.rna.tf32.f32 %0, %1;" : "=r"(r) : "f"(x)); return r;
}
__device__ __forceinline__ float ex2(float x) {
    float r; asm("ex2.approx.ftz.f32 %0, %1;" : "=f"(r) : "f"(x)); return r;
}
__device__ __forceinline__ void mma_tf32(float* d, const unsigned* a,
                                         unsigned b0, unsigned b1) {
    asm volatile("mma.sync.aligned.m16n8k8.row.col.f32.tf32.tf32.f32 "
        "{%0,%1,%2,%3},{%4,%5,%6,%7},{%8,%9},{%0,%1,%2,%3};"
        : "+f"(d[0]), "+f"(d[1]), "+f"(d[2]), "+f"(d[3])
        : "r"(a[0]), "r"(a[1]), "r"(a[2]), "r"(a[3]), "r"(b0), "r"(b1));
}
__device__ __forceinline__ float gelu(float x) {
    return 0.5f * x * (1.f + erff(x * 0.70710678118654752f));
}
// C-layout frag (m16n8) -> A-layout frag (m16k8), with scale and tf32 cvt
__device__ __forceinline__ void c2a(const float c[4], int t, int sl0, int sl2,
                                    float scale, unsigned a[4]) {
    float r0 = __shfl_sync(0xffffffffu, c[0], sl0);
    float r1 = __shfl_sync(0xffffffffu, c[1], sl0);
    float v0 = (t & 1) ? r1 : r0;
    r0 = __shfl_sync(0xffffffffu, c[0], sl2);
    r1 = __shfl_sync(0xffffffffu, c[1], sl2);
    float v2 = (t & 1) ? r1 : r0;
    r0 = __shfl_sync(0xffffffffu, c[2], sl0);
    r1 = __shfl_sync(0xffffffffu, c[3], sl0);
    float v1 = (t & 1) ? r1 : r0;
    r0 = __shfl_sync(0xffffffffu, c[2], sl2);
    r1 = __shfl_sync(0xffffffffu, c[3], sl2);
    float v3 = (t & 1) ? r1 : r0;
    a[0] = f2tf(v0 * scale); a[1] = f2tf(v1 * scale);
    a[2] = f2tf(v2 * scale); a[3] = f2tf(v3 * scale);
}
// 64-col GEMM: acc[2][8][4] = A(h frags) @ B(wsm, transposed tf32, stride 68)
__device__ __forceinline__ void gemm64(const unsigned aq[2][8][4],
                                       const unsigned* __restrict__ wsm,
                                       int g, int t, float acc[2][8][4]) {
    #pragma unroll
    for (int m = 0; m < 2; m++)
        #pragma unroll
        for (int nt = 0; nt < 8; nt++)
            #pragma unroll
            for (int i = 0; i < 4; i++) acc[m][nt][i] = 0.f;
    #pragma unroll
    for (int nt = 0; nt < 8; nt++)
        #pragma unroll
        for (int kt = 0; kt < 8; kt++) {
            int jr = (nt*8 + g)*68 + kt*8 + t;
            unsigned b0 = wsm[jr], b1 = wsm[jr + 4];
            mma_tf32(acc[0][nt], aq[0][kt], b0, b1);
            mma_tf32(acc[1][nt], aq[1][kt], b0, b1);
        }
}

// ---------------- kA: gather + LN1 + QKV + attention + o@wo + t -----------
// block = patch (722), 256 thr = 8 warps. smem 190.5 KB:
//   ps  : 256*68 fp32 (patch -> h tf32)      -> reused as K^T [4][16][KSTR]
//   ws  : 3*64*68 tf32 (wq,wk,wv transposed) -> first 64*68 reused for wo^T
//   vsm : V^T [4][16][VSTR]
__global__ __launch_bounds__(256) void kA(const float* __restrict__ x,
                                          const float* __restrict__ g1,
                                          const float* __restrict__ b1,
                                          const float* __restrict__ wq,
                                          const float* __restrict__ wk,
                                          const float* __restrict__ wv,
                                          const float* __restrict__ wo)
{
    extern __shared__ float sm[];
    float*    ps  = sm;                               // 17408 words
    unsigned* ws  = (unsigned*)(sm + 17408);          // 13056 words
    unsigned* vsm = (unsigned*)(sm + 17408 + 13056);  // 17152 words
    unsigned* ksm = (unsigned*)ps;                    // after barrier A

    int tid = threadIdx.x;
    int bn = blockIdx.x;
    int b  = bn / NPAT, n = bn % NPAT;
    int ph = n / NHP,   pw = n % NHP;
    int top  = min(STEP*ph, HH-PP);
    int left = min(STEP*pw, WW-PP);
    const float* xb = x + (size_t)b * CC * HWSZ;

    // ---- weights transposed+tf32 ; patch gather ----
    for (int idx = tid; idx < 3*64*64; idx += 256) {
        int mat = idx >> 12; int rem = idx & 4095;
        int c = rem >> 6, j = rem & 63;
        const float* w = (mat == 0) ? wq : (mat == 1) ? wk : wv;
        ws[mat*64*68 + j*68 + c] = f2tf(w[rem]);
    }
    for (int idx = tid; idx < CC*LL; idx += 256) {
        int c = idx >> 8, l = idx & 255;
        int li = l >> 4, lj = l & 15;
        ps[l*68 + c] = xb[(size_t)c*HWSZ + (size_t)(top+li)*WW + (left+lj)];
    }
    __syncthreads();

    // ---- LN1: residual t -> gmem, h tf32 in place ----
    int lane = tid & 31, warp = tid >> 5;
    {
        float ga = g1[lane], gb = g1[lane+32], ba = b1[lane], bbv = b1[lane+32];
        for (int l = warp; l < LL; l += 8) {
            float v0 = ps[l*68 + lane], v1 = ps[l*68 + lane + 32];
            size_t tb = ((size_t)bn*LL + l) * CC;
            g_t[tb + lane] = v0;  g_t[tb + lane + 32] = v1;
            float s = v0 + v1, ss = v0*v0 + v1*v1;
            #pragma unroll
            for (int o = 16; o; o >>= 1) {
                s  += __shfl_xor_sync(0xffffffffu, s,  o);
                ss += __shfl_xor_sync(0xffffffffu, ss, o);
            }
            float mean = s * (1.f/64.f);
            float var  = ss * (1.f/64.f) - mean*mean;
            float rstd = rsqrtf(var + 1e-5f);
            ps[l*68 + lane]      = __uint_as_float(f2tf((v0 - mean) * rstd * ga + ba));
            ps[l*68 + lane + 32] = __uint_as_float(f2tf((v1 - mean) * rstd * gb + bbv));
        }
    }
    __syncthreads();

    // ---- load h A-frags (warp rows 32w..32w+31) ----
    const unsigned* hs = (const unsigned*)ps;
    int g = lane >> 2, t = lane & 3;
    unsigned aq[2][8][4];
    {
        int r0 = (warp*32 + g)*68;
        #pragma unroll
        for (int m = 0; m < 2; m++)
            #pragma unroll
            for (int kt = 0; kt < 8; kt++) {
                int rb = r0 + m*16*68, c0 = kt*8 + t;
                aq[m][kt][0] = hs[rb + c0];
                aq[m][kt][1] = hs[rb + 544 + c0];
                aq[m][kt][2] = hs[rb + c0 + 4];
                aq[m][kt][3] = hs[rb + 544 + c0 + 4];
            }
    }
    __syncthreads();   // barrier A: everyone has frags; ps region now free

    // ---- K GEMM -> K^T smem ; V GEMM -> V^T smem ; Q GEMM -> regs ----
    {
        float acc[2][8][4];
        gemm64(aq, ws + 64*68, g, t, acc);       // K
        #pragma unroll
        for (int m = 0; m < 2; m++)
            #pragma unroll
            for (int nt = 0; nt < 8; nt++) {
                int tok = warp*32 + m*16 + g;
                int hd  = nt >> 1;
                int d0  = (nt & 1)*8 + 2*t;
                unsigned* kp = ksm + (hd*16 + d0)*KSTR;
                kp[tok]            = f2tf(acc[m][nt][0]);
                kp[KSTR + tok]     = f2tf(acc[m][nt][1]);
                kp[tok + 8]        = f2tf(acc[m][nt][2]);
                kp[KSTR + tok + 8] = f2tf(acc[m][nt][3]);
            }
        gemm64(aq, ws + 2*64*68, g, t, acc);     // V
        #pragma unroll
        for (int m = 0; m < 2; m++)
            #pragma unroll
            for (int nt = 0; nt < 8; nt++) {
                int tok = warp*32 + m*16 + g;
                int hd  = nt >> 1;
                int d0  = (nt & 1)*8 + 2*t;
                unsigned* vp = vsm + (hd*16 + d0)*VSTR;
                vp[tok]            = f2tf(acc[m][nt][0]);
                vp[VSTR + tok]     = f2tf(acc[m][nt][1]);
                vp[tok + 8]        = f2tf(acc[m][nt][2]);
                vp[VSTR + tok + 8] = f2tf(acc[m][nt][3]);
            }
    }
    float qacc[2][8][4];
    gemm64(aq, ws, g, t, qacc);                  // Q (stays in registers)
    __syncthreads();   // barrier B: K/V visible; ws no longer read

    // ---- overwrite wq region with wo^T (consumed after barrier C) ----
    for (int idx = tid; idx < 4096; idx += 256) {
        int c = idx >> 6, j = idx & 63;
        ws[j*68 + c] = f2tf(wo[idx]);
    }

    // ---- flash attention per head; o kept in registers ----
    int sl0 = (lane & ~3) + (t >> 1);
    int sl2 = sl0 + 2;
    float oall[4][2][2][4];
    #pragma unroll
    for (int head = 0; head < NHEAD; head++) {
        unsigned aqh[2][2][4];
        #pragma unroll
        for (int m = 0; m < 2; m++)
            #pragma unroll
            for (int kt = 0; kt < 2; kt++)
                c2a(qacc[m][head*2 + kt], t, sl0, sl2, QSCALE, aqh[m][kt]);

        const unsigned* kh = ksm + head*16*KSTR;
        const unsigned* vh = vsm + head*16*VSTR;
        float oh[2][2][4];
        #pragma unroll
        for (int m = 0; m < 2; m++)
            #pragma unroll
            for (int nd = 0; nd < 2; nd++)
                #pragma unroll
                for (int i = 0; i < 4; i++) oh[m][nd][i] = 0.f;
        float mrow[4] = {-1e30f, -1e30f, -1e30f, -1e30f};
        float drow[4] = {0.f, 0.f, 0.f, 0.f};

        #pragma unroll 1
        for (int jt = 0; jt < 8; jt++) {
            float s[2][4][4];
            #pragma unroll
            for (int m = 0; m < 2; m++)
                #pragma unroll
                for (int nt = 0; nt < 4; nt++)
                    #pragma unroll
                    for (int i = 0; i < 4; i++) s[m][nt][i] = 0.f;
            #pragma unroll
            for (int nt = 0; nt < 4; nt++)
                #pragma unroll
                for (int kt = 0; kt < 2; kt++) {
                    int jr = (kt*8 + t)*KSTR + jt*32 + nt*8 + g;
                    unsigned b0 = kh[jr], b1 = kh[jr + 4*KSTR];
                    mma_tf32(s[0][nt], aqh[0][kt], b0, b1);
                    mma_tf32(s[1][nt], aqh[1][kt], b0, b1);
                }
            #pragma unroll
            for (int m = 0; m < 2; m++) {
                #pragma unroll
                for (int h = 0; h < 2; h++) {
                    int ri = m*2 + h;
                    float mx = fmaxf(s[m][0][h*2], s[m][0][h*2+1]);
                    #pragma unroll
                    for (int nt = 1; nt < 4; nt++)
                        mx = fmaxf(mx, fmaxf(s[m][nt][h*2], s[m][nt][h*2+1]));
                    mx = fmaxf(mx, __shfl_xor_sync(0xffffffffu, mx, 1));
                    mx = fmaxf(mx, __shfl_xor_sync(0xffffffffu, mx, 2));
                    float mn = fmaxf(mrow[ri], mx);
                    float scale = ex2(mrow[ri] - mn);
                    mrow[ri] = mn;
                    drow[ri] *= scale;
                    #pragma unroll
                    for (int nd = 0; nd < 2; nd++) {
                        oh[m][nd][h*2]   *= scale;
                        oh[m][nd][h*2+1] *= scale;
                    }
                    float psum = 0.f;
                    #pragma unroll
                    for (int nt = 0; nt < 4; nt++) {
                        float e0 = ex2(s[m][nt][h*2]   - mn);
                        float e1 = ex2(s[m][nt][h*2+1] - mn);
                        s[m][nt][h*2] = e0; s[m][nt][h*2+1] = e1;
                        psum += e0 + e1;
                    }
                    drow[ri] += psum;
                }
            }
            unsigned p[2][4][4];
            #pragma unroll
            for (int m = 0; m < 2; m++)
                #pragma unroll
                for (int nt = 0; nt < 4; nt++)
                    #pragma unroll
                    for (int i = 0; i < 4; i++) p[m][nt][i] = f2tf(s[m][nt][i]);
            #pragma unroll
            for (int kt = 0; kt < 4; kt++) {
                unsigned ap[2][4];
                #pragma unroll
                for (int m = 0; m < 2; m++) {
                    unsigned r0 = __shfl_sync(0xffffffffu, p[m][kt][0], sl0);
                    unsigned r1 = __shfl_sync(0xffffffffu, p[m][kt][1], sl0);
                    ap[m][0] = (t & 1) ? r1 : r0;
                    r0 = __shfl_sync(0xffffffffu, p[m][kt][0], sl2);
                    r1 = __shfl_sync(0xffffffffu, p[m][kt][1], sl2);
                    ap[m][2] = (t & 1) ? r1 : r0;
                    r0 = __shfl_sync(0xffffffffu, p[m][kt][2], sl0);
                    r1 = __shfl_sync(0xffffffffu, p[m][kt][3], sl0);
                    ap[m][1] = (t & 1) ? r1 : r0;
                    r0 = __shfl_sync(0xffffffffu, p[m][kt][2], sl2);
                    r1 = __shfl_sync(0xffffffffu, p[m][kt][3], sl2);
                    ap[m][3] = (t & 1) ? r1 : r0;
                }
                #pragma unroll
                for (int nd = 0; nd < 2; nd++) {
                    int vr = (nd*8 + g)*VSTR + jt*32 + kt*8 + t;
                    unsigned b0 = vh[vr], b1 = vh[vr + 4];
                    mma_tf32(oh[0][nd], ap[0], b0, b1);
                    mma_tf32(oh[1][nd], ap[1], b0, b1);
                }
            }
        }
        float inv[4];
        #pragma unroll
        for (int ri = 0; ri < 4; ri++) {
            float d = drow[ri];
            d += __shfl_xor_sync(0xffffffffu, d, 1);
            d += __shfl_xor_sync(0xffffffffu, d, 2);
            inv[ri] = 1.f / d;
        }
        #pragma unroll
        for (int m = 0; m < 2; m++)
            #pragma unroll
            for (int nd = 0; nd < 2; nd++) {
                oall[head][m][nd][0] = oh[m][nd][0]*inv[m*2];
                oall[head][m][nd][1] = oh[m][nd][1]*inv[m*2];
                oall[head][m][nd][2] = oh[m][nd][2]*inv[m*2+1];
                oall[head][m][nd][3] = oh[m][nd][3]*inv[m*2+1];
            }
    }
    __syncthreads();   // barrier C: wo^T visible

    // ---- t2 = o @ wo + t ----
    {
        float acc[2][8][4];
        #pragma unroll
        for (int m = 0; m < 2; m++)
            #pragma unroll
            for (int nt = 0; nt < 8; nt++)
                #pragma unroll
                for (int i = 0; i < 4; i++) acc[m][nt][i] = 0.f;
        #pragma unroll
        for (int kt = 0; kt < 8; kt++) {
            int head = kt >> 1, nd = kt & 1;
            unsigned ao[2][4];
            c2a(oall[head][0][nd], t, sl0, sl2, 1.f, ao[0]);
            c2a(oall[head][1][nd], t, sl0, sl2, 1.f, ao[1]);
            #pragma unroll
            for (int nt = 0; nt < 8; nt++) {
                int jr = (nt*8 + g)*68 + kt*8 + t;
                unsigned b0 = ws[jr], b1 = ws[jr + 4];
                mma_tf32(acc[0][nt], ao[0], b0, b1);
                mma_tf32(acc[1][nt], ao[1], b0, b1);
            }
        }
        size_t row0 = (size_t)bn * LL;
        #pragma unroll
        for (int m = 0; m < 2; m++)
            #pragma unroll
            for (int nt = 0; nt < 8; nt++) {
                int row = warp*32 + m*16 + g, col = nt*8 + 2*t;
                size_t a0 = (row0 + row)*CC + col;
                size_t a1 = (row0 + row + 8)*CC + col;
                float2 t0 = *(const float2*)&g_t[a0];
                float2 t1 = *(const float2*)&g_t[a1];
                float2 w0; w0.x = acc[m][nt][0] + t0.x; w0.y = acc[m][nt][1] + t0.y;
                float2 w1; w1.x = acc[m][nt][2] + t1.x; w1.y = acc[m][nt][3] + t1.y;
                *(float2*)&g_o[a0] = w0;
                *(float2*)&g_o[a1] = w1;
            }
    }
}

// ---------------- K3b: deterministic patch_reverse + div ------------------
__global__ __launch_bounds__(256) void k3b()
{
    int e = blockIdx.x * 256 + threadIdx.x;
    int c   = e & 63;
    int pix = e >> 6;
    int b   = pix >> 16;
    int hw  = pix & 65535;
    int r   = hw >> 8, w = hw & 255;
    float acc = 0.f;
    int hc = d_cov_cnt[r], wc = d_cov_cnt[w];
    for (int i = 0; i < hc; i++) {
        int php = d_cov_p[r][i], li = d_cov_o[r][i];
        for (int k = 0; k < wc; k++) {
            int n = php*NHP + d_cov_p[w][k];
            int l = li*PP  + d_cov_o[w][k];
            acc += g_o[(((size_t)(b*NPAT + n))*LL + l)*CC + c];
        }
    }
    g_xs[e] = acc * d_invdiv[r] * d_invdiv[w];
}

// ---------------- K4: LN2 + fc1 + GELU via tf32 mma -----------------------
__global__ __launch_bounds__(256) void k4(const float* __restrict__ g2,
                                          const float* __restrict__ b2,
                                          const float* __restrict__ fc1w,
                                          const float* __restrict__ fc1b)
{
    extern __shared__ float sm4[];
    float*    xsm = sm4;                        // 128*68
    unsigned* fw  = (unsigned*)(sm4 + 128*68);  // 128*68 transposed tf32
    int tid = threadIdx.x;
    size_t pix0 = (size_t)blockIdx.x * 128;
    for (int idx = tid; idx < 2048; idx += 256) {
        int row = idx >> 4, c4 = (idx & 15) * 4;
        *(float4*)&xsm[row*68 + c4] = *(const float4*)&g_xs[(pix0 + row)*CC + c4];
    }
    for (int idx = tid; idx < 8192; idx += 256) {
        int c = idx >> 7, j = idx & 127;
        fw[j*68 + c] = f2tf(fc1w[idx]);
    }
    __syncthreads();

    int lane = tid & 31, warp = tid >> 5;
    float ga = g2[lane], gb = g2[lane+32], ba = b2[lane], bbv = b2[lane+32];
    for (int r = warp; r < 128; r += 8) {
        float v0 = xsm[r*68+lane], v1 = xsm[r*68+lane+32];
        float s = v0+v1, ss = v0*v0+v1*v1;
        #pragma unroll
        for (int o = 16; o; o >>= 1) {
            s  += __shfl_xor_sync(0xffffffffu, s,  o);
            ss += __shfl_xor_sync(0xffffffffu, ss, o);
        }
        float mean = s * (1.f/64.f);
        float var  = ss * (1.f/64.f) - mean*mean;
        float rstd = rsqrtf(var + 1e-5f);
        xsm[r*68+lane]    = __uint_as_float(f2tf((v0 - mean) * rstd * ga + ba));
        xsm[r*68+lane+32] = __uint_as_float(f2tf((v1 - mean) * rstd * gb + bbv));
    }
    __syncthreads();

    const unsigned* hs = (const unsigned*)xsm;
    int g = lane >> 2, t = lane & 3;
    int r0 = (warp*16 + g)*68;
    unsigned aq[8][4];
    #pragma unroll
    for (int kt = 0; kt < 8; kt++) {
        int c0 = kt*8 + t;
        aq[kt][0] = hs[r0 + c0];
        aq[kt][1] = hs[r0 + 544 + c0];
        aq[kt][2] = hs[r0 + c0 + 4];
        aq[kt][3] = hs[r0 + 544 + c0 + 4];
    }
    float acc[16][4];
    #pragma unroll
    for (int nt = 0; nt < 16; nt++) {
        float2 bb = *(const float2*)&fc1b[nt*8 + 2*t];
        acc[nt][0] = bb.x; acc[nt][1] = bb.y; acc[nt][2] = bb.x; acc[nt][3] = bb.y;
    }
    #pragma unroll
    for (int nt = 0; nt < 16; nt++)
        #pragma unroll
        for (int kt = 0; kt < 8; kt++) {
            int jr = (nt*8 + g)*68 + kt*8 + t;
            unsigned b0 = fw[jr], b1 = fw[jr + 4];
            mma_tf32(acc[nt], aq[kt], b0, b1);
        }
    #pragma unroll
    for (int nt = 0; nt < 16; nt++) {
        int row = warp*16 + g, col = nt*8 + 2*t;
        float2 w0; w0.x = gelu(acc[nt][0]); w0.y = gelu(acc[nt][1]);
        float2 w1; w1.x = gelu(acc[nt][2]); w1.y = gelu(acc[nt][3]);
        *(float2*)&g_h1[(pix0 + row)*MLP + col]     = w0;
        *(float2*)&g_h1[(pix0 + row + 8)*MLP + col] = w1;
    }
}

// ---------------- K5: depthwise 5x5 + GELU + residual ---------------------
__global__ __launch_bounds__(128) void k5(const float* __restrict__ dww,
                                          const float* __restrict__ dwb)
{
    extern __shared__ float si[];            // 100*128
    int ch = threadIdx.x;
    int bx = blockIdx.x;
    int cw0 = (bx & 15) * 16;
    int r   = (bx >> 4) & 255;
    int b   = bx >> 12;
    float wreg[25];
    #pragma unroll
    for (int i = 0; i < 25; i++) wreg[i] = dww[ch*25 + i];
    float bias = dwb[ch];
    const float* hp = g_h1 + (size_t)b * HWSZ * MLP;

    for (int slot = 0; slot < 100; slot++) {
        int ry = slot / 20, cx = slot % 20;
        int rr = r + ry - 2, cc = cw0 + cx - 2;
        float v = 0.f;
        if (rr >= 0 && rr < 256 && cc >= 0 && cc < 256)
            v = hp[((size_t)rr*256 + cc)*MLP + ch];
        si[slot*MLP + ch] = v;
    }
    __syncthreads();

    float* op = g_h2 + ((size_t)b*HWSZ + (size_t)r*256 + cw0) * MLP;
    #pragma unroll 1
    for (int half = 0; half < 2; half++) {
        int k0 = half * 8;
        float val[5][12];
        #pragma unroll
        for (int dy = 0; dy < 5; dy++)
            #pragma unroll
            for (int xx = 0; xx < 12; xx++)
                val[dy][xx] = si[(dy*20 + k0 + xx)*MLP + ch];
        #pragma unroll
        for (int k = 0; k < 8; k++) {
            float acc = bias;
            #pragma unroll
            for (int dy = 0; dy < 5; dy++)
                #pragma unroll
                for (int dx = 0; dx < 5; dx++)
                    acc += val[dy][k + dx] * wreg[dy*5 + dx];
            float center = val[2][k + 2];
            op[(size_t)(k0 + k)*MLP + ch] = center + gelu(acc);
        }
    }
}

// ---------------- K6: fc2 + bias + residual + transpose via tf32 mma ------
__global__ __launch_bounds__(256) void k6(const float* __restrict__ fc2w,
                                          const float* __restrict__ fc2b,
                                          float* __restrict__ out)
{
    extern __shared__ unsigned sm6[];
    unsigned* hs = sm6;              // 128*132 tf32
    unsigned* fw = sm6 + 128*132;    // 64*132 transposed tf32 (reused as out tile)
    float*  tile = (float*)fw;
    int tid = threadIdx.x;
    size_t pix0 = (size_t)blockIdx.x * 128;
    int b   = (int)(pix0 >> 16);
    int hw0 = (int)(pix0 & 65535);
    for (int idx = tid; idx < 4096; idx += 256) {
        int row = idx >> 5, c4 = (idx & 31) * 4;
        float4 v = *(const float4*)&g_h2[(pix0 + row)*MLP + c4];
        uint4 u = { f2tf(v.x), f2tf(v.y), f2tf(v.z), f2tf(v.w) };
        *(uint4*)&hs[row*132 + c4] = u;
    }
    for (int idx = tid; idx < 8192; idx += 256) {
        int c = idx >> 6, j = idx & 63;
        fw[j*132 + c] = f2tf(fc2w[idx]);
    }
    __syncthreads();

    int lane = tid & 31, w = tid >> 5, g = lane >> 2, t = lane & 3;
    int r0 = (w*16 + g)*132;
    unsigned aq[16][4];
    #pragma unroll
    for (int kt = 0; kt < 16; kt++) {
        int c0 = kt*8 + t;
        aq[kt][0] = hs[r0 + c0];
        aq[kt][1] = hs[r0 + 8*132 + c0];
        aq[kt][2] = hs[r0 + c0 + 4];
        aq[kt][3] = hs[r0 + 8*132 + c0 + 4];
    }
    float acc[8][4];
    #pragma unroll
    for (int nt = 0; nt < 8; nt++)
        #pragma unroll
        for (int i = 0; i < 4; i++) acc[nt][i] = 0.f;
    #pragma unroll
    for (int nt = 0; nt < 8; nt++)
        #pragma unroll
        for (int kt = 0; kt < 16; kt++) {
            int jr = (nt*8 + g)*132 + kt*8 + t;
            unsigned b0 = fw[jr], b1 = fw[jr + 4];
            mma_tf32(acc[nt], aq[kt], b0, b1);
        }
    __syncthreads();
    #pragma unroll
    for (int nt = 0; nt < 8; nt++) {
        int row = w*16 + g, col = nt*8 + 2*t;
        float2 bb = *(const float2*)&fc2b[col];
        float2 x0 = *(const float2*)&g_xs[(pix0 + row)*CC + col];
        float2 x1 = *(const float2*)&g_xs[(pix0 + row + 8)*CC + col];
        tile[(col  )*132 + row]     = acc[nt][0] + bb.x + x0.x;
        tile[(col+1)*132 + row]     = acc[nt][1] + bb.y + x0.y;
        tile[(col  )*132 + row + 8] = acc[nt][2] + bb.x + x1.x;
        tile[(col+1)*132 + row + 8] = acc[nt][3] + bb.y + x1.y;
    }
    __syncthreads();
    for (int idx = tid; idx < 2048; idx += 256) {
        int c = idx >> 5, p4 = (idx & 31) * 4;
        *(float4*)&out[((size_t)(b*CC + c))*HWSZ + hw0 + p4] = *(const float4*)&tile[c*132 + p4];
    }
}

// ---------------- launch ---------------------------------------------------
#define KA_SMEM ((17408 + 13056 + 17152) * 4)

extern "C" void kernel_launch(void* const* d_in, const int* in_sizes, int n_in,
                              void* d_out, int out_size)
{
    const float* x    = (const float*)d_in[0];
    const float* ln1g = (const float*)d_in[1];
    const float* ln1b = (const float*)d_in[2];
    const float* wq   = (const float*)d_in[3];
    const float* wk   = (const float*)d_in[4];
    const float* wv   = (const float*)d_in[5];
    const float* wo   = (const float*)d_in[6];
    const float* ln2g = (const float*)d_in[7];
    const float* ln2b = (const float*)d_in[8];
    const float* fc1w = (const float*)d_in[9];
    const float* fc1b = (const float*)d_in[10];
    const float* dww  = (const float*)d_in[11];
    const float* dwb  = (const float*)d_in[12];
    const float* fc2w = (const float*)d_in[13];
    const float* fc2b = (const float*)d_in[14];
    float* out = (float*)d_out;

    static int s_attr = 0;
    if (!s_attr) {
        cudaFuncSetAttribute(kA, cudaFuncAttributeMaxDynamicSharedMemorySize, KA_SMEM);
        cudaFuncSetAttribute(k4, cudaFuncAttributeMaxDynamicSharedMemorySize, (128*68 + 128*68)*4);
        cudaFuncSetAttribute(k5, cudaFuncAttributeMaxDynamicSharedMemorySize, 100*128*4);
        cudaFuncSetAttribute(k6, cudaFuncAttributeMaxDynamicSharedMemorySize, (128*132 + 64*132)*4);
        s_attr = 1;
    }

    k_init<<<1, 256>>>();
    kA<<<BN, 256, KA_SMEM>>>(x, ln1g, ln1b, wq, wk, wv, wo);
    k3b<<<(BB*HWSZ*CC)/256, 256>>>();
    k4<<<(BB*HWSZ)/128, 256, (128*68 + 128*68)*4>>>(ln2g, ln2b, fc1w, fc1b);
    k5<<<BB*256*16, 128, 100*128*4>>>(dww, dwb);
    k6<<<(BB*HWSZ)/128, 256, (128*132 + 64*132)*4>>>(fc2w, fc2b, out);
}

// round 7
// speedup vs baseline: 3.0677x; 1.0724x over previous
#include <cuda_runtime.h>
#include <cuda_bf16.h>
#include <cstddef>

// ---------------- problem geometry (fixed by setup_inputs) ----------------
#define BB    2
#define CC    64
#define HH    256
#define WW    256
#define PP    16
#define STEP  14
#define NHP   19
#define NPAT  361
#define BN    722
#define LL    256
#define NHEAD 4
#define DHEAD 16
#define MLP   128
#define HWSZ  65536

#define QSCALE 0.36067376022224085f   // 0.25 * log2(e)

#define KSTR 264
#define VSTR 268

// ---------------- scratch ----------
__device__ float g_t [(size_t)BN*LL*CC];
__device__ float g_o [(size_t)BN*LL*CC];
__device__ float g_xs[(size_t)BB*HWSZ*CC];
__device__ float g_h1[(size_t)BB*HWSZ*MLP];
__device__ float g_h2[(size_t)BB*HWSZ*MLP];

__device__ int   d_cov_cnt[256];
__device__ int   d_cov_p[256][2];
__device__ int   d_cov_o[256][2];
__device__ float d_invdiv[256];

__global__ void k_init()
{
    int r = threadIdx.x;
    if (r < 256) {
        int cnt = 0;
        for (int ph = 0; ph < NHP; ph++) {
            int top = min(STEP*ph, HH-PP);
            if (r >= top && r < top + PP && cnt < 2) {
                d_cov_p[r][cnt] = ph;
                d_cov_o[r][cnt] = r - top;
                cnt++;
            }
        }
        d_cov_cnt[r] = cnt;
    }
    if (threadIdx.x == 0) {
        float div[256];
        for (int i = 0; i < 256; i++) div[i] = 1.f;
        for (int i = STEP; i < HH + STEP - PP; i += STEP) {
            int top = (i + PP > HH) ? (HH - PP) : i;
            for (int r2 = top; r2 < i + PP - STEP; ++r2) div[r2] *= 2.f;
        }
        for (int i = 0; i < 256; i++) d_invdiv[i] = 1.f / div[i];
    }
}

// ---------------- mma helpers ---------------------------------------------
__device__ __forceinline__ unsigned f2tf(float x) {
    unsigned r; asm("cvt.rna.tf32.f32 %0, %1;" : "=r"(r) : "f"(x)); return r;
}
__device__ __forceinline__ float ex2(float x) {
    float r; asm("ex2.approx.ftz.f32 %0, %1;" : "=f"(r) : "f"(x)); return r;
}
__device__ __forceinline__ void mma_tf32(float* d, const unsigned* a,
                                         unsigned b0, unsigned b1) {
    asm volatile("mma.sync.aligned.m16n8k8.row.col.f32.tf32.tf32.f32 "
        "{%0,%1,%2,%3},{%4,%5,%6,%7},{%8,%9},{%0,%1,%2,%3};"
        : "+f"(d[0]), "+f"(d[1]), "+f"(d[2]), "+f"(d[3])
        : "r"(a[0]), "r"(a[1]), "r"(a[2]), "r"(a[3]), "r"(b0), "r"(b1));
}
__device__ __forceinline__ float gelu(float x) {
    return 0.5f * x * (1.f + erff(x * 0.70710678118654752f));
}
__device__ __forceinline__ void c2a(const float c[4], int t, int sl0, int sl2,
                                    float scale, unsigned a[4]) {
    float r0 = __shfl_sync(0xffffffffu, c[0], sl0);
    float r1 = __shfl_sync(0xffffffffu, c[1], sl0);
    float v0 = (t & 1) ? r1 : r0;
    r0 = __shfl_sync(0xffffffffu, c[0], sl2);
    r1 = __shfl_sync(0xffffffffu, c[1], sl2);
    float v2 = (t & 1) ? r1 : r0;
    r0 = __shfl_sync(0xffffffffu, c[2], sl0);
    r1 = __shfl_sync(0xffffffffu, c[3], sl0);
    float v1 = (t & 1) ? r1 : r0;
    r0 = __shfl_sync(0xffffffffu, c[2], sl2);
    r1 = __shfl_sync(0xffffffffu, c[3], sl2);
    float v3 = (t & 1) ? r1 : r0;
    a[0] = f2tf(v0 * scale); a[1] = f2tf(v1 * scale);
    a[2] = f2tf(v2 * scale); a[3] = f2tf(v3 * scale);
}
// 16-row x 64-col GEMM for one warp: acc[8][4] += A(frags) @ B(wsm stride 68)
__device__ __forceinline__ void gemm64(const unsigned aq[8][4],
                                       const unsigned* __restrict__ wsm,
                                       int g, int t, float acc[8][4]) {
    #pragma unroll
    for (int nt = 0; nt < 8; nt++)
        #pragma unroll
        for (int i = 0; i < 4; i++) acc[nt][i] = 0.f;
    #pragma unroll
    for (int nt = 0; nt < 8; nt++)
        #pragma unroll
        for (int kt = 0; kt < 8; kt++) {
            int jr = (nt*8 + g)*68 + kt*8 + t;
            mma_tf32(acc[nt], aq[kt], wsm[jr], wsm[jr + 4]);
        }
}

// ---------------- kA: gather + LN1 + QKV + attention + o@wo + t -----------
// block = patch (722), 512 thr = 16 warps (warp = 16 rows). smem 190.5 KB.
__global__ __launch_bounds__(512) void kA(const float* __restrict__ x,
                                          const float* __restrict__ g1,
                                          const float* __restrict__ b1,
                                          const float* __restrict__ wq,
                                          const float* __restrict__ wk,
                                          const float* __restrict__ wv,
                                          const float* __restrict__ wo)
{
    extern __shared__ float sm[];
    float*    ps  = sm;                               // 17408 words
    unsigned* ws  = (unsigned*)(sm + 17408);          // 13056 words
    unsigned* vsm = (unsigned*)(sm + 17408 + 13056);  // 17152 words
    unsigned* ksm = (unsigned*)ps;

    int tid = threadIdx.x;
    int bn = blockIdx.x;
    int b  = bn / NPAT, n = bn % NPAT;
    int ph = n / NHP,   pw = n % NHP;
    int top  = min(STEP*ph, HH-PP);
    int left = min(STEP*pw, WW-PP);
    const float* xb = x + (size_t)b * CC * HWSZ;

    for (int idx = tid; idx < 3*64*64; idx += 512) {
        int mat = idx >> 12; int rem = idx & 4095;
        int c = rem >> 6, j = rem & 63;
        const float* w = (mat == 0) ? wq : (mat == 1) ? wk : wv;
        ws[mat*64*68 + j*68 + c] = f2tf(w[rem]);
    }
    for (int idx = tid; idx < CC*LL; idx += 512) {
        int c = idx >> 8, l = idx & 255;
        int li = l >> 4, lj = l & 15;
        ps[l*68 + c] = xb[(size_t)c*HWSZ + (size_t)(top+li)*WW + (left+lj)];
    }
    __syncthreads();

    int lane = tid & 31, warp = tid >> 5;    // 16 warps
    {
        float ga = g1[lane], gb = g1[lane+32], ba = b1[lane], bbv = b1[lane+32];
        for (int l = warp; l < LL; l += 16) {
            float v0 = ps[l*68 + lane], v1 = ps[l*68 + lane + 32];
            size_t tb = ((size_t)bn*LL + l) * CC;
            g_t[tb + lane] = v0;  g_t[tb + lane + 32] = v1;
            float s = v0 + v1, ss = v0*v0 + v1*v1;
            #pragma unroll
            for (int o = 16; o; o >>= 1) {
                s  += __shfl_xor_sync(0xffffffffu, s,  o);
                ss += __shfl_xor_sync(0xffffffffu, ss, o);
            }
            float mean = s * (1.f/64.f);
            float var  = ss * (1.f/64.f) - mean*mean;
            float rstd = rsqrtf(var + 1e-5f);
            ps[l*68 + lane]      = __uint_as_float(f2tf((v0 - mean) * rstd * ga + ba));
            ps[l*68 + lane + 32] = __uint_as_float(f2tf((v1 - mean) * rstd * gb + bbv));
        }
    }
    __syncthreads();

    const unsigned* hs = (const unsigned*)ps;
    int g = lane >> 2, t = lane & 3;
    unsigned aq[8][4];
    {
        int r0 = (warp*16 + g)*68;
        #pragma unroll
        for (int kt = 0; kt < 8; kt++) {
            int c0 = kt*8 + t;
            aq[kt][0] = hs[r0 + c0];
            aq[kt][1] = hs[r0 + 544 + c0];
            aq[kt][2] = hs[r0 + c0 + 4];
            aq[kt][3] = hs[r0 + 544 + c0 + 4];
        }
    }
    __syncthreads();   // barrier A: ps free (becomes K^T)

    {
        float acc[8][4];
        gemm64(aq, ws + 64*68, g, t, acc);       // K
        #pragma unroll
        for (int nt = 0; nt < 8; nt++) {
            int tok = warp*16 + g;
            int hd  = nt >> 1;
            int d0  = (nt & 1)*8 + 2*t;
            unsigned* kp = ksm + (hd*16 + d0)*KSTR;
            kp[tok]            = f2tf(acc[nt][0]);
            kp[KSTR + tok]     = f2tf(acc[nt][1]);
            kp[tok + 8]        = f2tf(acc[nt][2]);
            kp[KSTR + tok + 8] = f2tf(acc[nt][3]);
        }
        gemm64(aq, ws + 2*64*68, g, t, acc);     // V
        #pragma unroll
        for (int nt = 0; nt < 8; nt++) {
            int tok = warp*16 + g;
            int hd  = nt >> 1;
            int d0  = (nt & 1)*8 + 2*t;
            unsigned* vp = vsm + (hd*16 + d0)*VSTR;
            vp[tok]            = f2tf(acc[nt][0]);
            vp[VSTR + tok]     = f2tf(acc[nt][1]);
            vp[tok + 8]        = f2tf(acc[nt][2]);
            vp[VSTR + tok + 8] = f2tf(acc[nt][3]);
        }
    }
    float qacc[8][4];
    gemm64(aq, ws, g, t, qacc);                  // Q (registers)
    __syncthreads();   // barrier B: K/V visible; ws writable

    for (int idx = tid; idx < 4096; idx += 512) {
        int c = idx >> 6, j = idx & 63;
        ws[j*68 + c] = f2tf(wo[idx]);
    }

    int sl0 = (lane & ~3) + (t >> 1);
    int sl2 = sl0 + 2;
    float oall[4][2][4];
    #pragma unroll
    for (int head = 0; head < NHEAD; head++) {
        unsigned aqh[2][4];
        #pragma unroll
        for (int kt = 0; kt < 2; kt++)
            c2a(qacc[head*2 + kt], t, sl0, sl2, QSCALE, aqh[kt]);

        const unsigned* kh = ksm + head*16*KSTR;
        const unsigned* vh = vsm + head*16*VSTR;
        float oh[2][4];
        #pragma unroll
        for (int nd = 0; nd < 2; nd++)
            #pragma unroll
            for (int i = 0; i < 4; i++) oh[nd][i] = 0.f;
        float mrow[2] = {-1e30f, -1e30f};
        float drow[2] = {0.f, 0.f};

        #pragma unroll 1
        for (int jt = 0; jt < 8; jt++) {
            float s[4][4];
            #pragma unroll
            for (int nt = 0; nt < 4; nt++)
                #pragma unroll
                for (int i = 0; i < 4; i++) s[nt][i] = 0.f;
            #pragma unroll
            for (int nt = 0; nt < 4; nt++)
                #pragma unroll
                for (int kt = 0; kt < 2; kt++) {
                    int jr = (kt*8 + t)*KSTR + jt*32 + nt*8 + g;
                    mma_tf32(s[nt], aqh[kt], kh[jr], kh[jr + 4*KSTR]);
                }
            #pragma unroll
            for (int h = 0; h < 2; h++) {
                float mx = fmaxf(s[0][h*2], s[0][h*2+1]);
                #pragma unroll
                for (int nt = 1; nt < 4; nt++)
                    mx = fmaxf(mx, fmaxf(s[nt][h*2], s[nt][h*2+1]));
                mx = fmaxf(mx, __shfl_xor_sync(0xffffffffu, mx, 1));
                mx = fmaxf(mx, __shfl_xor_sync(0xffffffffu, mx, 2));
                float mn = fmaxf(mrow[h], mx);
                float scale = ex2(mrow[h] - mn);
                mrow[h] = mn;
                drow[h] *= scale;
                #pragma unroll
                for (int nd = 0; nd < 2; nd++) {
                    oh[nd][h*2]   *= scale;
                    oh[nd][h*2+1] *= scale;
                }
                float psum = 0.f;
                #pragma unroll
                for (int nt = 0; nt < 4; nt++) {
                    float e0 = ex2(s[nt][h*2]   - mn);
                    float e1 = ex2(s[nt][h*2+1] - mn);
                    s[nt][h*2] = e0; s[nt][h*2+1] = e1;
                    psum += e0 + e1;
                }
                drow[h] += psum;
            }
            unsigned p[4][4];
            #pragma unroll
            for (int nt = 0; nt < 4; nt++)
                #pragma unroll
                for (int i = 0; i < 4; i++) p[nt][i] = f2tf(s[nt][i]);
            #pragma unroll
            for (int kt = 0; kt < 4; kt++) {
                unsigned ap[4];
                {
                    unsigned r0 = __shfl_sync(0xffffffffu, p[kt][0], sl0);
                    unsigned r1 = __shfl_sync(0xffffffffu, p[kt][1], sl0);
                    ap[0] = (t & 1) ? r1 : r0;
                    r0 = __shfl_sync(0xffffffffu, p[kt][0], sl2);
                    r1 = __shfl_sync(0xffffffffu, p[kt][1], sl2);
                    ap[2] = (t & 1) ? r1 : r0;
                    r0 = __shfl_sync(0xffffffffu, p[kt][2], sl0);
                    r1 = __shfl_sync(0xffffffffu, p[kt][3], sl0);
                    ap[1] = (t & 1) ? r1 : r0;
                    r0 = __shfl_sync(0xffffffffu, p[kt][2], sl2);
                    r1 = __shfl_sync(0xffffffffu, p[kt][3], sl2);
                    ap[3] = (t & 1) ? r1 : r0;
                }
                #pragma unroll
                for (int nd = 0; nd < 2; nd++) {
                    int vr = (nd*8 + g)*VSTR + jt*32 + kt*8 + t;
                    mma_tf32(oh[nd], ap, vh[vr], vh[vr + 4]);
                }
            }
        }
        float inv[2];
        #pragma unroll
        for (int h = 0; h < 2; h++) {
            float d = drow[h];
            d += __shfl_xor_sync(0xffffffffu, d, 1);
            d += __shfl_xor_sync(0xffffffffu, d, 2);
            inv[h] = 1.f / d;
        }
        #pragma unroll
        for (int nd = 0; nd < 2; nd++) {
            oall[head][nd][0] = oh[nd][0]*inv[0];
            oall[head][nd][1] = oh[nd][1]*inv[0];
            oall[head][nd][2] = oh[nd][2]*inv[1];
            oall[head][nd][3] = oh[nd][3]*inv[1];
        }
    }
    __syncthreads();   // barrier C: wo^T visible

    {
        float acc[8][4];
        #pragma unroll
        for (int nt = 0; nt < 8; nt++)
            #pragma unroll
            for (int i = 0; i < 4; i++) acc[nt][i] = 0.f;
        #pragma unroll
        for (int kt = 0; kt < 8; kt++) {
            int head = kt >> 1, nd = kt & 1;
            unsigned ao[4];
            c2a(oall[head][nd], t, sl0, sl2, 1.f, ao);
            #pragma unroll
            for (int nt = 0; nt < 8; nt++) {
                int jr = (nt*8 + g)*68 + kt*8 + t;
                mma_tf32(acc[nt], ao, ws[jr], ws[jr + 4]);
            }
        }
        size_t row0 = (size_t)bn * LL;
        #pragma unroll
        for (int nt = 0; nt < 8; nt++) {
            int row = warp*16 + g, col = nt*8 + 2*t;
            size_t a0 = (row0 + row)*CC + col;
            size_t a1 = (row0 + row + 8)*CC + col;
            float2 t0 = *(const float2*)&g_t[a0];
            float2 t1 = *(const float2*)&g_t[a1];
            float2 w0; w0.x = acc[nt][0] + t0.x; w0.y = acc[nt][1] + t0.y;
            float2 w1; w1.x = acc[nt][2] + t1.x; w1.y = acc[nt][3] + t1.y;
            *(float2*)&g_o[a0] = w0;
            *(float2*)&g_o[a1] = w1;
        }
    }
}

// ---------------- K3b: deterministic patch_reverse + div ------------------
__global__ __launch_bounds__(256) void k3b()
{
    int e = blockIdx.x * 256 + threadIdx.x;
    int c   = e & 63;
    int pix = e >> 6;
    int b   = pix >> 16;
    int hw  = pix & 65535;
    int r   = hw >> 8, w = hw & 255;
    float acc = 0.f;
    int hc = d_cov_cnt[r], wc = d_cov_cnt[w];
    for (int i = 0; i < hc; i++) {
        int php = d_cov_p[r][i], li = d_cov_o[r][i];
        for (int k = 0; k < wc; k++) {
            int n = php*NHP + d_cov_p[w][k];
            int l = li*PP  + d_cov_o[w][k];
            acc += g_o[(((size_t)(b*NPAT + n))*LL + l)*CC + c];
        }
    }
    g_xs[e] = acc * d_invdiv[r] * d_invdiv[w];
}

// ---------------- K4: LN2 + fc1 + GELU via tf32 mma (512 thr, 256 rows) ---
__global__ __launch_bounds__(512) void k4(const float* __restrict__ g2,
                                          const float* __restrict__ b2,
                                          const float* __restrict__ fc1w,
                                          const float* __restrict__ fc1b)
{
    extern __shared__ float sm4[];
    float*    xsm = sm4;                        // 256*68
    unsigned* fw  = (unsigned*)(sm4 + 256*68);  // 128*68 transposed tf32
    int tid = threadIdx.x;
    size_t pix0 = (size_t)blockIdx.x * 256;
    for (int idx = tid; idx < 4096; idx += 512) {
        int row = idx >> 4, c4 = (idx & 15) * 4;
        *(float4*)&xsm[row*68 + c4] = *(const float4*)&g_xs[(pix0 + row)*CC + c4];
    }
    for (int idx = tid; idx < 8192; idx += 512) {
        int c = idx >> 7, j = idx & 127;
        fw[j*68 + c] = f2tf(fc1w[idx]);
    }
    __syncthreads();

    int lane = tid & 31, warp = tid >> 5;
    float ga = g2[lane], gb = g2[lane+32], ba = b2[lane], bbv = b2[lane+32];
    for (int r = warp; r < 256; r += 16) {
        float v0 = xsm[r*68+lane], v1 = xsm[r*68+lane+32];
        float s = v0+v1, ss = v0*v0+v1*v1;
        #pragma unroll
        for (int o = 16; o; o >>= 1) {
            s  += __shfl_xor_sync(0xffffffffu, s,  o);
            ss += __shfl_xor_sync(0xffffffffu, ss, o);
        }
        float mean = s * (1.f/64.f);
        float var  = ss * (1.f/64.f) - mean*mean;
        float rstd = rsqrtf(var + 1e-5f);
        xsm[r*68+lane]    = __uint_as_float(f2tf((v0 - mean) * rstd * ga + ba));
        xsm[r*68+lane+32] = __uint_as_float(f2tf((v1 - mean) * rstd * gb + bbv));
    }
    __syncthreads();

    const unsigned* hs = (const unsigned*)xsm;
    int g = lane >> 2, t = lane & 3;
    int r0 = (warp*16 + g)*68;
    unsigned aq[8][4];
    #pragma unroll
    for (int kt = 0; kt < 8; kt++) {
        int c0 = kt*8 + t;
        aq[kt][0] = hs[r0 + c0];
        aq[kt][1] = hs[r0 + 544 + c0];
        aq[kt][2] = hs[r0 + c0 + 4];
        aq[kt][3] = hs[r0 + 544 + c0 + 4];
    }
    float acc[16][4];
    #pragma unroll
    for (int nt = 0; nt < 16; nt++) {
        float2 bb = *(const float2*)&fc1b[nt*8 + 2*t];
        acc[nt][0] = bb.x; acc[nt][1] = bb.y; acc[nt][2] = bb.x; acc[nt][3] = bb.y;
    }
    #pragma unroll
    for (int nt = 0; nt < 16; nt++)
        #pragma unroll
        for (int kt = 0; kt < 8; kt++) {
            int jr = (nt*8 + g)*68 + kt*8 + t;
            mma_tf32(acc[nt], aq[kt], fw[jr], fw[jr + 4]);
        }
    #pragma unroll
    for (int nt = 0; nt < 16; nt++) {
        int row = warp*16 + g, col = nt*8 + 2*t;
        float2 w0; w0.x = gelu(acc[nt][0]); w0.y = gelu(acc[nt][1]);
        float2 w1; w1.x = gelu(acc[nt][2]); w1.y = gelu(acc[nt][3]);
        *(float2*)&g_h1[(pix0 + row)*MLP + col]     = w0;
        *(float2*)&g_h1[(pix0 + row + 8)*MLP + col] = w1;
    }
}

// ---------------- K5: depthwise 5x5 + GELU + residual ---------------------
__global__ __launch_bounds__(128) void k5(const float* __restrict__ dww,
                                          const float* __restrict__ dwb)
{
    extern __shared__ float si[];            // 100*128
    int ch = threadIdx.x;
    int bx = blockIdx.x;
    int cw0 = (bx & 15) * 16;
    int r   = (bx >> 4) & 255;
    int b   = bx >> 12;
    float wreg[25];
    #pragma unroll
    for (int i = 0; i < 25; i++) wreg[i] = dww[ch*25 + i];
    float bias = dwb[ch];
    const float* hp = g_h1 + (size_t)b * HWSZ * MLP;

    for (int slot = 0; slot < 100; slot++) {
        int ry = slot / 20, cx = slot % 20;
        int rr = r + ry - 2, cc = cw0 + cx - 2;
        float v = 0.f;
        if (rr >= 0 && rr < 256 && cc >= 0 && cc < 256)
            v = hp[((size_t)rr*256 + cc)*MLP + ch];
        si[slot*MLP + ch] = v;
    }
    __syncthreads();

    float* op = g_h2 + ((size_t)b*HWSZ + (size_t)r*256 + cw0) * MLP;
    #pragma unroll 1
    for (int half = 0; half < 2; half++) {
        int k0 = half * 8;
        float val[5][12];
        #pragma unroll
        for (int dy = 0; dy < 5; dy++)
            #pragma unroll
            for (int xx = 0; xx < 12; xx++)
                val[dy][xx] = si[(dy*20 + k0 + xx)*MLP + ch];
        #pragma unroll
        for (int k = 0; k < 8; k++) {
            float acc = bias;
            #pragma unroll
            for (int dy = 0; dy < 5; dy++)
                #pragma unroll
                for (int dx = 0; dx < 5; dx++)
                    acc += val[dy][k + dx] * wreg[dy*5 + dx];
            float center = val[2][k + 2];
            op[(size_t)(k0 + k)*MLP + ch] = center + gelu(acc);
        }
    }
}

// ---------------- K6: fc2 + bias + residual + transpose via tf32 mma ------
__global__ __launch_bounds__(256) void k6(const float* __restrict__ fc2w,
                                          const float* __restrict__ fc2b,
                                          float* __restrict__ out)
{
    extern __shared__ unsigned sm6[];
    unsigned* hs = sm6;              // 128*132 tf32
    unsigned* fw = sm6 + 128*132;    // 64*132 transposed tf32 (reused as out tile)
    float*  tile = (float*)fw;
    int tid = threadIdx.x;
    size_t pix0 = (size_t)blockIdx.x * 128;
    int b   = (int)(pix0 >> 16);
    int hw0 = (int)(pix0 & 65535);
    for (int idx = tid; idx < 4096; idx += 256) {
        int row = idx >> 5, c4 = (idx & 31) * 4;
        float4 v = *(const float4*)&g_h2[(pix0 + row)*MLP + c4];
        uint4 u = { f2tf(v.x), f2tf(v.y), f2tf(v.z), f2tf(v.w) };
        *(uint4*)&hs[row*132 + c4] = u;
    }
    for (int idx = tid; idx < 8192; idx += 256) {
        int c = idx >> 6, j = idx & 63;
        fw[j*132 + c] = f2tf(fc2w[idx]);
    }
    __syncthreads();

    int lane = tid & 31, w = tid >> 5, g = lane >> 2, t = lane & 3;
    int r0 = (w*16 + g)*132;
    unsigned aq[16][4];
    #pragma unroll
    for (int kt = 0; kt < 16; kt++) {
        int c0 = kt*8 + t;
        aq[kt][0] = hs[r0 + c0];
        aq[kt][1] = hs[r0 + 8*132 + c0];
        aq[kt][2] = hs[r0 + c0 + 4];
        aq[kt][3] = hs[r0 + 8*132 + c0 + 4];
    }
    float acc[8][4];
    #pragma unroll
    for (int nt = 0; nt < 8; nt++)
        #pragma unroll
        for (int i = 0; i < 4; i++) acc[nt][i] = 0.f;
    #pragma unroll
    for (int nt = 0; nt < 8; nt++)
        #pragma unroll
        for (int kt = 0; kt < 16; kt++) {
            int jr = (nt*8 + g)*132 + kt*8 + t;
            mma_tf32(acc[nt], aq[kt], fw[jr], fw[jr + 4]);
        }
    __syncthreads();
    #pragma unroll
    for (int nt = 0; nt < 8; nt++) {
        int row = w*16 + g, col = nt*8 + 2*t;
        float2 bb = *(const float2*)&fc2b[col];
        float2 x0 = *(const float2*)&g_xs[(pix0 + row)*CC + col];
        float2 x1 = *(const float2*)&g_xs[(pix0 + row + 8)*CC + col];
        tile[(col  )*132 + row]     = acc[nt][0] + bb.x + x0.x;
        tile[(col+1)*132 + row]     = acc[nt][1] + bb.y + x0.y;
        tile[(col  )*132 + row + 8] = acc[nt][2] + bb.x + x1.x;
        tile[(col+1)*132 + row + 8] = acc[nt][3] + bb.y + x1.y;
    }
    __syncthreads();
    for (int idx = tid; idx < 2048; idx += 256) {
        int c = idx >> 5, p4 = (idx & 31) * 4;
        *(float4*)&out[((size_t)(b*CC + c))*HWSZ + hw0 + p4] = *(const float4*)&tile[c*132 + p4];
    }
}

// ---------------- launch ---------------------------------------------------
#define KA_SMEM ((17408 + 13056 + 17152) * 4)
#define K4_SMEM ((256*68 + 128*68) * 4)

extern "C" void kernel_launch(void* const* d_in, const int* in_sizes, int n_in,
                              void* d_out, int out_size)
{
    const float* x    = (const float*)d_in[0];
    const float* ln1g = (const float*)d_in[1];
    const float* ln1b = (const float*)d_in[2];
    const float* wq   = (const float*)d_in[3];
    const float* wk   = (const float*)d_in[4];
    const float* wv   = (const float*)d_in[5];
    const float* wo   = (const float*)d_in[6];
    const float* ln2g = (const float*)d_in[7];
    const float* ln2b = (const float*)d_in[8];
    const float* fc1w = (const float*)d_in[9];
    const float* fc1b = (const float*)d_in[10];
    const float* dww  = (const float*)d_in[11];
    const float* dwb  = (const float*)d_in[12];
    const float* fc2w = (const float*)d_in[13];
    const float* fc2b = (const float*)d_in[14];
    float* out = (float*)d_out;

    static int s_attr = 0;
    if (!s_attr) {
        cudaFuncSetAttribute(kA, cudaFuncAttributeMaxDynamicSharedMemorySize, KA_SMEM);
        cudaFuncSetAttribute(k4, cudaFuncAttributeMaxDynamicSharedMemorySize, K4_SMEM);
        cudaFuncSetAttribute(k5, cudaFuncAttributeMaxDynamicSharedMemorySize, 100*128*4);
        cudaFuncSetAttribute(k6, cudaFuncAttributeMaxDynamicSharedMemorySize, (128*132 + 64*132)*4);
        s_attr = 1;
    }

    k_init<<<1, 256>>>();
    kA<<<BN, 512, KA_SMEM>>>(x, ln1g, ln1b, wq, wk, wv, wo);
    k3b<<<(BB*HWSZ*CC)/256, 256>>>();
    k4<<<(BB*HWSZ)/256, 512, K4_SMEM>>>(ln2g, ln2b, fc1w, fc1b);
    k5<<<BB*256*16, 128, 100*128*4>>>(dww, dwb);
    k6<<<(BB*HWSZ)/128, 256, (128*132 + 64*132)*4>>>(fc2w, fc2b, out);
}

// round 10
// speedup vs baseline: 3.3505x; 1.0922x over previous
#include <cuda_runtime.h>
#include <cuda_fp16.h>
#include <cuda_bf16.h>
#include <cstddef>

// ---------------- problem geometry (fixed by setup_inputs) ----------------
#define BB    2
#define CC    64
#define HH    256
#define WW    256
#define PP    16
#define STEP  14
#define NHP   19
#define NPAT  361
#define BN    722
#define LL    256
#define NHEAD 4
#define DHEAD 16
#define MLP   128
#define HWSZ  65536

#define QSCALE 0.36067376022224085f   // 0.25 * log2(e)

#define KSTR 264
#define VSTR 268
#define WMAT 4608                     // words per weight matrix in pair layout

// ---------------- scratch ----------
__device__ float g_t [(size_t)BN*LL*CC];
__device__ float g_o [(size_t)BN*LL*CC];
__device__ float g_xs[(size_t)BB*HWSZ*CC];
__device__ __half g_h1[(size_t)BB*HWSZ*MLP];
__device__ __half g_h2[(size_t)BB*HWSZ*MLP];

__device__ int   d_cov_cnt[256];
__device__ int   d_cov_p[256][2];
__device__ int   d_cov_o[256][2];
__device__ float d_invdiv[256];

__global__ void k_init()
{
    int r = threadIdx.x;
    if (r < 256) {
        int cnt = 0;
        for (int ph = 0; ph < NHP; ph++) {
            int top = min(STEP*ph, HH-PP);
            if (r >= top && r < top + PP && cnt < 2) {
                d_cov_p[r][cnt] = ph;
                d_cov_o[r][cnt] = r - top;
                cnt++;
            }
        }
        d_cov_cnt[r] = cnt;
    }
    if (threadIdx.x == 0) {
        float div[256];
        for (int i = 0; i < 256; i++) div[i] = 1.f;
        for (int i = STEP; i < HH + STEP - PP; i += STEP) {
            int top = (i + PP > HH) ? (HH - PP) : i;
            for (int r2 = top; r2 < i + PP - STEP; ++r2) div[r2] *= 2.f;
        }
        for (int i = 0; i < 256; i++) d_invdiv[i] = 1.f / div[i];
    }
}

// ---------------- mma helpers ---------------------------------------------
__device__ __forceinline__ unsigned f2tf(float x) {
    unsigned r; asm("cvt.rna.tf32.f32 %0, %1;" : "=r"(r) : "f"(x)); return r;
}
__device__ __forceinline__ float ex2(float x) {
    float r; asm("ex2.approx.ftz.f32 %0, %1;" : "=f"(r) : "f"(x)); return r;
}
__device__ __forceinline__ void mma_tf32(float* d, const unsigned* a,
                                         unsigned b0, unsigned b1) {
    asm volatile("mma.sync.aligned.m16n8k8.row.col.f32.tf32.tf32.f32 "
        "{%0,%1,%2,%3},{%4,%5,%6,%7},{%8,%9},{%0,%1,%2,%3};"
        : "+f"(d[0]), "+f"(d[1]), "+f"(d[2]), "+f"(d[3])
        : "r"(a[0]), "r"(a[1]), "r"(a[2]), "r"(a[3]), "r"(b0), "r"(b1));
}
__device__ __forceinline__ float gelu(float x) {
    return 0.5f * x * (1.f + erff(x * 0.70710678118654752f));
}
__device__ __forceinline__ void c2a(const float c[4], int t, int sl0, int sl2,
                                    float scale, unsigned a[4]) {
    float r0 = __shfl_sync(0xffffffffu, c[0], sl0);
    float r1 = __shfl_sync(0xffffffffu, c[1], sl0);
    float v0 = (t & 1) ? r1 : r0;
    r0 = __shfl_sync(0xffffffffu, c[0], sl2);
    r1 = __shfl_sync(0xffffffffu, c[1], sl2);
    float v2 = (t & 1) ? r1 : r0;
    r0 = __shfl_sync(0xffffffffu, c[2], sl0);
    r1 = __shfl_sync(0xffffffffu, c[3], sl0);
    float v1 = (t & 1) ? r1 : r0;
    r0 = __shfl_sync(0xffffffffu, c[2], sl2);
    r1 = __shfl_sync(0xffffffffu, c[3], sl2);
    float v3 = (t & 1) ? r1 : r0;
    a[0] = f2tf(v0 * scale); a[1] = f2tf(v1 * scale);
    a[2] = f2tf(v2 * scale); a[3] = f2tf(v3 * scale);
}
// frag-pair weight layout: pair index p = j*36 + kt*4 + t; words {2p,2p+1}
// hold input channels c = kt*8+t and kt*8+t+4 of output column j.
// 16-row x 64-col GEMM: acc[8][4] += A(frags) @ B (pair layout, stride 36)
__device__ __forceinline__ void gemm64p(const unsigned aq[8][4],
                                        const unsigned* __restrict__ wsm,
                                        int g, int t, float acc[8][4]) {
    #pragma unroll
    for (int nt = 0; nt < 8; nt++)
        #pragma unroll
        for (int i = 0; i < 4; i++) acc[nt][i] = 0.f;
    #pragma unroll
    for (int nt = 0; nt < 8; nt++)
        #pragma unroll
        for (int kt = 0; kt < 8; kt++) {
            uint2 b = *(const uint2*)&wsm[((nt*8 + g)*36 + kt*4 + t)*2];
            mma_tf32(acc[nt], aq[kt], b.x, b.y);
        }
}

// ---------------- kA: gather + LN1 + QKV + attention + o@wo + t -----------
// block = patch (722), 512 thr = 16 warps. smem 193.5 KB.
//   ps  : 256*68 fp32 (patch -> h tf32)   -> reused as K^T
//   ws  : 3 mats x WMAT words (frag-pair tf32); mat-0 slot reused for wo
//   vsm : V^T
__global__ __launch_bounds__(512) void kA(const float* __restrict__ x,
                                          const float* __restrict__ g1,
                                          const float* __restrict__ b1,
                                          const float* __restrict__ wq,
                                          const float* __restrict__ wk,
                                          const float* __restrict__ wv,
                                          const float* __restrict__ wo)
{
    extern __shared__ float sm[];
    float*    ps  = sm;                               // 17408 words
    unsigned* ws  = (unsigned*)(sm + 17408);          // 13824 words (3*WMAT)
    unsigned* vsm = (unsigned*)(sm + 17408 + 13824);  // 17152 words
    unsigned* ksm = (unsigned*)ps;

    int tid = threadIdx.x;
    int bn = blockIdx.x;
    int b  = bn / NPAT, n = bn % NPAT;
    int ph = n / NHP,   pw = n % NHP;
    int top  = min(STEP*ph, HH-PP);
    int left = min(STEP*pw, WW-PP);
    const float* xb = x + (size_t)b * CC * HWSZ;

    // weights -> frag-pair layout (per-matrix stride WMAT = 4608 words)
    for (int idx = tid; idx < 3*64*64; idx += 512) {
        int mat = idx >> 12; int rem = idx & 4095;
        int c = rem >> 6, j = rem & 63;
        const float* w = (mat == 0) ? wq : (mat == 1) ? wk : wv;
        int kt = c >> 3, r = c & 7, tt = r & 3, hi = r >> 2;
        ws[mat*WMAT + (j*36 + kt*4 + tt)*2 + hi] = f2tf(w[rem]);
    }
    for (int idx = tid; idx < CC*LL; idx += 512) {
        int c = idx >> 8, l = idx & 255;
        int li = l >> 4, lj = l & 15;
        ps[l*68 + c] = xb[(size_t)c*HWSZ + (size_t)(top+li)*WW + (left+lj)];
    }
    __syncthreads();

    int lane = tid & 31, warp = tid >> 5;
    {
        float ga = g1[lane], gb = g1[lane+32], ba = b1[lane], bbv = b1[lane+32];
        for (int l = warp; l < LL; l += 16) {
            float v0 = ps[l*68 + lane], v1 = ps[l*68 + lane + 32];
            size_t tb = ((size_t)bn*LL + l) * CC;
            g_t[tb + lane] = v0;  g_t[tb + lane + 32] = v1;
            float s = v0 + v1, ss = v0*v0 + v1*v1;
            #pragma unroll
            for (int o = 16; o; o >>= 1) {
                s  += __shfl_xor_sync(0xffffffffu, s,  o);
                ss += __shfl_xor_sync(0xffffffffu, ss, o);
            }
            float mean = s * (1.f/64.f);
            float var  = ss * (1.f/64.f) - mean*mean;
            float rstd = rsqrtf(var + 1e-5f);
            ps[l*68 + lane]      = __uint_as_float(f2tf((v0 - mean) * rstd * ga + ba));
            ps[l*68 + lane + 32] = __uint_as_float(f2tf((v1 - mean) * rstd * gb + bbv));
        }
    }
    __syncthreads();

    const unsigned* hs = (const unsigned*)ps;
    int g = lane >> 2, t = lane & 3;
    unsigned aq[8][4];
    {
        int r0 = (warp*16 + g)*68;
        #pragma unroll
        for (int kt = 0; kt < 8; kt++) {
            int c0 = kt*8 + t;
            aq[kt][0] = hs[r0 + c0];
            aq[kt][1] = hs[r0 + 544 + c0];
            aq[kt][2] = hs[r0 + c0 + 4];
            aq[kt][3] = hs[r0 + 544 + c0 + 4];
        }
    }
    __syncthreads();   // barrier A: ps free (becomes K^T)

    {
        float acc[8][4];
        gemm64p(aq, ws + WMAT, g, t, acc);       // K (mat 1)
        #pragma unroll
        for (int nt = 0; nt < 8; nt++) {
            int tok = warp*16 + g;
            int hd  = nt >> 1;
            int d0  = (nt & 1)*8 + 2*t;
            unsigned* kp = ksm + (hd*16 + d0)*KSTR;
            kp[tok]            = f2tf(acc[nt][0]);
            kp[KSTR + tok]     = f2tf(acc[nt][1]);
            kp[tok + 8]        = f2tf(acc[nt][2]);
            kp[KSTR + tok + 8] = f2tf(acc[nt][3]);
        }
        gemm64p(aq, ws + 2*WMAT, g, t, acc);     // V (mat 2)
        #pragma unroll
        for (int nt = 0; nt < 8; nt++) {
            int tok = warp*16 + g;
            int hd  = nt >> 1;
            int d0  = (nt & 1)*8 + 2*t;
            unsigned* vp = vsm + (hd*16 + d0)*VSTR;
            vp[tok]            = f2tf(acc[nt][0]);
            vp[VSTR + tok]     = f2tf(acc[nt][1]);
            vp[tok + 8]        = f2tf(acc[nt][2]);
            vp[VSTR + tok + 8] = f2tf(acc[nt][3]);
        }
    }
    float qacc[8][4];
    gemm64p(aq, ws, g, t, qacc);                 // Q (mat 0, registers)
    __syncthreads();   // barrier B: K/V visible; ws mat-0 writable

    // wo -> frag-pair layout (reuse mat-0 slot)
    for (int idx = tid; idx < 4096; idx += 512) {
        int c = idx >> 6, j = idx & 63;
        int kt = c >> 3, r = c & 7, tt = r & 3, hi = r >> 2;
        ws[(j*36 + kt*4 + tt)*2 + hi] = f2tf(wo[idx]);
    }

    int sl0 = (lane & ~3) + (t >> 1);
    int sl2 = sl0 + 2;
    float oall[4][2][4];
    #pragma unroll
    for (int head = 0; head < NHEAD; head++) {
        unsigned aqh[2][4];
        #pragma unroll
        for (int kt = 0; kt < 2; kt++)
            c2a(qacc[head*2 + kt], t, sl0, sl2, QSCALE, aqh[kt]);

        const unsigned* kh = ksm + head*16*KSTR;
        const unsigned* vh = vsm + head*16*VSTR;
        float oh[2][4];
        #pragma unroll
        for (int nd = 0; nd < 2; nd++)
            #pragma unroll
            for (int i = 0; i < 4; i++) oh[nd][i] = 0.f;
        float mrow[2] = {-1e30f, -1e30f};
        float drow[2] = {0.f, 0.f};

        #pragma unroll 1
        for (int jt = 0; jt < 8; jt++) {
            float s[4][4];
            #pragma unroll
            for (int nt = 0; nt < 4; nt++)
                #pragma unroll
                for (int i = 0; i < 4; i++) s[nt][i] = 0.f;
            #pragma unroll
            for (int nt = 0; nt < 4; nt++)
                #pragma unroll
                for (int kt = 0; kt < 2; kt++) {
                    int jr = (kt*8 + t)*KSTR + jt*32 + nt*8 + g;
                    mma_tf32(s[nt], aqh[kt], kh[jr], kh[jr + 4*KSTR]);
                }
            #pragma unroll
            for (int h = 0; h < 2; h++) {
                float mx = fmaxf(s[0][h*2], s[0][h*2+1]);
                #pragma unroll
                for (int nt = 1; nt < 4; nt++)
                    mx = fmaxf(mx, fmaxf(s[nt][h*2], s[nt][h*2+1]));
                mx = fmaxf(mx, __shfl_xor_sync(0xffffffffu, mx, 1));
                mx = fmaxf(mx, __shfl_xor_sync(0xffffffffu, mx, 2));
                float mn = fmaxf(mrow[h], mx);
                float scale = ex2(mrow[h] - mn);
                mrow[h] = mn;
                drow[h] *= scale;
                #pragma unroll
                for (int nd = 0; nd < 2; nd++) {
                    oh[nd][h*2]   *= scale;
                    oh[nd][h*2+1] *= scale;
                }
                float psum = 0.f;
                #pragma unroll
                for (int nt = 0; nt < 4; nt++) {
                    float e0 = ex2(s[nt][h*2]   - mn);
                    float e1 = ex2(s[nt][h*2+1] - mn);
                    s[nt][h*2] = e0; s[nt][h*2+1] = e1;
                    psum += e0 + e1;
                }
                drow[h] += psum;
            }
            unsigned p[4][4];
            #pragma unroll
            for (int nt = 0; nt < 4; nt++)
                #pragma unroll
                for (int i = 0; i < 4; i++) p[nt][i] = f2tf(s[nt][i]);
            #pragma unroll
            for (int kt = 0; kt < 4; kt++) {
                unsigned ap[4];
                {
                    unsigned r0 = __shfl_sync(0xffffffffu, p[kt][0], sl0);
                    unsigned r1 = __shfl_sync(0xffffffffu, p[kt][1], sl0);
                    ap[0] = (t & 1) ? r1 : r0;
                    r0 = __shfl_sync(0xffffffffu, p[kt][0], sl2);
                    r1 = __shfl_sync(0xffffffffu, p[kt][1], sl2);
                    ap[2] = (t & 1) ? r1 : r0;
                    r0 = __shfl_sync(0xffffffffu, p[kt][2], sl0);
                    r1 = __shfl_sync(0xffffffffu, p[kt][3], sl0);
                    ap[1] = (t & 1) ? r1 : r0;
                    r0 = __shfl_sync(0xffffffffu, p[kt][2], sl2);
                    r1 = __shfl_sync(0xffffffffu, p[kt][3], sl2);
                    ap[3] = (t & 1) ? r1 : r0;
                }
                #pragma unroll
                for (int nd = 0; nd < 2; nd++) {
                    int vr = (nd*8 + g)*VSTR + jt*32 + kt*8 + t;
                    mma_tf32(oh[nd], ap, vh[vr], vh[vr + 4]);
                }
            }
        }
        float inv[2];
        #pragma unroll
        for (int h = 0; h < 2; h++) {
            float d = drow[h];
            d += __shfl_xor_sync(0xffffffffu, d, 1);
            d += __shfl_xor_sync(0xffffffffu, d, 2);
            inv[h] = 1.f / d;
        }
        #pragma unroll
        for (int nd = 0; nd < 2; nd++) {
            oall[head][nd][0] = oh[nd][0]*inv[0];
            oall[head][nd][1] = oh[nd][1]*inv[0];
            oall[head][nd][2] = oh[nd][2]*inv[1];
            oall[head][nd][3] = oh[nd][3]*inv[1];
        }
    }
    __syncthreads();   // barrier C: wo visible

    {
        float acc[8][4];
        #pragma unroll
        for (int nt = 0; nt < 8; nt++)
            #pragma unroll
            for (int i = 0; i < 4; i++) acc[nt][i] = 0.f;
        #pragma unroll
        for (int kt = 0; kt < 8; kt++) {
            int head = kt >> 1, nd = kt & 1;
            unsigned ao[4];
            c2a(oall[head][nd], t, sl0, sl2, 1.f, ao);
            #pragma unroll
            for (int nt = 0; nt < 8; nt++) {
                uint2 bw = *(const uint2*)&ws[((nt*8 + g)*36 + kt*4 + t)*2];
                mma_tf32(acc[nt], ao, bw.x, bw.y);
            }
        }
        size_t row0 = (size_t)bn * LL;
        #pragma unroll
        for (int nt = 0; nt < 8; nt++) {
            int row = warp*16 + g, col = nt*8 + 2*t;
            size_t a0 = (row0 + row)*CC + col;
            size_t a1 = (row0 + row + 8)*CC + col;
            float2 t0 = *(const float2*)&g_t[a0];
            float2 t1 = *(const float2*)&g_t[a1];
            float2 w0; w0.x = acc[nt][0] + t0.x; w0.y = acc[nt][1] + t0.y;
            float2 w1; w1.x = acc[nt][2] + t1.x; w1.y = acc[nt][3] + t1.y;
            *(float2*)&g_o[a0] = w0;
            *(float2*)&g_o[a1] = w1;
        }
    }
}

// ---------------- K3b: deterministic patch_reverse + div ------------------
__global__ __launch_bounds__(256) void k3b()
{
    int e = blockIdx.x * 256 + threadIdx.x;
    int c   = e & 63;
    int pix = e >> 6;
    int b   = pix >> 16;
    int hw  = pix & 65535;
    int r   = hw >> 8, w = hw & 255;
    float acc = 0.f;
    int hc = d_cov_cnt[r], wc = d_cov_cnt[w];
    for (int i = 0; i < hc; i++) {
        int php = d_cov_p[r][i], li = d_cov_o[r][i];
        for (int k = 0; k < wc; k++) {
            int n = php*NHP + d_cov_p[w][k];
            int l = li*PP  + d_cov_o[w][k];
            acc += g_o[(((size_t)(b*NPAT + n))*LL + l)*CC + c];
        }
    }
    g_xs[e] = acc * d_invdiv[r] * d_invdiv[w];
}

// ---------------- K4: LN2 + fc1 + GELU (pair layout, fp16 out) ------------
__global__ __launch_bounds__(512) void k4(const float* __restrict__ g2,
                                          const float* __restrict__ b2,
                                          const float* __restrict__ fc1w,
                                          const float* __restrict__ fc1b)
{
    extern __shared__ float sm4[];
    float*    xsm = sm4;                        // 256*68
    unsigned* fw  = (unsigned*)(sm4 + 256*68);  // 128 j x 36 pairs x 2 = 9216 words
    int tid = threadIdx.x;
    size_t pix0 = (size_t)blockIdx.x * 256;
    for (int idx = tid; idx < 4096; idx += 512) {
        int row = idx >> 4, c4 = (idx & 15) * 4;
        *(float4*)&xsm[row*68 + c4] = *(const float4*)&g_xs[(pix0 + row)*CC + c4];
    }
    for (int idx = tid; idx < 8192; idx += 512) {
        int c = idx >> 7, j = idx & 127;
        int kt = c >> 3, r = c & 7, tt = r & 3, hi = r >> 2;
        fw[(j*36 + kt*4 + tt)*2 + hi] = f2tf(fc1w[idx]);
    }
    __syncthreads();

    int lane = tid & 31, warp = tid >> 5;
    float ga = g2[lane], gb = g2[lane+32], ba = b2[lane], bbv = b2[lane+32];
    for (int r = warp; r < 256; r += 16) {
        float v0 = xsm[r*68+lane], v1 = xsm[r*68+lane+32];
        float s = v0+v1, ss = v0*v0+v1*v1;
        #pragma unroll
        for (int o = 16; o; o >>= 1) {
            s  += __shfl_xor_sync(0xffffffffu, s,  o);
            ss += __shfl_xor_sync(0xffffffffu, ss, o);
        }
        float mean = s * (1.f/64.f);
        float var  = ss * (1.f/64.f) - mean*mean;
        float rstd = rsqrtf(var + 1e-5f);
        xsm[r*68+lane]    = __uint_as_float(f2tf((v0 - mean) * rstd * ga + ba));
        xsm[r*68+lane+32] = __uint_as_float(f2tf((v1 - mean) * rstd * gb + bbv));
    }
    __syncthreads();

    const unsigned* hs = (const unsigned*)xsm;
    int g = lane >> 2, t = lane & 3;
    int r0 = (warp*16 + g)*68;
    unsigned aq[8][4];
    #pragma unroll
    for (int kt = 0; kt < 8; kt++) {
        int c0 = kt*8 + t;
        aq[kt][0] = hs[r0 + c0];
        aq[kt][1] = hs[r0 + 544 + c0];
        aq[kt][2] = hs[r0 + c0 + 4];
        aq[kt][3] = hs[r0 + 544 + c0 + 4];
    }
    float acc[16][4];
    #pragma unroll
    for (int nt = 0; nt < 16; nt++) {
        float2 bb = *(const float2*)&fc1b[nt*8 + 2*t];
        acc[nt][0] = bb.x; acc[nt][1] = bb.y; acc[nt][2] = bb.x; acc[nt][3] = bb.y;
    }
    #pragma unroll
    for (int nt = 0; nt < 16; nt++)
        #pragma unroll
        for (int kt = 0; kt < 8; kt++) {
            uint2 b = *(const uint2*)&fw[((nt*8 + g)*36 + kt*4 + t)*2];
            mma_tf32(acc[nt], aq[kt], b.x, b.y);
        }
    #pragma unroll
    for (int nt = 0; nt < 16; nt++) {
        int row = warp*16 + g, col = nt*8 + 2*t;
        __half2 h0 = __floats2half2_rn(gelu(acc[nt][0]), gelu(acc[nt][1]));
        __half2 h1 = __floats2half2_rn(gelu(acc[nt][2]), gelu(acc[nt][3]));
        *(__half2*)&g_h1[(pix0 + row)*MLP + col]     = h0;
        *(__half2*)&g_h1[(pix0 + row + 8)*MLP + col] = h1;
    }
}

// ---------------- K5: depthwise 5x5 + GELU + residual (fp16 io) -----------
__global__ __launch_bounds__(128) void k5(const float* __restrict__ dww,
                                          const float* __restrict__ dwb)
{
    extern __shared__ __half si[];           // 100 slots x 128 ch fp16 = 25.6KB
    int ch = threadIdx.x;
    int bx = blockIdx.x;
    int cw0 = (bx & 15) * 16;
    int r   = (bx >> 4) & 255;
    int b   = bx >> 12;
    float wreg[25];
    #pragma unroll
    for (int i = 0; i < 25; i++) wreg[i] = dww[ch*25 + i];
    float bias = dwb[ch];
    const uint4* hp = (const uint4*)(g_h1 + (size_t)b * HWSZ * MLP);

    // halo: 100 slots x 128 ch, 16 uint4 per slot (256 B)
    for (int idx = ch; idx < 100*16; idx += 128) {
        int slot = idx >> 4, u = idx & 15;
        int ry = slot / 20, cx = slot % 20;
        int rr = r + ry - 2, cc = cw0 + cx - 2;
        uint4 v = {0u, 0u, 0u, 0u};
        if (rr >= 0 && rr < 256 && cc >= 0 && cc < 256)
            v = hp[(size_t)(rr*256 + cc)*16 + u];
        *(uint4*)&si[slot*MLP + u*8] = v;
    }
    __syncthreads();

    __half* op = g_h2 + ((size_t)b*HWSZ + (size_t)r*256 + cw0) * MLP;
    #pragma unroll 1
    for (int half = 0; half < 2; half++) {
        int k0 = half * 8;
        float val[5][12];
        #pragma unroll
        for (int dy = 0; dy < 5; dy++)
            #pragma unroll
            for (int xx = 0; xx < 12; xx++)
                val[dy][xx] = __half2float(si[(dy*20 + k0 + xx)*MLP + ch]);
        #pragma unroll
        for (int k = 0; k < 8; k++) {
            float acc = bias;
            #pragma unroll
            for (int dy = 0; dy < 5; dy++)
                #pragma unroll
                for (int dx = 0; dx < 5; dx++)
                    acc += val[dy][k + dx] * wreg[dy*5 + dx];
            float center = val[2][k + 2];
            op[(size_t)(k0 + k)*MLP + ch] = __float2half(center + gelu(acc));
        }
    }
}

// ---------------- K6: fc2 + bias + residual + transpose (pair layout) -----
__global__ __launch_bounds__(256) void k6(const float* __restrict__ fc2w,
                                          const float* __restrict__ fc2b,
                                          float* __restrict__ out)
{
    extern __shared__ unsigned sm6[];
    unsigned* hs = sm6;              // 128*132 tf32
    unsigned* fw = sm6 + 128*132;    // 64 j x 68 pairs x 2 = 8704 words (reused as tile)
    float*  tile = (float*)fw;       // 64*132 = 8448 <= 8704
    int tid = threadIdx.x;
    size_t pix0 = (size_t)blockIdx.x * 128;
    int b   = (int)(pix0 >> 16);
    int hw0 = (int)(pix0 & 65535);
    for (int idx = tid; idx < 4096; idx += 256) {
        int row = idx >> 5, c4 = (idx & 31) * 4;
        const __half2* h2p = (const __half2*)&g_h2[(pix0 + row)*MLP + c4];
        __half2 a = h2p[0], c = h2p[1];
        hs[row*132 + c4    ] = f2tf(__low2float(a));
        hs[row*132 + c4 + 1] = f2tf(__high2float(a));
        hs[row*132 + c4 + 2] = f2tf(__low2float(c));
        hs[row*132 + c4 + 3] = f2tf(__high2float(c));
    }
    for (int idx = tid; idx < 8192; idx += 256) {
        int c = idx >> 6, j = idx & 63;
        int kt = c >> 3, r = c & 7, tt = r & 3, hi = r >> 2;
        fw[(j*68 + kt*4 + tt)*2 + hi] = f2tf(fc2w[idx]);
    }
    __syncthreads();

    int lane = tid & 31, w = tid >> 5, g = lane >> 2, t = lane & 3;
    int r0 = (w*16 + g)*132;
    unsigned aq[16][4];
    #pragma unroll
    for (int kt = 0; kt < 16; kt++) {
        int c0 = kt*8 + t;
        aq[kt][0] = hs[r0 + c0];
        aq[kt][1] = hs[r0 + 8*132 + c0];
        aq[kt][2] = hs[r0 + c0 + 4];
        aq[kt][3] = hs[r0 + 8*132 + c0 + 4];
    }
    float acc[8][4];
    #pragma unroll
    for (int nt = 0; nt < 8; nt++)
        #pragma unroll
        for (int i = 0; i < 4; i++) acc[nt][i] = 0.f;
    #pragma unroll
    for (int nt = 0; nt < 8; nt++)
        #pragma unroll
        for (int kt = 0; kt < 16; kt++) {
            uint2 bw = *(const uint2*)&fw[((nt*8 + g)*68 + kt*4 + t)*2];
            mma_tf32(acc[nt], aq[kt], bw.x, bw.y);
        }
    __syncthreads();
    #pragma unroll
    for (int nt = 0; nt < 8; nt++) {
        int row = w*16 + g, col = nt*8 + 2*t;
        float2 bb = *(const float2*)&fc2b[col];
        float2 x0 = *(const float2*)&g_xs[(pix0 + row)*CC + col];
        float2 x1 = *(const float2*)&g_xs[(pix0 + row + 8)*CC + col];
        tile[(col  )*132 + row]     = acc[nt][0] + bb.x + x0.x;
        tile[(col+1)*132 + row]     = acc[nt][1] + bb.y + x0.y;
        tile[(col  )*132 + row + 8] = acc[nt][2] + bb.x + x1.x;
        tile[(col+1)*132 + row + 8] = acc[nt][3] + bb.y + x1.y;
    }
    __syncthreads();
    for (int idx = tid; idx < 2048; idx += 256) {
        int c = idx >> 5, p4 = (idx & 31) * 4;
        *(float4*)&out[((size_t)(b*CC + c))*HWSZ + hw0 + p4] = *(const float4*)&tile[c*132 + p4];
    }
}

// ---------------- launch ---------------------------------------------------
#define KA_SMEM ((17408 + 13824 + 17152) * 4)
#define K4_SMEM ((256*68 + 9216) * 4)
#define K6_SMEM ((128*132 + 8704) * 4)

extern "C" void kernel_launch(void* const* d_in, const int* in_sizes, int n_in,
                              void* d_out, int out_size)
{
    const float* x    = (const float*)d_in[0];
    const float* ln1g = (const float*)d_in[1];
    const float* ln1b = (const float*)d_in[2];
    const float* wq   = (const float*)d_in[3];
    const float* wk   = (const float*)d_in[4];
    const float* wv   = (const float*)d_in[5];
    const float* wo   = (const float*)d_in[6];
    const float* ln2g = (const float*)d_in[7];
    const float* ln2b = (const float*)d_in[8];
    const float* fc1w = (const float*)d_in[9];
    const float* fc1b = (const float*)d_in[10];
    const float* dww  = (const float*)d_in[11];
    const float* dwb  = (const float*)d_in[12];
    const float* fc2w = (const float*)d_in[13];
    const float* fc2b = (const float*)d_in[14];
    float* out = (float*)d_out;

    static int s_attr = 0;
    if (!s_attr) {
        cudaFuncSetAttribute(kA, cudaFuncAttributeMaxDynamicSharedMemorySize, KA_SMEM);
        cudaFuncSetAttribute(k4, cudaFuncAttributeMaxDynamicSharedMemorySize, K4_SMEM);
        cudaFuncSetAttribute(k5, cudaFuncAttributeMaxDynamicSharedMemorySize, 100*128*2);
        cudaFuncSetAttribute(k6, cudaFuncAttributeMaxDynamicSharedMemorySize, K6_SMEM);
        s_attr = 1;
    }

    k_init<<<1, 256>>>();
    kA<<<BN, 512, KA_SMEM>>>(x, ln1g, ln1b, wq, wk, wv, wo);
    k3b<<<(BB*HWSZ*CC)/256, 256>>>();
    k4<<<(BB*HWSZ)/256, 512, K4_SMEM>>>(ln2g, ln2b, fc1w, fc1b);
    k5<<<BB*256*16, 128, 100*128*2>>>(dww, dwb);
    k6<<<(BB*HWSZ)/128, 256, K6_SMEM>>>(fc2w, fc2b, out);
}

// round 11
// speedup vs baseline: 3.4893x; 1.0414x over previous
#include <cuda_runtime.h>
#include <cuda_fp16.h>
#include <cuda_bf16.h>
#include <cstddef>

// ---------------- problem geometry (fixed by setup_inputs) ----------------
#define BB    2
#define CC    64
#define HH    256
#define WW    256
#define PP    16
#define STEP  14
#define NHP   19
#define NPAT  361
#define BN    722
#define LL    256
#define NHEAD 4
#define DHEAD 16
#define MLP   128
#define HWSZ  65536

#define QSCALE 0.36067376022224085f   // 0.25 * log2(e)

#define KSTR 264
#define VSTR 268
#define WMAT 4608                     // words per weight matrix in pair layout

// ---------------- scratch ----------
__device__ float g_t [(size_t)BN*LL*CC];
__device__ float g_o [(size_t)BN*LL*CC];
__device__ float g_xs[(size_t)BB*HWSZ*CC];
__device__ __half g_h1[(size_t)BB*HWSZ*MLP];

__device__ int   d_cov_cnt[256];
__device__ int   d_cov_p[256][2];
__device__ int   d_cov_o[256][2];
__device__ float d_invdiv[256];

__global__ void k_init()
{
    int r = threadIdx.x;
    if (r < 256) {
        int cnt = 0;
        for (int ph = 0; ph < NHP; ph++) {
            int top = min(STEP*ph, HH-PP);
            if (r >= top && r < top + PP && cnt < 2) {
                d_cov_p[r][cnt] = ph;
                d_cov_o[r][cnt] = r - top;
                cnt++;
            }
        }
        d_cov_cnt[r] = cnt;
    }
    if (threadIdx.x == 0) {
        float div[256];
        for (int i = 0; i < 256; i++) div[i] = 1.f;
        for (int i = STEP; i < HH + STEP - PP; i += STEP) {
            int top = (i + PP > HH) ? (HH - PP) : i;
            for (int r2 = top; r2 < i + PP - STEP; ++r2) div[r2] *= 2.f;
        }
        for (int i = 0; i < 256; i++) d_invdiv[i] = 1.f / div[i];
    }
}

// ---------------- mma helpers ---------------------------------------------
__device__ __forceinline__ unsigned f2tf(float x) {
    unsigned r; asm("cvt.rna.tf32.f32 %0, %1;" : "=r"(r) : "f"(x)); return r;
}
__device__ __forceinline__ float ex2(float x) {
    float r; asm("ex2.approx.ftz.f32 %0, %1;" : "=f"(r) : "f"(x)); return r;
}
__device__ __forceinline__ void mma_tf32(float* d, const unsigned* a,
                                         unsigned b0, unsigned b1) {
    asm volatile("mma.sync.aligned.m16n8k8.row.col.f32.tf32.tf32.f32 "
        "{%0,%1,%2,%3},{%4,%5,%6,%7},{%8,%9},{%0,%1,%2,%3};"
        : "+f"(d[0]), "+f"(d[1]), "+f"(d[2]), "+f"(d[3])
        : "r"(a[0]), "r"(a[1]), "r"(a[2]), "r"(a[3]), "r"(b0), "r"(b1));
}
__device__ __forceinline__ float gelu(float x) {
    return 0.5f * x * (1.f + erff(x * 0.70710678118654752f));
}
__device__ __forceinline__ void c2a(const float c[4], int t, int sl0, int sl2,
                                    float scale, unsigned a[4]) {
    float r0 = __shfl_sync(0xffffffffu, c[0], sl0);
    float r1 = __shfl_sync(0xffffffffu, c[1], sl0);
    float v0 = (t & 1) ? r1 : r0;
    r0 = __shfl_sync(0xffffffffu, c[0], sl2);
    r1 = __shfl_sync(0xffffffffu, c[1], sl2);
    float v2 = (t & 1) ? r1 : r0;
    r0 = __shfl_sync(0xffffffffu, c[2], sl0);
    r1 = __shfl_sync(0xffffffffu, c[3], sl0);
    float v1 = (t & 1) ? r1 : r0;
    r0 = __shfl_sync(0xffffffffu, c[2], sl2);
    r1 = __shfl_sync(0xffffffffu, c[3], sl2);
    float v3 = (t & 1) ? r1 : r0;
    a[0] = f2tf(v0 * scale); a[1] = f2tf(v1 * scale);
    a[2] = f2tf(v2 * scale); a[3] = f2tf(v3 * scale);
}
// frag-pair weight layout: pair index p = j*36 + kt*4 + t; words {2p,2p+1}
// hold input channels c = kt*8+t and kt*8+t+4 of output column j.
__device__ __forceinline__ void gemm64p(const unsigned aq[8][4],
                                        const unsigned* __restrict__ wsm,
                                        int g, int t, float acc[8][4]) {
    #pragma unroll
    for (int nt = 0; nt < 8; nt++)
        #pragma unroll
        for (int i = 0; i < 4; i++) acc[nt][i] = 0.f;
    #pragma unroll
    for (int nt = 0; nt < 8; nt++)
        #pragma unroll
        for (int kt = 0; kt < 8; kt++) {
            uint2 b = *(const uint2*)&wsm[((nt*8 + g)*36 + kt*4 + t)*2];
            mma_tf32(acc[nt], aq[kt], b.x, b.y);
        }
}

// ---------------- kA: gather + LN1 + QKV + attention + o@wo + t -----------
__global__ __launch_bounds__(512) void kA(const float* __restrict__ x,
                                          const float* __restrict__ g1,
                                          const float* __restrict__ b1,
                                          const float* __restrict__ wq,
                                          const float* __restrict__ wk,
                                          const float* __restrict__ wv,
                                          const float* __restrict__ wo)
{
    extern __shared__ float sm[];
    float*    ps  = sm;                               // 17408 words
    unsigned* ws  = (unsigned*)(sm + 17408);          // 13824 words (3*WMAT)
    unsigned* vsm = (unsigned*)(sm + 17408 + 13824);  // 17152 words
    unsigned* ksm = (unsigned*)ps;

    int tid = threadIdx.x;
    int bn = blockIdx.x;
    int b  = bn / NPAT, n = bn % NPAT;
    int ph = n / NHP,   pw = n % NHP;
    int top  = min(STEP*ph, HH-PP);
    int left = min(STEP*pw, WW-PP);
    const float* xb = x + (size_t)b * CC * HWSZ;

    for (int idx = tid; idx < 3*64*64; idx += 512) {
        int mat = idx >> 12; int rem = idx & 4095;
        int c = rem >> 6, j = rem & 63;
        const float* w = (mat == 0) ? wq : (mat == 1) ? wk : wv;
        int kt = c >> 3, r = c & 7, tt = r & 3, hi = r >> 2;
        ws[mat*WMAT + (j*36 + kt*4 + tt)*2 + hi] = f2tf(w[rem]);
    }
    for (int idx = tid; idx < CC*LL; idx += 512) {
        int c = idx >> 8, l = idx & 255;
        int li = l >> 4, lj = l & 15;
        ps[l*68 + c] = xb[(size_t)c*HWSZ + (size_t)(top+li)*WW + (left+lj)];
    }
    __syncthreads();

    int lane = tid & 31, warp = tid >> 5;
    {
        float ga = g1[lane], gb = g1[lane+32], ba = b1[lane], bbv = b1[lane+32];
        for (int l = warp; l < LL; l += 16) {
            float v0 = ps[l*68 + lane], v1 = ps[l*68 + lane + 32];
            size_t tb = ((size_t)bn*LL + l) * CC;
            g_t[tb + lane] = v0;  g_t[tb + lane + 32] = v1;
            float s = v0 + v1, ss = v0*v0 + v1*v1;
            #pragma unroll
            for (int o = 16; o; o >>= 1) {
                s  += __shfl_xor_sync(0xffffffffu, s,  o);
                ss += __shfl_xor_sync(0xffffffffu, ss, o);
            }
            float mean = s * (1.f/64.f);
            float var  = ss * (1.f/64.f) - mean*mean;
            float rstd = rsqrtf(var + 1e-5f);
            ps[l*68 + lane]      = __uint_as_float(f2tf((v0 - mean) * rstd * ga + ba));
            ps[l*68 + lane + 32] = __uint_as_float(f2tf((v1 - mean) * rstd * gb + bbv));
        }
    }
    __syncthreads();

    const unsigned* hs = (const unsigned*)ps;
    int g = lane >> 2, t = lane & 3;
    unsigned aq[8][4];
    {
        int r0 = (warp*16 + g)*68;
        #pragma unroll
        for (int kt = 0; kt < 8; kt++) {
            int c0 = kt*8 + t;
            aq[kt][0] = hs[r0 + c0];
            aq[kt][1] = hs[r0 + 544 + c0];
            aq[kt][2] = hs[r0 + c0 + 4];
            aq[kt][3] = hs[r0 + 544 + c0 + 4];
        }
    }
    __syncthreads();   // barrier A: ps free (becomes K^T)

    {
        float acc[8][4];
        gemm64p(aq, ws + WMAT, g, t, acc);       // K (mat 1)
        #pragma unroll
        for (int nt = 0; nt < 8; nt++) {
            int tok = warp*16 + g;
            int hd  = nt >> 1;
            int d0  = (nt & 1)*8 + 2*t;
            unsigned* kp = ksm + (hd*16 + d0)*KSTR;
            kp[tok]            = f2tf(acc[nt][0]);
            kp[KSTR + tok]     = f2tf(acc[nt][1]);
            kp[tok + 8]        = f2tf(acc[nt][2]);
            kp[KSTR + tok + 8] = f2tf(acc[nt][3]);
        }
        gemm64p(aq, ws + 2*WMAT, g, t, acc);     // V (mat 2)
        #pragma unroll
        for (int nt = 0; nt < 8; nt++) {
            int tok = warp*16 + g;
            int hd  = nt >> 1;
            int d0  = (nt & 1)*8 + 2*t;
            unsigned* vp = vsm + (hd*16 + d0)*VSTR;
            vp[tok]            = f2tf(acc[nt][0]);
            vp[VSTR + tok]     = f2tf(acc[nt][1]);
            vp[tok + 8]        = f2tf(acc[nt][2]);
            vp[VSTR + tok + 8] = f2tf(acc[nt][3]);
        }
    }
    float qacc[8][4];
    gemm64p(aq, ws, g, t, qacc);                 // Q (mat 0, registers)
    __syncthreads();   // barrier B: K/V visible; ws mat-0 writable

    for (int idx = tid; idx < 4096; idx += 512) {
        int c = idx >> 6, j = idx & 63;
        int kt = c >> 3, r = c & 7, tt = r & 3, hi = r >> 2;
        ws[(j*36 + kt*4 + tt)*2 + hi] = f2tf(wo[idx]);
    }

    int sl0 = (lane & ~3) + (t >> 1);
    int sl2 = sl0 + 2;
    float oall[4][2][4];
    #pragma unroll
    for (int head = 0; head < NHEAD; head++) {
        unsigned aqh[2][4];
        #pragma unroll
        for (int kt = 0; kt < 2; kt++)
            c2a(qacc[head*2 + kt], t, sl0, sl2, QSCALE, aqh[kt]);

        const unsigned* kh = ksm + head*16*KSTR;
        const unsigned* vh = vsm + head*16*VSTR;
        float oh[2][4];
        #pragma unroll
        for (int nd = 0; nd < 2; nd++)
            #pragma unroll
            for (int i = 0; i < 4; i++) oh[nd][i] = 0.f;
        float mrow[2] = {-1e30f, -1e30f};
        float drow[2] = {0.f, 0.f};

        #pragma unroll 1
        for (int jt = 0; jt < 8; jt++) {
            float s[4][4];
            #pragma unroll
            for (int nt = 0; nt < 4; nt++)
                #pragma unroll
                for (int i = 0; i < 4; i++) s[nt][i] = 0.f;
            #pragma unroll
            for (int nt = 0; nt < 4; nt++)
                #pragma unroll
                for (int kt = 0; kt < 2; kt++) {
                    int jr = (kt*8 + t)*KSTR + jt*32 + nt*8 + g;
                    mma_tf32(s[nt], aqh[kt], kh[jr], kh[jr + 4*KSTR]);
                }
            #pragma unroll
            for (int h = 0; h < 2; h++) {
                float mx = fmaxf(s[0][h*2], s[0][h*2+1]);
                #pragma unroll
                for (int nt = 1; nt < 4; nt++)
                    mx = fmaxf(mx, fmaxf(s[nt][h*2], s[nt][h*2+1]));
                mx = fmaxf(mx, __shfl_xor_sync(0xffffffffu, mx, 1));
                mx = fmaxf(mx, __shfl_xor_sync(0xffffffffu, mx, 2));
                float mn = fmaxf(mrow[h], mx);
                float scale = ex2(mrow[h] - mn);
                mrow[h] = mn;
                drow[h] *= scale;
                #pragma unroll
                for (int nd = 0; nd < 2; nd++) {
                    oh[nd][h*2]   *= scale;
                    oh[nd][h*2+1] *= scale;
                }
                float psum = 0.f;
                #pragma unroll
                for (int nt = 0; nt < 4; nt++) {
                    float e0 = ex2(s[nt][h*2]   - mn);
                    float e1 = ex2(s[nt][h*2+1] - mn);
                    s[nt][h*2] = e0; s[nt][h*2+1] = e1;
                    psum += e0 + e1;
                }
                drow[h] += psum;
            }
            unsigned p[4][4];
            #pragma unroll
            for (int nt = 0; nt < 4; nt++)
                #pragma unroll
                for (int i = 0; i < 4; i++) p[nt][i] = f2tf(s[nt][i]);
            #pragma unroll
            for (int kt = 0; kt < 4; kt++) {
                unsigned ap[4];
                {
                    unsigned r0 = __shfl_sync(0xffffffffu, p[kt][0], sl0);
                    unsigned r1 = __shfl_sync(0xffffffffu, p[kt][1], sl0);
                    ap[0] = (t & 1) ? r1 : r0;
                    r0 = __shfl_sync(0xffffffffu, p[kt][0], sl2);
                    r1 = __shfl_sync(0xffffffffu, p[kt][1], sl2);
                    ap[2] = (t & 1) ? r1 : r0;
                    r0 = __shfl_sync(0xffffffffu, p[kt][2], sl0);
                    r1 = __shfl_sync(0xffffffffu, p[kt][3], sl0);
                    ap[1] = (t & 1) ? r1 : r0;
                    r0 = __shfl_sync(0xffffffffu, p[kt][2], sl2);
                    r1 = __shfl_sync(0xffffffffu, p[kt][3], sl2);
                    ap[3] = (t & 1) ? r1 : r0;
                }
                #pragma unroll
                for (int nd = 0; nd < 2; nd++) {
                    int vr = (nd*8 + g)*VSTR + jt*32 + kt*8 + t;
                    mma_tf32(oh[nd], ap, vh[vr], vh[vr + 4]);
                }
            }
        }
        float inv[2];
        #pragma unroll
        for (int h = 0; h < 2; h++) {
            float d = drow[h];
            d += __shfl_xor_sync(0xffffffffu, d, 1);
            d += __shfl_xor_sync(0xffffffffu, d, 2);
            inv[h] = 1.f / d;
        }
        #pragma unroll
        for (int nd = 0; nd < 2; nd++) {
            oall[head][nd][0] = oh[nd][0]*inv[0];
            oall[head][nd][1] = oh[nd][1]*inv[0];
            oall[head][nd][2] = oh[nd][2]*inv[1];
            oall[head][nd][3] = oh[nd][3]*inv[1];
        }
    }
    __syncthreads();   // barrier C: wo visible

    {
        float acc[8][4];
        #pragma unroll
        for (int nt = 0; nt < 8; nt++)
            #pragma unroll
            for (int i = 0; i < 4; i++) acc[nt][i] = 0.f;
        #pragma unroll
        for (int kt = 0; kt < 8; kt++) {
            int head = kt >> 1, nd = kt & 1;
            unsigned ao[4];
            c2a(oall[head][nd], t, sl0, sl2, 1.f, ao);
            #pragma unroll
            for (int nt = 0; nt < 8; nt++) {
                uint2 bw = *(const uint2*)&ws[((nt*8 + g)*36 + kt*4 + t)*2];
                mma_tf32(acc[nt], ao, bw.x, bw.y);
            }
        }
        size_t row0 = (size_t)bn * LL;
        #pragma unroll
        for (int nt = 0; nt < 8; nt++) {
            int row = warp*16 + g, col = nt*8 + 2*t;
            size_t a0 = (row0 + row)*CC + col;
            size_t a1 = (row0 + row + 8)*CC + col;
            float2 t0 = *(const float2*)&g_t[a0];
            float2 t1 = *(const float2*)&g_t[a1];
            float2 w0; w0.x = acc[nt][0] + t0.x; w0.y = acc[nt][1] + t0.y;
            float2 w1; w1.x = acc[nt][2] + t1.x; w1.y = acc[nt][3] + t1.y;
            *(float2*)&g_o[a0] = w0;
            *(float2*)&g_o[a1] = w1;
        }
    }
}

// ---------------- K4: patch_reverse gather + LN2 + fc1 + GELU -------------
// block = one image row (256 pixels), 512 thr. Gathers xs from g_o directly
// (replaces k3b), writes g_xs for the kB residual, then LN2+fc1+GELU.
__global__ __launch_bounds__(512) void k4(const float* __restrict__ g2,
                                          const float* __restrict__ b2,
                                          const float* __restrict__ fc1w,
                                          const float* __restrict__ fc1b)
{
    extern __shared__ float sm4[];
    float*    xsm = sm4;                        // 256*68
    unsigned* fw  = (unsigned*)(sm4 + 256*68);  // 128 j x 36 pairs x 2 = 9216 words
    int tid = threadIdx.x;
    size_t pix0 = (size_t)blockIdx.x * 256;
    int b4   = (int)(pix0 >> 16);
    int rrow = (int)((pix0 & 65535) >> 8);

    // gather + div (ex-k3b), store to smem and g_xs
    {
        int hc = d_cov_cnt[rrow];
        float idr = d_invdiv[rrow];
        for (int idx = tid; idx < 4096; idx += 512) {
            int row = idx >> 4, c4 = (idx & 15) * 4;   // row = w coordinate
            float4 a4; a4.x = 0.f; a4.y = 0.f; a4.z = 0.f; a4.w = 0.f;
            int wc2 = d_cov_cnt[row];
            for (int i = 0; i < hc; i++) {
                int n0 = d_cov_p[rrow][i]*NHP, l0 = d_cov_o[rrow][i]*PP;
                for (int k = 0; k < wc2; k++) {
                    int n = n0 + d_cov_p[row][k];
                    int l = l0 + d_cov_o[row][k];
                    float4 v = *(const float4*)&g_o[(((size_t)(b4*NPAT + n))*LL + l)*CC + c4];
                    a4.x += v.x; a4.y += v.y; a4.z += v.z; a4.w += v.w;
                }
            }
            float sc = idr * d_invdiv[row];
            a4.x *= sc; a4.y *= sc; a4.z *= sc; a4.w *= sc;
            *(float4*)&xsm[row*68 + c4] = a4;
            *(float4*)&g_xs[(pix0 + row)*CC + c4] = a4;
        }
    }
    for (int idx = tid; idx < 8192; idx += 512) {
        int c = idx >> 7, j = idx & 127;
        int kt = c >> 3, r = c & 7, tt = r & 3, hi = r >> 2;
        fw[(j*36 + kt*4 + tt)*2 + hi] = f2tf(fc1w[idx]);
    }
    __syncthreads();

    int lane = tid & 31, warp = tid >> 5;
    float ga = g2[lane], gb = g2[lane+32], ba = b2[lane], bbv = b2[lane+32];
    for (int r = warp; r < 256; r += 16) {
        float v0 = xsm[r*68+lane], v1 = xsm[r*68+lane+32];
        float s = v0+v1, ss = v0*v0+v1*v1;
        #pragma unroll
        for (int o = 16; o; o >>= 1) {
            s  += __shfl_xor_sync(0xffffffffu, s,  o);
            ss += __shfl_xor_sync(0xffffffffu, ss, o);
        }
        float mean = s * (1.f/64.f);
        float var  = ss * (1.f/64.f) - mean*mean;
        float rstd = rsqrtf(var + 1e-5f);
        xsm[r*68+lane]    = __uint_as_float(f2tf((v0 - mean) * rstd * ga + ba));
        xsm[r*68+lane+32] = __uint_as_float(f2tf((v1 - mean) * rstd * gb + bbv));
    }
    __syncthreads();

    const unsigned* hs = (const unsigned*)xsm;
    int g = lane >> 2, t = lane & 3;
    int r0 = (warp*16 + g)*68;
    unsigned aq[8][4];
    #pragma unroll
    for (int kt = 0; kt < 8; kt++) {
        int c0 = kt*8 + t;
        aq[kt][0] = hs[r0 + c0];
        aq[kt][1] = hs[r0 + 544 + c0];
        aq[kt][2] = hs[r0 + c0 + 4];
        aq[kt][3] = hs[r0 + 544 + c0 + 4];
    }
    float acc[16][4];
    #pragma unroll
    for (int nt = 0; nt < 16; nt++) {
        float2 bb = *(const float2*)&fc1b[nt*8 + 2*t];
        acc[nt][0] = bb.x; acc[nt][1] = bb.y; acc[nt][2] = bb.x; acc[nt][3] = bb.y;
    }
    #pragma unroll
    for (int nt = 0; nt < 16; nt++)
        #pragma unroll
        for (int kt = 0; kt < 8; kt++) {
            uint2 b = *(const uint2*)&fw[((nt*8 + g)*36 + kt*4 + t)*2];
            mma_tf32(acc[nt], aq[kt], b.x, b.y);
        }
    #pragma unroll
    for (int nt = 0; nt < 16; nt++) {
        int row = warp*16 + g, col = nt*8 + 2*t;
        __half2 h0 = __floats2half2_rn(gelu(acc[nt][0]), gelu(acc[nt][1]));
        __half2 h1 = __floats2half2_rn(gelu(acc[nt][2]), gelu(acc[nt][3]));
        *(__half2*)&g_h1[(pix0 + row)*MLP + col]     = h0;
        *(__half2*)&g_h1[(pix0 + row + 8)*MLP + col] = h1;
    }
}

// ---------------- kB: dwconv 5x5 + GELU + residual + fc2 + store ----------
// block = 16x16 spatial tile (512 blocks), 512 threads.
// smem: si (halo h1 fp16 [400][128] = 102400 B) -> reused as out tile f32 [64][260]
//       fsm (conv result fp16 [256][130] = 66560 B)
//       fw  (fc2w pair-layout tf32, 8704 words = 34816 B)
#define KB_SI_BYTES   102400
#define KB_FSM_BYTES  66560
#define KB_FW_BYTES   34816
#define KB_SMEM (KB_SI_BYTES + KB_FSM_BYTES + KB_FW_BYTES)
__global__ __launch_bounds__(512) void kB(const float* __restrict__ dww,
                                          const float* __restrict__ dwb,
                                          const float* __restrict__ fc2w,
                                          const float* __restrict__ fc2b,
                                          float* __restrict__ out)
{
    extern __shared__ char smB[];
    __half*   si  = (__half*)smB;
    __half*   fsm = (__half*)(smB + KB_SI_BYTES);
    unsigned* fw  = (unsigned*)(smB + KB_SI_BYTES + KB_FSM_BYTES);
    float*    tile = (float*)smB;            // overlay si (dead after conv)

    int tid = threadIdx.x;
    int bx = blockIdx.x;
    int b  = bx >> 8;
    int tr = (bx >> 4) & 15, tc = bx & 15;
    int r0 = tr*16, c0 = tc*16;

    // halo load: 400 pixels x 128 ch fp16, 16B vectors (zero-filled OOB)
    const uint4* h1v = (const uint4*)(g_h1 + (size_t)b * HWSZ * MLP);
    for (int idx = tid; idx < 400*16; idx += 512) {
        int p = idx >> 4, u = idx & 15;
        int hr = p / 20, hc = p % 20;
        int gr = r0 + hr - 2, gc = c0 + hc - 2;
        uint4 v = {0u, 0u, 0u, 0u};
        if (gr >= 0 && gr < 256 && gc >= 0 && gc < 256)
            v = h1v[(size_t)(gr*256 + gc)*16 + u];
        *(uint4*)&si[(size_t)p*128 + u*8] = v;
    }
    // fc2 weights -> pair layout
    for (int idx = tid; idx < 8192; idx += 512) {
        int c = idx >> 6, j = idx & 63;
        int kt = c >> 3, r = c & 7, tt = r & 3, hi = r >> 2;
        fw[(j*68 + kt*4 + tt)*2 + hi] = f2tf(fc2w[idx]);
    }
    __syncthreads();

    // conv: ch = tid&127, quarter = tid>>7 handles 4 tile rows
    {
        int ch = tid & 127, q = tid >> 7;
        float wreg[25];
        #pragma unroll
        for (int i = 0; i < 25; i++) wreg[i] = dww[ch*25 + i];
        float bias = dwb[ch];
        for (int r = q*4; r < q*4 + 4; r++) {
            #pragma unroll 1
            for (int half = 0; half < 2; half++) {
                int cb = half * 8;
                float val[5][12];
                #pragma unroll
                for (int dy = 0; dy < 5; dy++)
                    #pragma unroll
                    for (int xx = 0; xx < 12; xx++)
                        val[dy][xx] = __half2float(si[(size_t)((r+dy)*20 + cb + xx)*128 + ch]);
                #pragma unroll
                for (int k = 0; k < 8; k++) {
                    float acc = bias;
                    #pragma unroll
                    for (int dy = 0; dy < 5; dy++)
                        #pragma unroll
                        for (int dx = 0; dx < 5; dx++)
                            acc += val[dy][k + dx] * wreg[dy*5 + dx];
                    float center = val[2][k + 2];
                    fsm[(size_t)(r*16 + cb + k)*130 + ch] =
                        __float2half(center + gelu(acc));
                }
            }
        }
    }
    __syncthreads();

    // fc2 mma: 16 warps x 16 pixels, K=128
    int lane = tid & 31, w = tid >> 5, g = lane >> 2, t = lane & 3;
    {
        int rb = (w*16 + g)*130;
        unsigned aq[16][4];
        #pragma unroll
        for (int kt = 0; kt < 16; kt++) {
            int cc = kt*8 + t;
            aq[kt][0] = f2tf(__half2float(fsm[rb + cc]));
            aq[kt][1] = f2tf(__half2float(fsm[rb + 8*130 + cc]));
            aq[kt][2] = f2tf(__half2float(fsm[rb + cc + 4]));
            aq[kt][3] = f2tf(__half2float(fsm[rb + 8*130 + cc + 4]));
        }
        float acc[8][4];
        #pragma unroll
        for (int nt = 0; nt < 8; nt++)
            #pragma unroll
            for (int i = 0; i < 4; i++) acc[nt][i] = 0.f;
        #pragma unroll
        for (int nt = 0; nt < 8; nt++)
            #pragma unroll
            for (int kt = 0; kt < 16; kt++) {
                uint2 bw = *(const uint2*)&fw[((nt*8 + g)*68 + kt*4 + t)*2];
                mma_tf32(acc[nt], aq[kt], bw.x, bw.y);
            }
        // epilogue: bias + residual, write transposed out tile (overlay si)
        int p0 = w*16 + g;                 // pixel (tile row w, tile col g)
        int p1 = p0 + 8;                   // tile col g+8
        size_t hwb = (size_t)b*HWSZ + (size_t)(r0 + w)*256 + c0;
        #pragma unroll
        for (int nt = 0; nt < 8; nt++) {
            int col = nt*8 + 2*t;
            float2 bb = *(const float2*)&fc2b[col];
            float2 x0 = *(const float2*)&g_xs[(hwb + g)*CC + col];
            float2 x1 = *(const float2*)&g_xs[(hwb + g + 8)*CC + col];
            tile[(col  )*260 + p0] = acc[nt][0] + bb.x + x0.x;
            tile[(col+1)*260 + p0] = acc[nt][1] + bb.y + x0.y;
            tile[(col  )*260 + p1] = acc[nt][2] + bb.x + x1.x;
            tile[(col+1)*260 + p1] = acc[nt][3] + bb.y + x1.y;
        }
    }
    __syncthreads();

    // coalesced NCHW store: 64 ch x 16 rows x 16 cols
    for (int idx = tid; idx < 4096; idx += 512) {
        int c = idx >> 6, qq = idx & 63;
        int r = qq >> 2, x4 = (qq & 3) * 4;
        *(float4*)&out[((size_t)(b*CC + c))*HWSZ + (size_t)(r0 + r)*256 + c0 + x4] =
            *(const float4*)&tile[c*260 + r*16 + x4];
    }
}

// ---------------- launch ---------------------------------------------------
#define KA_SMEM ((17408 + 13824 + 17152) * 4)
#define K4_SMEM ((256*68 + 9216) * 4)

extern "C" void kernel_launch(void* const* d_in, const int* in_sizes, int n_in,
                              void* d_out, int out_size)
{
    const float* x    = (const float*)d_in[0];
    const float* ln1g = (const float*)d_in[1];
    const float* ln1b = (const float*)d_in[2];
    const float* wq   = (const float*)d_in[3];
    const float* wk   = (const float*)d_in[4];
    const float* wv   = (const float*)d_in[5];
    const float* wo   = (const float*)d_in[6];
    const float* ln2g = (const float*)d_in[7];
    const float* ln2b = (const float*)d_in[8];
    const float* fc1w = (const float*)d_in[9];
    const float* fc1b = (const float*)d_in[10];
    const float* dww  = (const float*)d_in[11];
    const float* dwb  = (const float*)d_in[12];
    const float* fc2w = (const float*)d_in[13];
    const float* fc2b = (const float*)d_in[14];
    float* out = (float*)d_out;

    static int s_attr = 0;
    if (!s_attr) {
        cudaFuncSetAttribute(kA, cudaFuncAttributeMaxDynamicSharedMemorySize, KA_SMEM);
        cudaFuncSetAttribute(k4, cudaFuncAttributeMaxDynamicSharedMemorySize, K4_SMEM);
        cudaFuncSetAttribute(kB, cudaFuncAttributeMaxDynamicSharedMemorySize, KB_SMEM);
        s_attr = 1;
    }

    k_init<<<1, 256>>>();
    kA<<<BN, 512, KA_SMEM>>>(x, ln1g, ln1b, wq, wk, wv, wo);
    k4<<<(BB*HWSZ)/256, 512, K4_SMEM>>>(ln2g, ln2b, fc1w, fc1b);
    kB<<<BB*256, 512, KB_SMEM>>>(dww, dwb, fc2w, fc2b, out);
}

// round 12
// speedup vs baseline: 3.8946x; 1.1161x over previous
#include <cuda_runtime.h>
#include <cuda_fp16.h>
#include <cuda_bf16.h>
#include <cstddef>

// ---------------- problem geometry (fixed by setup_inputs) ----------------
#define BB    2
#define CC    64
#define HH    256
#define WW    256
#define PP    16
#define STEP  14
#define NHP   19
#define NPAT  361
#define BN    722
#define LL    256
#define NHEAD 4
#define DHEAD 16
#define MLP   128
#define HWSZ  65536

#define QSCALE 0.36067376022224085f   // 0.25 * log2(e)

#define KSTR 264
#define VSH  272                      // V^T fp16 row stride in halves (136 words)
#define WMAT 4608                     // words per weight matrix in pair layout

// ---------------- scratch ----------
__device__ float g_t [(size_t)BN*LL*CC];
__device__ float g_o [(size_t)BN*LL*CC];
__device__ float g_xs[(size_t)BB*HWSZ*CC];
__device__ __half g_h1[(size_t)BB*HWSZ*MLP];

__device__ int   d_cov_cnt[256];
__device__ int   d_cov_p[256][2];
__device__ int   d_cov_o[256][2];
__device__ float d_invdiv[256];

__global__ void k_init()
{
    int r = threadIdx.x;
    if (r < 256) {
        int cnt = 0;
        for (int ph = 0; ph < NHP; ph++) {
            int top = min(STEP*ph, HH-PP);
            if (r >= top && r < top + PP && cnt < 2) {
                d_cov_p[r][cnt] = ph;
                d_cov_o[r][cnt] = r - top;
                cnt++;
            }
        }
        d_cov_cnt[r] = cnt;
    }
    if (threadIdx.x == 0) {
        float div[256];
        for (int i = 0; i < 256; i++) div[i] = 1.f;
        for (int i = STEP; i < HH + STEP - PP; i += STEP) {
            int top = (i + PP > HH) ? (HH - PP) : i;
            for (int r2 = top; r2 < i + PP - STEP; ++r2) div[r2] *= 2.f;
        }
        for (int i = 0; i < 256; i++) d_invdiv[i] = 1.f / div[i];
    }
}

// ---------------- mma helpers ---------------------------------------------
__device__ __forceinline__ unsigned f2tf(float x) {
    unsigned r; asm("cvt.rna.tf32.f32 %0, %1;" : "=r"(r) : "f"(x)); return r;
}
__device__ __forceinline__ float ex2(float x) {
    float r; asm("ex2.approx.ftz.f32 %0, %1;" : "=f"(r) : "f"(x)); return r;
}
__device__ __forceinline__ unsigned packh2(float x, float y) {
    __half2 h = __floats2half2_rn(x, y);
    return *(unsigned*)&h;
}
__device__ __forceinline__ void mma_tf32(float* d, const unsigned* a,
                                         unsigned b0, unsigned b1) {
    asm volatile("mma.sync.aligned.m16n8k8.row.col.f32.tf32.tf32.f32 "
        "{%0,%1,%2,%3},{%4,%5,%6,%7},{%8,%9},{%0,%1,%2,%3};"
        : "+f"(d[0]), "+f"(d[1]), "+f"(d[2]), "+f"(d[3])
        : "r"(a[0]), "r"(a[1]), "r"(a[2]), "r"(a[3]), "r"(b0), "r"(b1));
}
__device__ __forceinline__ void mma_f16(float* d, const unsigned* a,
                                        unsigned b0, unsigned b1) {
    asm volatile("mma.sync.aligned.m16n8k16.row.col.f32.f16.f16.f32 "
        "{%0,%1,%2,%3},{%4,%5,%6,%7},{%8,%9},{%0,%1,%2,%3};"
        : "+f"(d[0]), "+f"(d[1]), "+f"(d[2]), "+f"(d[3])
        : "r"(a[0]), "r"(a[1]), "r"(a[2]), "r"(a[3]), "r"(b0), "r"(b1));
}
__device__ __forceinline__ float gelu(float x) {
    return 0.5f * x * (1.f + erff(x * 0.70710678118654752f));
}
__device__ __forceinline__ void c2a(const float c[4], int t, int sl0, int sl2,
                                    float scale, unsigned a[4]) {
    float r0 = __shfl_sync(0xffffffffu, c[0], sl0);
    float r1 = __shfl_sync(0xffffffffu, c[1], sl0);
    float v0 = (t & 1) ? r1 : r0;
    r0 = __shfl_sync(0xffffffffu, c[0], sl2);
    r1 = __shfl_sync(0xffffffffu, c[1], sl2);
    float v2 = (t & 1) ? r1 : r0;
    r0 = __shfl_sync(0xffffffffu, c[2], sl0);
    r1 = __shfl_sync(0xffffffffu, c[3], sl0);
    float v1 = (t & 1) ? r1 : r0;
    r0 = __shfl_sync(0xffffffffu, c[2], sl2);
    r1 = __shfl_sync(0xffffffffu, c[3], sl2);
    float v3 = (t & 1) ? r1 : r0;
    a[0] = f2tf(v0 * scale); a[1] = f2tf(v1 * scale);
    a[2] = f2tf(v2 * scale); a[3] = f2tf(v3 * scale);
}
// frag-pair weight layout: pair index p = j*36 + kt*4 + t; words {2p,2p+1}
__device__ __forceinline__ void gemm64p(const unsigned aq[8][4],
                                        const unsigned* __restrict__ wsm,
                                        int g, int t, float acc[8][4]) {
    #pragma unroll
    for (int nt = 0; nt < 8; nt++)
        #pragma unroll
        for (int i = 0; i < 4; i++) acc[nt][i] = 0.f;
    #pragma unroll
    for (int nt = 0; nt < 8; nt++)
        #pragma unroll
        for (int kt = 0; kt < 8; kt++) {
            uint2 b = *(const uint2*)&wsm[((nt*8 + g)*36 + kt*4 + t)*2];
            mma_tf32(acc[nt], aq[kt], b.x, b.y);
        }
}

// ---------------- kA: gather + LN1 + QKV + attention + o@wo + t -----------
// block = patch (722), 512 thr = 16 warps. smem 156 KB:
//   ps  : 256*68 fp32 (patch -> h tf32)   -> reused as K^T (tf32)
//   ws  : 3 mats x WMAT words; mat-0 slot reused for wo
//   vsm : V^T fp16 [64 d][VSH tokens]
__global__ __launch_bounds__(512) void kA(const float* __restrict__ x,
                                          const float* __restrict__ g1,
                                          const float* __restrict__ b1,
                                          const float* __restrict__ wq,
                                          const float* __restrict__ wk,
                                          const float* __restrict__ wv,
                                          const float* __restrict__ wo)
{
    extern __shared__ float sm[];
    float*    ps    = sm;                               // 17408 words
    unsigned* ws    = (unsigned*)(sm + 17408);          // 13824 words (3*WMAT)
    __half*   vsm_h = (__half*)(sm + 17408 + 13824);    // 64*VSH halves = 8704 words
    unsigned* ksm   = (unsigned*)ps;

    int tid = threadIdx.x;
    int bn = blockIdx.x;
    int b  = bn / NPAT, n = bn % NPAT;
    int ph = n / NHP,   pw = n % NHP;
    int top  = min(STEP*ph, HH-PP);
    int left = min(STEP*pw, WW-PP);
    const float* xb = x + (size_t)b * CC * HWSZ;

    for (int idx = tid; idx < 3*64*64; idx += 512) {
        int mat = idx >> 12; int rem = idx & 4095;
        int c = rem >> 6, j = rem & 63;
        const float* w = (mat == 0) ? wq : (mat == 1) ? wk : wv;
        int kt = c >> 3, r = c & 7, tt = r & 3, hi = r >> 2;
        ws[mat*WMAT + (j*36 + kt*4 + tt)*2 + hi] = f2tf(w[rem]);
    }
    for (int idx = tid; idx < CC*LL; idx += 512) {
        int c = idx >> 8, l = idx & 255;
        int li = l >> 4, lj = l & 15;
        ps[l*68 + c] = xb[(size_t)c*HWSZ + (size_t)(top+li)*WW + (left+lj)];
    }
    __syncthreads();

    int lane = tid & 31, warp = tid >> 5;
    {
        float ga = g1[lane], gb = g1[lane+32], ba = b1[lane], bbv = b1[lane+32];
        for (int l = warp; l < LL; l += 16) {
            float v0 = ps[l*68 + lane], v1 = ps[l*68 + lane + 32];
            size_t tb = ((size_t)bn*LL + l) * CC;
            g_t[tb + lane] = v0;  g_t[tb + lane + 32] = v1;
            float s = v0 + v1, ss = v0*v0 + v1*v1;
            #pragma unroll
            for (int o = 16; o; o >>= 1) {
                s  += __shfl_xor_sync(0xffffffffu, s,  o);
                ss += __shfl_xor_sync(0xffffffffu, ss, o);
            }
            float mean = s * (1.f/64.f);
            float var  = ss * (1.f/64.f) - mean*mean;
            float rstd = rsqrtf(var + 1e-5f);
            ps[l*68 + lane]      = __uint_as_float(f2tf((v0 - mean) * rstd * ga + ba));
            ps[l*68 + lane + 32] = __uint_as_float(f2tf((v1 - mean) * rstd * gb + bbv));
        }
    }
    __syncthreads();

    const unsigned* hs = (const unsigned*)ps;
    int g = lane >> 2, t = lane & 3;
    unsigned aq[8][4];
    {
        int r0 = (warp*16 + g)*68;
        #pragma unroll
        for (int kt = 0; kt < 8; kt++) {
            int c0 = kt*8 + t;
            aq[kt][0] = hs[r0 + c0];
            aq[kt][1] = hs[r0 + 544 + c0];
            aq[kt][2] = hs[r0 + c0 + 4];
            aq[kt][3] = hs[r0 + 544 + c0 + 4];
        }
    }
    __syncthreads();   // barrier A: ps free (becomes K^T)

    {
        float acc[8][4];
        gemm64p(aq, ws + WMAT, g, t, acc);       // K (mat 1) -> tf32 K^T
        #pragma unroll
        for (int nt = 0; nt < 8; nt++) {
            int tok = warp*16 + g;
            int hd  = nt >> 1;
            int d0  = (nt & 1)*8 + 2*t;
            unsigned* kp = ksm + (hd*16 + d0)*KSTR;
            kp[tok]            = f2tf(acc[nt][0]);
            kp[KSTR + tok]     = f2tf(acc[nt][1]);
            kp[tok + 8]        = f2tf(acc[nt][2]);
            kp[KSTR + tok + 8] = f2tf(acc[nt][3]);
        }
        gemm64p(aq, ws + 2*WMAT, g, t, acc);     // V (mat 2) -> fp16 V^T [d][tok]
        #pragma unroll
        for (int nt = 0; nt < 8; nt++) {
            int tok = warp*16 + g;
            int d0  = nt*8 + 2*t;                // global d (head*16 + local)
            __half* vp = vsm_h + (size_t)d0*VSH;
            vp[tok]           = __float2half(acc[nt][0]);
            vp[VSH + tok]     = __float2half(acc[nt][1]);
            vp[tok + 8]       = __float2half(acc[nt][2]);
            vp[VSH + tok + 8] = __float2half(acc[nt][3]);
        }
    }
    float qacc[8][4];
    gemm64p(aq, ws, g, t, qacc);                 // Q (mat 0, registers)
    __syncthreads();   // barrier B: K/V visible; ws mat-0 writable

    for (int idx = tid; idx < 4096; idx += 512) {
        int c = idx >> 6, j = idx & 63;
        int kt = c >> 3, r = c & 7, tt = r & 3, hi = r >> 2;
        ws[(j*36 + kt*4 + tt)*2 + hi] = f2tf(wo[idx]);
    }

    int sl0 = (lane & ~3) + (t >> 1);
    int sl2 = sl0 + 2;
    float oall[4][2][4];
    #pragma unroll
    for (int head = 0; head < NHEAD; head++) {
        unsigned aqh[2][4];
        #pragma unroll
        for (int kt = 0; kt < 2; kt++)
            c2a(qacc[head*2 + kt], t, sl0, sl2, QSCALE, aqh[kt]);

        const unsigned* kh = ksm + head*16*KSTR;
        const __half*   vh = vsm_h + (size_t)head*16*VSH;
        float oh[2][4];
        #pragma unroll
        for (int nd = 0; nd < 2; nd++)
            #pragma unroll
            for (int i = 0; i < 4; i++) oh[nd][i] = 0.f;
        float mrow[2] = {-1e30f, -1e30f};
        float drow[2] = {0.f, 0.f};

        #pragma unroll 1
        for (int jt = 0; jt < 8; jt++) {
            float s[4][4];
            #pragma unroll
            for (int nt = 0; nt < 4; nt++)
                #pragma unroll
                for (int i = 0; i < 4; i++) s[nt][i] = 0.f;
            #pragma unroll
            for (int nt = 0; nt < 4; nt++)
                #pragma unroll
                for (int kt = 0; kt < 2; kt++) {
                    int jr = (kt*8 + t)*KSTR + jt*32 + nt*8 + g;
                    mma_tf32(s[nt], aqh[kt], kh[jr], kh[jr + 4*KSTR]);
                }
            #pragma unroll
            for (int h = 0; h < 2; h++) {
                float mx = fmaxf(s[0][h*2], s[0][h*2+1]);
                #pragma unroll
                for (int nt = 1; nt < 4; nt++)
                    mx = fmaxf(mx, fmaxf(s[nt][h*2], s[nt][h*2+1]));
                mx = fmaxf(mx, __shfl_xor_sync(0xffffffffu, mx, 1));
                mx = fmaxf(mx, __shfl_xor_sync(0xffffffffu, mx, 2));
                float mn = fmaxf(mrow[h], mx);
                float scale = ex2(mrow[h] - mn);
                mrow[h] = mn;
                drow[h] *= scale;
                #pragma unroll
                for (int nd = 0; nd < 2; nd++) {
                    oh[nd][h*2]   *= scale;
                    oh[nd][h*2+1] *= scale;
                }
                float psum = 0.f;
                #pragma unroll
                for (int nt = 0; nt < 4; nt++) {
                    float e0 = ex2(s[nt][h*2]   - mn);
                    float e1 = ex2(s[nt][h*2+1] - mn);
                    s[nt][h*2] = e0; s[nt][h*2+1] = e1;
                    psum += e0 + e1;
                }
                drow[h] += psum;
            }
            // pack P (C-layout == fp16 A-layout; no shuffles)
            unsigned pa[2][4];
            #pragma unroll
            for (int kc = 0; kc < 2; kc++) {
                pa[kc][0] = packh2(s[2*kc  ][0], s[2*kc  ][1]);
                pa[kc][1] = packh2(s[2*kc  ][2], s[2*kc  ][3]);
                pa[kc][2] = packh2(s[2*kc+1][0], s[2*kc+1][1]);
                pa[kc][3] = packh2(s[2*kc+1][2], s[2*kc+1][3]);
            }
            #pragma unroll
            for (int nd = 0; nd < 2; nd++) {
                #pragma unroll
                for (int kc = 0; kc < 2; kc++) {
                    const __half* vb = vh + (size_t)(nd*8 + g)*VSH + jt*32 + kc*16;
                    unsigned b0 = *(const unsigned*)&vb[2*t];
                    unsigned b1 = *(const unsigned*)&vb[2*t + 8];
                    mma_f16(oh[nd], pa[kc], b0, b1);
                }
            }
        }
        float inv[2];
        #pragma unroll
        for (int h = 0; h < 2; h++) {
            float d = drow[h];
            d += __shfl_xor_sync(0xffffffffu, d, 1);
            d += __shfl_xor_sync(0xffffffffu, d, 2);
            inv[h] = 1.f / d;
        }
        #pragma unroll
        for (int nd = 0; nd < 2; nd++) {
            oall[head][nd][0] = oh[nd][0]*inv[0];
            oall[head][nd][1] = oh[nd][1]*inv[0];
            oall[head][nd][2] = oh[nd][2]*inv[1];
            oall[head][nd][3] = oh[nd][3]*inv[1];
        }
    }
    __syncthreads();   // barrier C: wo visible

    {
        float acc[8][4];
        #pragma unroll
        for (int nt = 0; nt < 8; nt++)
            #pragma unroll
            for (int i = 0; i < 4; i++) acc[nt][i] = 0.f;
        #pragma unroll
        for (int kt = 0; kt < 8; kt++) {
            int head = kt >> 1, nd = kt & 1;
            unsigned ao[4];
            c2a(oall[head][nd], t, sl0, sl2, 1.f, ao);
            #pragma unroll
            for (int nt = 0; nt < 8; nt++) {
                uint2 bw = *(const uint2*)&ws[((nt*8 + g)*36 + kt*4 + t)*2];
                mma_tf32(acc[nt], ao, bw.x, bw.y);
            }
        }
        size_t row0 = (size_t)bn * LL;
        #pragma unroll
        for (int nt = 0; nt < 8; nt++) {
            int row = warp*16 + g, col = nt*8 + 2*t;
            size_t a0 = (row0 + row)*CC + col;
            size_t a1 = (row0 + row + 8)*CC + col;
            float2 t0 = *(const float2*)&g_t[a0];
            float2 t1 = *(const float2*)&g_t[a1];
            float2 w0; w0.x = acc[nt][0] + t0.x; w0.y = acc[nt][1] + t0.y;
            float2 w1; w1.x = acc[nt][2] + t1.x; w1.y = acc[nt][3] + t1.y;
            *(float2*)&g_o[a0] = w0;
            *(float2*)&g_o[a1] = w1;
        }
    }
}

// ---------------- K4: patch_reverse gather + LN2 + fc1 + GELU -------------
__global__ __launch_bounds__(512) void k4(const float* __restrict__ g2,
                                          const float* __restrict__ b2,
                                          const float* __restrict__ fc1w,
                                          const float* __restrict__ fc1b)
{
    extern __shared__ float sm4[];
    float*    xsm = sm4;                        // 256*68
    unsigned* fw  = (unsigned*)(sm4 + 256*68);  // 9216 words
    int tid = threadIdx.x;
    size_t pix0 = (size_t)blockIdx.x * 256;
    int b4   = (int)(pix0 >> 16);
    int rrow = (int)((pix0 & 65535) >> 8);

    {
        int hc = d_cov_cnt[rrow];
        float idr = d_invdiv[rrow];
        for (int idx = tid; idx < 4096; idx += 512) {
            int row = idx >> 4, c4 = (idx & 15) * 4;
            float4 a4; a4.x = 0.f; a4.y = 0.f; a4.z = 0.f; a4.w = 0.f;
            int wc2 = d_cov_cnt[row];
            for (int i = 0; i < hc; i++) {
                int n0 = d_cov_p[rrow][i]*NHP, l0 = d_cov_o[rrow][i]*PP;
                for (int k = 0; k < wc2; k++) {
                    int n = n0 + d_cov_p[row][k];
                    int l = l0 + d_cov_o[row][k];
                    float4 v = *(const float4*)&g_o[(((size_t)(b4*NPAT + n))*LL + l)*CC + c4];
                    a4.x += v.x; a4.y += v.y; a4.z += v.z; a4.w += v.w;
                }
            }
            float sc = idr * d_invdiv[row];
            a4.x *= sc; a4.y *= sc; a4.z *= sc; a4.w *= sc;
            *(float4*)&xsm[row*68 + c4] = a4;
            *(float4*)&g_xs[(pix0 + row)*CC + c4] = a4;
        }
    }
    for (int idx = tid; idx < 8192; idx += 512) {
        int c = idx >> 7, j = idx & 127;
        int kt = c >> 3, r = c & 7, tt = r & 3, hi = r >> 2;
        fw[(j*36 + kt*4 + tt)*2 + hi] = f2tf(fc1w[idx]);
    }
    __syncthreads();

    int lane = tid & 31, warp = tid >> 5;
    float ga = g2[lane], gb = g2[lane+32], ba = b2[lane], bbv = b2[lane+32];
    for (int r = warp; r < 256; r += 16) {
        float v0 = xsm[r*68+lane], v1 = xsm[r*68+lane+32];
        float s = v0+v1, ss = v0*v0+v1*v1;
        #pragma unroll
        for (int o = 16; o; o >>= 1) {
            s  += __shfl_xor_sync(0xffffffffu, s,  o);
            ss += __shfl_xor_sync(0xffffffffu, ss, o);
        }
        float mean = s * (1.f/64.f);
        float var  = ss * (1.f/64.f) - mean*mean;
        float rstd = rsqrtf(var + 1e-5f);
        xsm[r*68+lane]    = __uint_as_float(f2tf((v0 - mean) * rstd * ga + ba));
        xsm[r*68+lane+32] = __uint_as_float(f2tf((v1 - mean) * rstd * gb + bbv));
    }
    __syncthreads();

    const unsigned* hs = (const unsigned*)xsm;
    int g = lane >> 2, t = lane & 3;
    int r0 = (warp*16 + g)*68;
    unsigned aq[8][4];
    #pragma unroll
    for (int kt = 0; kt < 8; kt++) {
        int c0 = kt*8 + t;
        aq[kt][0] = hs[r0 + c0];
        aq[kt][1] = hs[r0 + 544 + c0];
        aq[kt][2] = hs[r0 + c0 + 4];
        aq[kt][3] = hs[r0 + 544 + c0 + 4];
    }
    float acc[16][4];
    #pragma unroll
    for (int nt = 0; nt < 16; nt++) {
        float2 bb = *(const float2*)&fc1b[nt*8 + 2*t];
        acc[nt][0] = bb.x; acc[nt][1] = bb.y; acc[nt][2] = bb.x; acc[nt][3] = bb.y;
    }
    #pragma unroll
    for (int nt = 0; nt < 16; nt++)
        #pragma unroll
        for (int kt = 0; kt < 8; kt++) {
            uint2 b = *(const uint2*)&fw[((nt*8 + g)*36 + kt*4 + t)*2];
            mma_tf32(acc[nt], aq[kt], b.x, b.y);
        }
    #pragma unroll
    for (int nt = 0; nt < 16; nt++) {
        int row = warp*16 + g, col = nt*8 + 2*t;
        __half2 h0 = __floats2half2_rn(gelu(acc[nt][0]), gelu(acc[nt][1]));
        __half2 h1 = __floats2half2_rn(gelu(acc[nt][2]), gelu(acc[nt][3]));
        *(__half2*)&g_h1[(pix0 + row)*MLP + col]     = h0;
        *(__half2*)&g_h1[(pix0 + row + 8)*MLP + col] = h1;
    }
}

// ---------------- kB: dwconv 5x5 + GELU + residual + fc2 + store ----------
// block = 8x8 spatial tile (2048 blocks), 256 threads. smem 88.3 KB -> 2 blk/SM.
//   si  : halo h1 fp16 [144 px][128]  (36864 B) -> reused as out tile f32 [64][68]
//   fsm : conv result fp16 [64 px][130] (16640 B)
//   fw  : fc2w pair-layout tf32 (34816 B)
#define KB_SI_BYTES   36864
#define KB_FSM_BYTES  16640
#define KB_FW_BYTES   34816
#define KB_SMEM (KB_SI_BYTES + KB_FSM_BYTES + KB_FW_BYTES)
__global__ __launch_bounds__(256) void kB(const float* __restrict__ dww,
                                          const float* __restrict__ dwb,
                                          const float* __restrict__ fc2w,
                                          const float* __restrict__ fc2b,
                                          float* __restrict__ out)
{
    extern __shared__ char smB[];
    __half*   si  = (__half*)smB;
    __half*   fsm = (__half*)(smB + KB_SI_BYTES);
    unsigned* fw  = (unsigned*)(smB + KB_SI_BYTES + KB_FSM_BYTES);
    float*    tile = (float*)smB;            // overlay si (dead after conv)

    int tid = threadIdx.x;
    int bx = blockIdx.x;
    int b  = bx >> 10;
    int tr = (bx >> 5) & 31, tc = bx & 31;
    int r0 = tr*8, c0 = tc*8;

    // halo load: 144 pixels (12x12) x 128 ch fp16 (zero-filled OOB)
    const uint4* h1v = (const uint4*)(g_h1 + (size_t)b * HWSZ * MLP);
    for (int idx = tid; idx < 144*16; idx += 256) {
        int p = idx >> 4, u = idx & 15;
        int hr = p / 12, hc = p % 12;
        int gr = r0 + hr - 2, gc = c0 + hc - 2;
        uint4 v = {0u, 0u, 0u, 0u};
        if (gr >= 0 && gr < 256 && gc >= 0 && gc < 256)
            v = h1v[(size_t)(gr*256 + gc)*16 + u];
        *(uint4*)&si[(size_t)p*128 + u*8] = v;
    }
    for (int idx = tid; idx < 8192; idx += 256) {
        int c = idx >> 6, j = idx & 63;
        int kt = c >> 3, r = c & 7, tt = r & 3, hi = r >> 2;
        fw[(j*68 + kt*4 + tt)*2 + hi] = f2tf(fc2w[idx]);
    }
    __syncthreads();

    // conv: ch = tid&127, q = tid>>7 handles 4 tile rows (8 total)
    {
        int ch = tid & 127, q = tid >> 7;
        float wreg[25];
        #pragma unroll
        for (int i = 0; i < 25; i++) wreg[i] = dww[ch*25 + i];
        float bias = dwb[ch];
        for (int r = q*4; r < q*4 + 4; r++) {
            float val[5][12];
            #pragma unroll
            for (int dy = 0; dy < 5; dy++)
                #pragma unroll
                for (int xx = 0; xx < 12; xx++)
                    val[dy][xx] = __half2float(si[(size_t)((r+dy)*12 + xx)*128 + ch]);
            #pragma unroll
            for (int k = 0; k < 8; k++) {
                float acc = bias;
                #pragma unroll
                for (int dy = 0; dy < 5; dy++)
                    #pragma unroll
                    for (int dx = 0; dx < 5; dx++)
                        acc += val[dy][k + dx] * wreg[dy*5 + dx];
                float center = val[2][k + 2];
                fsm[(size_t)(r*8 + k)*130 + ch] = __float2half(center + gelu(acc));
            }
        }
    }
    __syncthreads();

    // fc2 mma: 8 warps; warp = (mt = w>>1: 16 pixels, nh = w&1: 32 cols), K=128
    int lane = tid & 31, w = tid >> 5, g = lane >> 2, t = lane & 3;
    {
        int mt = w >> 1, nh = w & 1;
        int rb = (mt*16 + g)*130;
        unsigned aq[16][4];
        #pragma unroll
        for (int kt = 0; kt < 16; kt++) {
            int cc = kt*8 + t;
            aq[kt][0] = f2tf(__half2float(fsm[rb + cc]));
            aq[kt][1] = f2tf(__half2float(fsm[rb + 8*130 + cc]));
            aq[kt][2] = f2tf(__half2float(fsm[rb + cc + 4]));
            aq[kt][3] = f2tf(__half2float(fsm[rb + 8*130 + cc + 4]));
        }
        float acc[4][4];
        #pragma unroll
        for (int nt = 0; nt < 4; nt++)
            #pragma unroll
            for (int i = 0; i < 4; i++) acc[nt][i] = 0.f;
        #pragma unroll
        for (int nt = 0; nt < 4; nt++)
            #pragma unroll
            for (int kt = 0; kt < 16; kt++) {
                uint2 bw = *(const uint2*)&fw[((nh*32 + nt*8 + g)*68 + kt*4 + t)*2];
                mma_tf32(acc[nt], aq[kt], bw.x, bw.y);
            }
        __syncthreads();   // fsm consumed; si overlay becomes out tile
        int p0 = mt*16 + g, p1 = p0 + 8;
        int rr0 = p0 >> 3, kk0 = p0 & 7;
        int rr1 = p1 >> 3, kk1 = p1 & 7;
        size_t base = (size_t)b*HWSZ;
        #pragma unroll
        for (int nt = 0; nt < 4; nt++) {
            int col = nh*32 + nt*8 + 2*t;
            float2 bb = *(const float2*)&fc2b[col];
            float2 x0 = *(const float2*)&g_xs[(base + (size_t)(r0+rr0)*256 + c0 + kk0)*CC + col];
            float2 x1 = *(const float2*)&g_xs[(base + (size_t)(r0+rr1)*256 + c0 + kk1)*CC + col];
            tile[(col  )*68 + p0] = acc[nt][0] + bb.x + x0.x;
            tile[(col+1)*68 + p0] = acc[nt][1] + bb.y + x0.y;
            tile[(col  )*68 + p1] = acc[nt][2] + bb.x + x1.x;
            tile[(col+1)*68 + p1] = acc[nt][3] + bb.y + x1.y;
        }
    }
    __syncthreads();

    // NCHW store: 64 ch x 8 rows x 8 cols (float2)
    for (int idx = tid; idx < 2048; idx += 256) {
        int c = idx >> 5, pp = idx & 31;
        int r = pp >> 2, k2 = (pp & 3) * 2;
        *(float2*)&out[((size_t)(b*CC + c))*HWSZ + (size_t)(r0 + r)*256 + c0 + k2] =
            *(const float2*)&tile[c*68 + r*8 + k2];
    }
}

// ---------------- launch ---------------------------------------------------
#define KA_SMEM ((17408 + 13824 + 8704) * 4)
#define K4_SMEM ((256*68 + 9216) * 4)

extern "C" void kernel_launch(void* const* d_in, const int* in_sizes, int n_in,
                              void* d_out, int out_size)
{
    const float* x    = (const float*)d_in[0];
    const float* ln1g = (const float*)d_in[1];
    const float* ln1b = (const float*)d_in[2];
    const float* wq   = (const float*)d_in[3];
    const float* wk   = (const float*)d_in[4];
    const float* wv   = (const float*)d_in[5];
    const float* wo   = (const float*)d_in[6];
    const float* ln2g = (const float*)d_in[7];
    const float* ln2b = (const float*)d_in[8];
    const float* fc1w = (const float*)d_in[9];
    const float* fc1b = (const float*)d_in[10];
    const float* dww  = (const float*)d_in[11];
    const float* dwb  = (const float*)d_in[12];
    const float* fc2w = (const float*)d_in[13];
    const float* fc2b = (const float*)d_in[14];
    float* out = (float*)d_out;

    static int s_attr = 0;
    if (!s_attr) {
        cudaFuncSetAttribute(kA, cudaFuncAttributeMaxDynamicSharedMemorySize, KA_SMEM);
        cudaFuncSetAttribute(k4, cudaFuncAttributeMaxDynamicSharedMemorySize, K4_SMEM);
        cudaFuncSetAttribute(kB, cudaFuncAttributeMaxDynamicSharedMemorySize, KB_SMEM);
        s_attr = 1;
    }

    k_init<<<1, 256>>>();
    kA<<<BN, 512, KA_SMEM>>>(x, ln1g, ln1b, wq, wk, wv, wo);
    k4<<<(BB*HWSZ)/256, 512, K4_SMEM>>>(ln2g, ln2b, fc1w, fc1b);
    kB<<<BB*1024, 256, KB_SMEM>>>(dww, dwb, fc2w, fc2b, out);
}

// round 13
// speedup vs baseline: 4.1594x; 1.0680x over previous
#include <cuda_runtime.h>
#include <cuda_fp16.h>
#include <cuda_bf16.h>
#include <cstddef>

// ---------------- problem geometry (fixed by setup_inputs) ----------------
#define BB    2
#define CC    64
#define HH    256
#define WW    256
#define PP    16
#define STEP  14
#define NHP   19
#define NPAT  361
#define BN    722
#define LL    256
#define NHEAD 4
#define DHEAD 16
#define MLP   128
#define HWSZ  65536

#define QSCALE 0.36067376022224085f   // 0.25 * log2(e)

#define KSH  24                       // K fp16 row stride (halves): bank-clean
#define VSH  272                      // V^T fp16 row stride (halves)
#define WMAT 4608                     // words per weight matrix in pair layout

// ---------------- scratch ----------
__device__ float g_t [(size_t)BN*LL*CC];
__device__ float g_o [(size_t)BN*LL*CC];
__device__ float g_xs[(size_t)BB*HWSZ*CC];
__device__ __half g_h1[(size_t)BB*HWSZ*MLP];

__device__ int   d_cov_cnt[256];
__device__ int   d_cov_p[256][2];
__device__ int   d_cov_o[256][2];
__device__ float d_invdiv[256];

__global__ void k_init()
{
    int r = threadIdx.x;
    if (r < 256) {
        int cnt = 0;
        for (int ph = 0; ph < NHP; ph++) {
            int top = min(STEP*ph, HH-PP);
            if (r >= top && r < top + PP && cnt < 2) {
                d_cov_p[r][cnt] = ph;
                d_cov_o[r][cnt] = r - top;
                cnt++;
            }
        }
        d_cov_cnt[r] = cnt;
    }
    if (threadIdx.x == 0) {
        float div[256];
        for (int i = 0; i < 256; i++) div[i] = 1.f;
        for (int i = STEP; i < HH + STEP - PP; i += STEP) {
            int top = (i + PP > HH) ? (HH - PP) : i;
            for (int r2 = top; r2 < i + PP - STEP; ++r2) div[r2] *= 2.f;
        }
        for (int i = 0; i < 256; i++) d_invdiv[i] = 1.f / div[i];
    }
}

// ---------------- mma helpers ---------------------------------------------
__device__ __forceinline__ unsigned f2tf(float x) {
    unsigned r; asm("cvt.rna.tf32.f32 %0, %1;" : "=r"(r) : "f"(x)); return r;
}
__device__ __forceinline__ float ex2(float x) {
    float r; asm("ex2.approx.ftz.f32 %0, %1;" : "=f"(r) : "f"(x)); return r;
}
__device__ __forceinline__ unsigned packh2(float x, float y) {
    __half2 h = __floats2half2_rn(x, y);
    return *(unsigned*)&h;
}
__device__ __forceinline__ void mma_tf32(float* d, const unsigned* a,
                                         unsigned b0, unsigned b1) {
    asm volatile("mma.sync.aligned.m16n8k8.row.col.f32.tf32.tf32.f32 "
        "{%0,%1,%2,%3},{%4,%5,%6,%7},{%8,%9},{%0,%1,%2,%3};"
        : "+f"(d[0]), "+f"(d[1]), "+f"(d[2]), "+f"(d[3])
        : "r"(a[0]), "r"(a[1]), "r"(a[2]), "r"(a[3]), "r"(b0), "r"(b1));
}
__device__ __forceinline__ void mma_f16(float* d, const unsigned* a,
                                        unsigned b0, unsigned b1) {
    asm volatile("mma.sync.aligned.m16n8k16.row.col.f32.f16.f16.f32 "
        "{%0,%1,%2,%3},{%4,%5,%6,%7},{%8,%9},{%0,%1,%2,%3};"
        : "+f"(d[0]), "+f"(d[1]), "+f"(d[2]), "+f"(d[3])
        : "r"(a[0]), "r"(a[1]), "r"(a[2]), "r"(a[3]), "r"(b0), "r"(b1));
}
__device__ __forceinline__ float gelu(float x) {
    return 0.5f * x * (1.f + erff(x * 0.70710678118654752f));
}
// frag-pair weight layout: pair index p = j*36 + kt*4 + t; words {2p,2p+1}
__device__ __forceinline__ void gemm64p(const unsigned aq[8][4],
                                        const unsigned* __restrict__ wsm,
                                        int g, int t, float acc[8][4]) {
    #pragma unroll
    for (int nt = 0; nt < 8; nt++)
        #pragma unroll
        for (int i = 0; i < 4; i++) acc[nt][i] = 0.f;
    #pragma unroll
    for (int nt = 0; nt < 8; nt++)
        #pragma unroll
        for (int kt = 0; kt < 8; kt++) {
            uint2 b = *(const uint2*)&wsm[((nt*8 + g)*36 + kt*4 + t)*2];
            mma_tf32(acc[nt], aq[kt], b.x, b.y);
        }
}

// ---------------- kA: gather + LN1 + QKV + attention + o@wo + t -----------
// block = patch (722), 512 thr = 16 warps. smem 156 KB:
//   ps  : 256*68 fp32 (patch -> h tf32)  -> reused as K fp16 [head][tok][KSH]
//   ws  : 3 mats x WMAT tf32; mat-0 slot reused for wo fp16 [j][72]
//   vsm : V^T fp16 [64 d][VSH tokens]
__global__ __launch_bounds__(512) void kA(const float* __restrict__ x,
                                          const float* __restrict__ g1,
                                          const float* __restrict__ b1,
                                          const float* __restrict__ wq,
                                          const float* __restrict__ wk,
                                          const float* __restrict__ wv,
                                          const float* __restrict__ wo)
{
    extern __shared__ float sm[];
    float*    ps    = sm;                               // 17408 words
    unsigned* ws    = (unsigned*)(sm + 17408);          // 13824 words (3*WMAT)
    __half*   vsm_h = (__half*)(sm + 17408 + 13824);    // 8704 words
    __half*   ksm_h = (__half*)ps;                      // after barrier A
    __half*   woh   = (__half*)ws;                      // after barrier B

    int tid = threadIdx.x;
    int bn = blockIdx.x;
    int b  = bn / NPAT, n = bn % NPAT;
    int ph = n / NHP,   pw = n % NHP;
    int top  = min(STEP*ph, HH-PP);
    int left = min(STEP*pw, WW-PP);
    const float* xb = x + (size_t)b * CC * HWSZ;

    for (int idx = tid; idx < 3*64*64; idx += 512) {
        int mat = idx >> 12; int rem = idx & 4095;
        int c = rem >> 6, j = rem & 63;
        const float* w = (mat == 0) ? wq : (mat == 1) ? wk : wv;
        int kt = c >> 3, r = c & 7, tt = r & 3, hi = r >> 2;
        ws[mat*WMAT + (j*36 + kt*4 + tt)*2 + hi] = f2tf(w[rem]);
    }
    for (int idx = tid; idx < CC*LL; idx += 512) {
        int c = idx >> 8, l = idx & 255;
        int li = l >> 4, lj = l & 15;
        ps[l*68 + c] = xb[(size_t)c*HWSZ + (size_t)(top+li)*WW + (left+lj)];
    }
    __syncthreads();

    int lane = tid & 31, warp = tid >> 5;
    {
        float ga = g1[lane], gb = g1[lane+32], ba = b1[lane], bbv = b1[lane+32];
        for (int l = warp; l < LL; l += 16) {
            float v0 = ps[l*68 + lane], v1 = ps[l*68 + lane + 32];
            size_t tb = ((size_t)bn*LL + l) * CC;
            g_t[tb + lane] = v0;  g_t[tb + lane + 32] = v1;
            float s = v0 + v1, ss = v0*v0 + v1*v1;
            #pragma unroll
            for (int o = 16; o; o >>= 1) {
                s  += __shfl_xor_sync(0xffffffffu, s,  o);
                ss += __shfl_xor_sync(0xffffffffu, ss, o);
            }
            float mean = s * (1.f/64.f);
            float var  = ss * (1.f/64.f) - mean*mean;
            float rstd = rsqrtf(var + 1e-5f);
            ps[l*68 + lane]      = __uint_as_float(f2tf((v0 - mean) * rstd * ga + ba));
            ps[l*68 + lane + 32] = __uint_as_float(f2tf((v1 - mean) * rstd * gb + bbv));
        }
    }
    __syncthreads();

    const unsigned* hs = (const unsigned*)ps;
    int g = lane >> 2, t = lane & 3;
    unsigned aq[8][4];
    {
        int r0 = (warp*16 + g)*68;
        #pragma unroll
        for (int kt = 0; kt < 8; kt++) {
            int c0 = kt*8 + t;
            aq[kt][0] = hs[r0 + c0];
            aq[kt][1] = hs[r0 + 544 + c0];
            aq[kt][2] = hs[r0 + c0 + 4];
            aq[kt][3] = hs[r0 + 544 + c0 + 4];
        }
    }
    __syncthreads();   // barrier A: ps free (becomes K fp16)

    {
        float acc[8][4];
        gemm64p(aq, ws + WMAT, g, t, acc);       // K -> fp16 [head][tok][KSH]
        #pragma unroll
        for (int nt = 0; nt < 8; nt++) {
            int tok = warp*16 + g;
            int hd  = nt >> 1;
            int d0  = (nt & 1)*8 + 2*t;
            __half* kp = ksm_h + hd*(LL*KSH) + tok*KSH + d0;
            *(__half2*)kp            = __floats2half2_rn(acc[nt][0], acc[nt][1]);
            *(__half2*)(kp + 8*KSH)  = __floats2half2_rn(acc[nt][2], acc[nt][3]);
        }
        gemm64p(aq, ws + 2*WMAT, g, t, acc);     // V -> fp16 V^T [d][tok]
        #pragma unroll
        for (int nt = 0; nt < 8; nt++) {
            int tok = warp*16 + g;
            int d0  = nt*8 + 2*t;
            __half* vp = vsm_h + (size_t)d0*VSH;
            vp[tok]           = __float2half(acc[nt][0]);
            vp[VSH + tok]     = __float2half(acc[nt][1]);
            vp[tok + 8]       = __float2half(acc[nt][2]);
            vp[VSH + tok + 8] = __float2half(acc[nt][3]);
        }
    }
    float qacc[8][4];
    gemm64p(aq, ws, g, t, qacc);                 // Q (registers)
    __syncthreads();   // barrier B: K/V visible; ws mat-0 writable

    // wo -> fp16 [j][72] (reuse mat-0 slot)
    for (int idx = tid; idx < 4096; idx += 512) {
        int c = idx >> 6, j = idx & 63;
        woh[j*72 + c] = __float2half(wo[idx]);
    }

    float oall[4][2][4];
    #pragma unroll
    for (int head = 0; head < NHEAD; head++) {
        // Q A-frag fp16: C-layout == fp16 A-layout (packs, no shuffles)
        unsigned aqh[4];
        {
            int h2 = head*2;
            aqh[0] = packh2(qacc[h2  ][0]*QSCALE, qacc[h2  ][1]*QSCALE);
            aqh[1] = packh2(qacc[h2  ][2]*QSCALE, qacc[h2  ][3]*QSCALE);
            aqh[2] = packh2(qacc[h2+1][0]*QSCALE, qacc[h2+1][1]*QSCALE);
            aqh[3] = packh2(qacc[h2+1][2]*QSCALE, qacc[h2+1][3]*QSCALE);
        }
        const __half* kh = ksm_h + head*(LL*KSH);
        const __half* vh = vsm_h + (size_t)head*16*VSH;
        float oh[2][4];
        #pragma unroll
        for (int nd = 0; nd < 2; nd++)
            #pragma unroll
            for (int i = 0; i < 4; i++) oh[nd][i] = 0.f;
        float mrow[2] = {-1e30f, -1e30f};
        float drow[2] = {0.f, 0.f};

        #pragma unroll 1
        for (int jt = 0; jt < 8; jt++) {
            float s[4][4];
            #pragma unroll
            for (int nt = 0; nt < 4; nt++)
                #pragma unroll
                for (int i = 0; i < 4; i++) s[nt][i] = 0.f;
            #pragma unroll
            for (int nt = 0; nt < 4; nt++) {
                const __half* kb = kh + (jt*32 + nt*8 + g)*KSH;
                unsigned b0 = *(const unsigned*)&kb[2*t];
                unsigned b1 = *(const unsigned*)&kb[8 + 2*t];
                mma_f16(s[nt], aqh, b0, b1);
            }
            #pragma unroll
            for (int h = 0; h < 2; h++) {
                float mx = fmaxf(s[0][h*2], s[0][h*2+1]);
                #pragma unroll
                for (int nt = 1; nt < 4; nt++)
                    mx = fmaxf(mx, fmaxf(s[nt][h*2], s[nt][h*2+1]));
                mx = fmaxf(mx, __shfl_xor_sync(0xffffffffu, mx, 1));
                mx = fmaxf(mx, __shfl_xor_sync(0xffffffffu, mx, 2));
                float mn = fmaxf(mrow[h], mx);
                float scale = ex2(mrow[h] - mn);
                mrow[h] = mn;
                drow[h] *= scale;
                #pragma unroll
                for (int nd = 0; nd < 2; nd++) {
                    oh[nd][h*2]   *= scale;
                    oh[nd][h*2+1] *= scale;
                }
                float psum = 0.f;
                #pragma unroll
                for (int nt = 0; nt < 4; nt++) {
                    float e0 = ex2(s[nt][h*2]   - mn);
                    float e1 = ex2(s[nt][h*2+1] - mn);
                    s[nt][h*2] = e0; s[nt][h*2+1] = e1;
                    psum += e0 + e1;
                }
                drow[h] += psum;
            }
            unsigned pa[2][4];
            #pragma unroll
            for (int kc = 0; kc < 2; kc++) {
                pa[kc][0] = packh2(s[2*kc  ][0], s[2*kc  ][1]);
                pa[kc][1] = packh2(s[2*kc  ][2], s[2*kc  ][3]);
                pa[kc][2] = packh2(s[2*kc+1][0], s[2*kc+1][1]);
                pa[kc][3] = packh2(s[2*kc+1][2], s[2*kc+1][3]);
            }
            #pragma unroll
            for (int nd = 0; nd < 2; nd++) {
                #pragma unroll
                for (int kc = 0; kc < 2; kc++) {
                    const __half* vb = vh + (size_t)(nd*8 + g)*VSH + jt*32 + kc*16;
                    unsigned b0 = *(const unsigned*)&vb[2*t];
                    unsigned b1 = *(const unsigned*)&vb[2*t + 8];
                    mma_f16(oh[nd], pa[kc], b0, b1);
                }
            }
        }
        float inv[2];
        #pragma unroll
        for (int h = 0; h < 2; h++) {
            float d = drow[h];
            d += __shfl_xor_sync(0xffffffffu, d, 1);
            d += __shfl_xor_sync(0xffffffffu, d, 2);
            inv[h] = 1.f / d;
        }
        #pragma unroll
        for (int nd = 0; nd < 2; nd++) {
            oall[head][nd][0] = oh[nd][0]*inv[0];
            oall[head][nd][1] = oh[nd][1]*inv[0];
            oall[head][nd][2] = oh[nd][2]*inv[1];
            oall[head][nd][3] = oh[nd][3]*inv[1];
        }
    }
    __syncthreads();   // barrier C: wo fp16 visible

    // t2 = o @ wo + t (fp16 mma; o C-layout == A-layout)
    {
        float acc[8][4];
        #pragma unroll
        for (int nt = 0; nt < 8; nt++)
            #pragma unroll
            for (int i = 0; i < 4; i++) acc[nt][i] = 0.f;
        #pragma unroll
        for (int kc = 0; kc < 4; kc++) {         // kc = head (16 k each)
            unsigned ao[4];
            ao[0] = packh2(oall[kc][0][0], oall[kc][0][1]);
            ao[1] = packh2(oall[kc][0][2], oall[kc][0][3]);
            ao[2] = packh2(oall[kc][1][0], oall[kc][1][1]);
            ao[3] = packh2(oall[kc][1][2], oall[kc][1][3]);
            #pragma unroll
            for (int nt = 0; nt < 8; nt++) {
                const __half* wb = woh + (nt*8 + g)*72 + kc*16;
                unsigned b0 = *(const unsigned*)&wb[2*t];
                unsigned b1 = *(const unsigned*)&wb[8 + 2*t];
                mma_f16(acc[nt], ao, b0, b1);
            }
        }
        size_t row0 = (size_t)bn * LL;
        #pragma unroll
        for (int nt = 0; nt < 8; nt++) {
            int row = warp*16 + g, col = nt*8 + 2*t;
            size_t a0 = (row0 + row)*CC + col;
            size_t a1 = (row0 + row + 8)*CC + col;
            float2 t0 = *(const float2*)&g_t[a0];
            float2 t1 = *(const float2*)&g_t[a1];
            float2 w0; w0.x = acc[nt][0] + t0.x; w0.y = acc[nt][1] + t0.y;
            float2 w1; w1.x = acc[nt][2] + t1.x; w1.y = acc[nt][3] + t1.y;
            *(float2*)&g_o[a0] = w0;
            *(float2*)&g_o[a1] = w1;
        }
    }
}

// ---------------- K4: patch_reverse gather + LN2 + fc1 + GELU -------------
__global__ __launch_bounds__(512) void k4(const float* __restrict__ g2,
                                          const float* __restrict__ b2,
                                          const float* __restrict__ fc1w,
                                          const float* __restrict__ fc1b)
{
    extern __shared__ float sm4[];
    float*    xsm = sm4;                        // 256*68
    unsigned* fw  = (unsigned*)(sm4 + 256*68);  // 9216 words
    int tid = threadIdx.x;
    size_t pix0 = (size_t)blockIdx.x * 256;
    int b4   = (int)(pix0 >> 16);
    int rrow = (int)((pix0 & 65535) >> 8);

    {
        int hc = d_cov_cnt[rrow];
        float idr = d_invdiv[rrow];
        for (int idx = tid; idx < 4096; idx += 512) {
            int row = idx >> 4, c4 = (idx & 15) * 4;
            float4 a4; a4.x = 0.f; a4.y = 0.f; a4.z = 0.f; a4.w = 0.f;
            int wc2 = d_cov_cnt[row];
            for (int i = 0; i < hc; i++) {
                int n0 = d_cov_p[rrow][i]*NHP, l0 = d_cov_o[rrow][i]*PP;
                for (int k = 0; k < wc2; k++) {
                    int n = n0 + d_cov_p[row][k];
                    int l = l0 + d_cov_o[row][k];
                    float4 v = *(const float4*)&g_o[(((size_t)(b4*NPAT + n))*LL + l)*CC + c4];
                    a4.x += v.x; a4.y += v.y; a4.z += v.z; a4.w += v.w;
                }
            }
            float sc = idr * d_invdiv[row];
            a4.x *= sc; a4.y *= sc; a4.z *= sc; a4.w *= sc;
            *(float4*)&xsm[row*68 + c4] = a4;
            *(float4*)&g_xs[(pix0 + row)*CC + c4] = a4;
        }
    }
    for (int idx = tid; idx < 8192; idx += 512) {
        int c = idx >> 7, j = idx & 127;
        int kt = c >> 3, r = c & 7, tt = r & 3, hi = r >> 2;
        fw[(j*36 + kt*4 + tt)*2 + hi] = f2tf(fc1w[idx]);
    }
    __syncthreads();

    int lane = tid & 31, warp = tid >> 5;
    float ga = g2[lane], gb = g2[lane+32], ba = b2[lane], bbv = b2[lane+32];
    for (int r = warp; r < 256; r += 16) {
        float v0 = xsm[r*68+lane], v1 = xsm[r*68+lane+32];
        float s = v0+v1, ss = v0*v0+v1*v1;
        #pragma unroll
        for (int o = 16; o; o >>= 1) {
            s  += __shfl_xor_sync(0xffffffffu, s,  o);
            ss += __shfl_xor_sync(0xffffffffu, ss, o);
        }
        float mean = s * (1.f/64.f);
        float var  = ss * (1.f/64.f) - mean*mean;
        float rstd = rsqrtf(var + 1e-5f);
        xsm[r*68+lane]    = __uint_as_float(f2tf((v0 - mean) * rstd * ga + ba));
        xsm[r*68+lane+32] = __uint_as_float(f2tf((v1 - mean) * rstd * gb + bbv));
    }
    __syncthreads();

    const unsigned* hs = (const unsigned*)xsm;
    int g = lane >> 2, t = lane & 3;
    int r0 = (warp*16 + g)*68;
    unsigned aq[8][4];
    #pragma unroll
    for (int kt = 0; kt < 8; kt++) {
        int c0 = kt*8 + t;
        aq[kt][0] = hs[r0 + c0];
        aq[kt][1] = hs[r0 + 544 + c0];
        aq[kt][2] = hs[r0 + c0 + 4];
        aq[kt][3] = hs[r0 + 544 + c0 + 4];
    }
    float acc[16][4];
    #pragma unroll
    for (int nt = 0; nt < 16; nt++) {
        float2 bb = *(const float2*)&fc1b[nt*8 + 2*t];
        acc[nt][0] = bb.x; acc[nt][1] = bb.y; acc[nt][2] = bb.x; acc[nt][3] = bb.y;
    }
    #pragma unroll
    for (int nt = 0; nt < 16; nt++)
        #pragma unroll
        for (int kt = 0; kt < 8; kt++) {
            uint2 b = *(const uint2*)&fw[((nt*8 + g)*36 + kt*4 + t)*2];
            mma_tf32(acc[nt], aq[kt], b.x, b.y);
        }
    #pragma unroll
    for (int nt = 0; nt < 16; nt++) {
        int row = warp*16 + g, col = nt*8 + 2*t;
        __half2 h0 = __floats2half2_rn(gelu(acc[nt][0]), gelu(acc[nt][1]));
        __half2 h1 = __floats2half2_rn(gelu(acc[nt][2]), gelu(acc[nt][3]));
        *(__half2*)&g_h1[(pix0 + row)*MLP + col]     = h0;
        *(__half2*)&g_h1[(pix0 + row + 8)*MLP + col] = h1;
    }
}

// ---------------- kB: dwconv 5x5 + GELU + residual + fc2 + store ----------
// block = 8x8 spatial tile (2048 blocks), 256 threads. smem 71.7 KB -> 3 blk/SM.
//   si  : halo h1 fp16 [144 px][128]  (36864 B) -> reused as out tile f32 [64][68]
//   fsm : conv result fp16 [64 px][136] (17408 B)
//   fwh : fc2w fp16 [64 j][136]        (17408 B)
#define KB_SI_BYTES   36864
#define KB_FSM_BYTES  17408
#define KB_FW_BYTES   17408
#define KB_SMEM (KB_SI_BYTES + KB_FSM_BYTES + KB_FW_BYTES)
__global__ __launch_bounds__(256) void kB(const float* __restrict__ dww,
                                          const float* __restrict__ dwb,
                                          const float* __restrict__ fc2w,
                                          const float* __restrict__ fc2b,
                                          float* __restrict__ out)
{
    extern __shared__ char smB[];
    __half*   si  = (__half*)smB;
    __half*   fsm = (__half*)(smB + KB_SI_BYTES);
    __half*   fwh = (__half*)(smB + KB_SI_BYTES + KB_FSM_BYTES);
    float*    tile = (float*)smB;            // overlay si (dead after conv)

    int tid = threadIdx.x;
    int bx = blockIdx.x;
    int b  = bx >> 10;
    int tr = (bx >> 5) & 31, tc = bx & 31;
    int r0 = tr*8, c0 = tc*8;

    // halo load: 144 pixels (12x12) x 128 ch fp16 (zero-filled OOB)
    const uint4* h1v = (const uint4*)(g_h1 + (size_t)b * HWSZ * MLP);
    for (int idx = tid; idx < 144*16; idx += 256) {
        int p = idx >> 4, u = idx & 15;
        int hr = p / 12, hc = p % 12;
        int gr = r0 + hr - 2, gc = c0 + hc - 2;
        uint4 v = {0u, 0u, 0u, 0u};
        if (gr >= 0 && gr < 256 && gc >= 0 && gc < 256)
            v = h1v[(size_t)(gr*256 + gc)*16 + u];
        *(uint4*)&si[(size_t)p*128 + u*8] = v;
    }
    for (int idx = tid; idx < 8192; idx += 256) {
        int c = idx >> 6, j = idx & 63;
        fwh[j*136 + c] = __float2half(fc2w[idx]);
    }
    __syncthreads();

    // conv: ch = tid&127, q = tid>>7 handles 4 tile rows (8 total)
    {
        int ch = tid & 127, q = tid >> 7;
        float wreg[25];
        #pragma unroll
        for (int i = 0; i < 25; i++) wreg[i] = dww[ch*25 + i];
        float bias = dwb[ch];
        for (int r = q*4; r < q*4 + 4; r++) {
            float val[5][12];
            #pragma unroll
            for (int dy = 0; dy < 5; dy++)
                #pragma unroll
                for (int xx = 0; xx < 12; xx++)
                    val[dy][xx] = __half2float(si[(size_t)((r+dy)*12 + xx)*128 + ch]);
            #pragma unroll
            for (int k = 0; k < 8; k++) {
                float acc = bias;
                #pragma unroll
                for (int dy = 0; dy < 5; dy++)
                    #pragma unroll
                    for (int dx = 0; dx < 5; dx++)
                        acc += val[dy][k + dx] * wreg[dy*5 + dx];
                float center = val[2][k + 2];
                fsm[(size_t)(r*8 + k)*136 + ch] = __float2half(center + gelu(acc));
            }
        }
    }
    __syncthreads();

    // fc2 mma fp16: 8 warps; warp = (mt = w>>1: 16 pixels, nh = w&1: 32 cols)
    int lane = tid & 31, w = tid >> 5, g = lane >> 2, t = lane & 3;
    {
        int mt = w >> 1, nh = w & 1;
        int rb = (mt*16 + g)*136;
        float acc[4][4];
        #pragma unroll
        for (int nt = 0; nt < 4; nt++)
            #pragma unroll
            for (int i = 0; i < 4; i++) acc[nt][i] = 0.f;
        #pragma unroll
        for (int kc = 0; kc < 8; kc++) {
            unsigned a[4];
            a[0] = *(const unsigned*)&fsm[rb + kc*16 + 2*t];
            a[1] = *(const unsigned*)&fsm[rb + 8*136 + kc*16 + 2*t];
            a[2] = *(const unsigned*)&fsm[rb + kc*16 + 8 + 2*t];
            a[3] = *(const unsigned*)&fsm[rb + 8*136 + kc*16 + 8 + 2*t];
            #pragma unroll
            for (int nt = 0; nt < 4; nt++) {
                const __half* wb = fwh + (nh*32 + nt*8 + g)*136 + kc*16;
                unsigned b0 = *(const unsigned*)&wb[2*t];
                unsigned b1 = *(const unsigned*)&wb[8 + 2*t];
                mma_f16(acc[nt], a, b0, b1);
            }
        }
        __syncthreads();   // fsm consumed; si overlay becomes out tile
        int p0 = mt*16 + g, p1 = p0 + 8;
        int rr0 = p0 >> 3, kk0 = p0 & 7;
        int rr1 = p1 >> 3, kk1 = p1 & 7;
        size_t base = (size_t)b*HWSZ;
        #pragma unroll
        for (int nt = 0; nt < 4; nt++) {
            int col = nh*32 + nt*8 + 2*t;
            float2 bb = *(const float2*)&fc2b[col];
            float2 x0 = *(const float2*)&g_xs[(base + (size_t)(r0+rr0)*256 + c0 + kk0)*CC + col];
            float2 x1 = *(const float2*)&g_xs[(base + (size_t)(r0+rr1)*256 + c0 + kk1)*CC + col];
            tile[(col  )*68 + p0] = acc[nt][0] + bb.x + x0.x;
            tile[(col+1)*68 + p0] = acc[nt][1] + bb.y + x0.y;
            tile[(col  )*68 + p1] = acc[nt][2] + bb.x + x1.x;
            tile[(col+1)*68 + p1] = acc[nt][3] + bb.y + x1.y;
        }
    }
    __syncthreads();

    // NCHW store: 64 ch x 8 rows x 8 cols (float2)
    for (int idx = tid; idx < 2048; idx += 256) {
        int c = idx >> 5, pp = idx & 31;
        int r = pp >> 2, k2 = (pp & 3) * 2;
        *(float2*)&out[((size_t)(b*CC + c))*HWSZ + (size_t)(r0 + r)*256 + c0 + k2] =
            *(const float2*)&tile[c*68 + r*8 + k2];
    }
}

// ---------------- launch ---------------------------------------------------
#define KA_SMEM ((17408 + 13824 + 8704) * 4)
#define K4_SMEM ((256*68 + 9216) * 4)

extern "C" void kernel_launch(void* const* d_in, const int* in_sizes, int n_in,
                              void* d_out, int out_size)
{
    const float* x    = (const float*)d_in[0];
    const float* ln1g = (const float*)d_in[1];
    const float* ln1b = (const float*)d_in[2];
    const float* wq   = (const float*)d_in[3];
    const float* wk   = (const float*)d_in[4];
    const float* wv   = (const float*)d_in[5];
    const float* wo   = (const float*)d_in[6];
    const float* ln2g = (const float*)d_in[7];
    const float* ln2b = (const float*)d_in[8];
    const float* fc1w = (const float*)d_in[9];
    const float* fc1b = (const float*)d_in[10];
    const float* dww  = (const float*)d_in[11];
    const float* dwb  = (const float*)d_in[12];
    const float* fc2w = (const float*)d_in[13];
    const float* fc2b = (const float*)d_in[14];
    float* out = (float*)d_out;

    static int s_attr = 0;
    if (!s_attr) {
        cudaFuncSetAttribute(kA, cudaFuncAttributeMaxDynamicSharedMemorySize, KA_SMEM);
        cudaFuncSetAttribute(k4, cudaFuncAttributeMaxDynamicSharedMemorySize, K4_SMEM);
        cudaFuncSetAttribute(kB, cudaFuncAttributeMaxDynamicSharedMemorySize, KB_SMEM);
        s_attr = 1;
    }

    k_init<<<1, 256>>>();
    kA<<<BN, 512, KA_SMEM>>>(x, ln1g, ln1b, wq, wk, wv, wo);
    k4<<<(BB*HWSZ)/256, 512, K4_SMEM>>>(ln2g, ln2b, fc1w, fc1b);
    kB<<<BB*1024, 256, KB_SMEM>>>(dww, dwb, fc2w, fc2b, out);
}

// round 15
// speedup vs baseline: 4.4972x; 1.0812x over previous
#include <cuda_runtime.h>
#include <cuda_fp16.h>
#include <cuda_bf16.h>
#include <cstddef>

// ---------------- problem geometry (fixed by setup_inputs) ----------------
#define BB    2
#define CC    64
#define HH    256
#define WW    256
#define PP    16
#define STEP  14
#define NHP   19
#define NPAT  361
#define BN    722
#define LL    256
#define NHEAD 4
#define DHEAD 16
#define MLP   128
#define HWSZ  65536

#define QSCALE 0.36067376022224085f   // 0.25 * log2(e)

#define KSH  24                       // K fp16 row stride (halves)
#define VSH  272                      // V^T fp16 row stride (halves)
#define HSH  136                      // h fp16 row stride (halves) = 68 words
#define WSH  72                       // weight fp16 row stride (halves)

// ---------------- scratch ----------
__device__ float g_t [(size_t)BN*LL*CC];
__device__ float g_o [(size_t)BN*LL*CC];
__device__ float g_xs[(size_t)BB*HWSZ*CC];
__device__ __half g_h1[(size_t)BB*HWSZ*MLP];

__device__ int   d_cov_cnt[256];
__device__ int   d_cov_p[256][2];
__device__ int   d_cov_o[256][2];
__device__ float d_invdiv[256];

__global__ void k_init()
{
    int r = threadIdx.x;
    if (r < 256) {
        int cnt = 0;
        for (int ph = 0; ph < NHP; ph++) {
            int top = min(STEP*ph, HH-PP);
            if (r >= top && r < top + PP && cnt < 2) {
                d_cov_p[r][cnt] = ph;
                d_cov_o[r][cnt] = r - top;
                cnt++;
            }
        }
        d_cov_cnt[r] = cnt;
    }
    if (threadIdx.x == 0) {
        float div[256];
        for (int i = 0; i < 256; i++) div[i] = 1.f;
        for (int i = STEP; i < HH + STEP - PP; i += STEP) {
            int top = (i + PP > HH) ? (HH - PP) : i;
            for (int r2 = top; r2 < i + PP - STEP; ++r2) div[r2] *= 2.f;
        }
        for (int i = 0; i < 256; i++) d_invdiv[i] = 1.f / div[i];
    }
}

// ---------------- mma helpers ---------------------------------------------
__device__ __forceinline__ float ex2(float x) {
    float r; asm("ex2.approx.ftz.f32 %0, %1;" : "=f"(r) : "f"(x)); return r;
}
__device__ __forceinline__ unsigned packh2(float x, float y) {
    __half2 h = __floats2half2_rn(x, y);
    return *(unsigned*)&h;
}
__device__ __forceinline__ void mma_f16(float* d, const unsigned* a,
                                        unsigned b0, unsigned b1) {
    asm volatile("mma.sync.aligned.m16n8k16.row.col.f32.f16.f16.f32 "
        "{%0,%1,%2,%3},{%4,%5,%6,%7},{%8,%9},{%0,%1,%2,%3};"
        : "+f"(d[0]), "+f"(d[1]), "+f"(d[2]), "+f"(d[3])
        : "r"(a[0]), "r"(a[1]), "r"(a[2]), "r"(a[3]), "r"(b0), "r"(b1));
}
__device__ __forceinline__ float gelu(float x) {
    return 0.5f * x * (1.f + erff(x * 0.70710678118654752f));
}
// fp16 GEMM, warp = 16 rows x 64 cols, K=64: A-frags [4 kc][4], B = wm [j][WSH]
__device__ __forceinline__ void gemm64h(const unsigned aq[4][4],
                                        const __half* __restrict__ wm,
                                        int g, int t, float acc[8][4]) {
    #pragma unroll
    for (int nt = 0; nt < 8; nt++)
        #pragma unroll
        for (int i = 0; i < 4; i++) acc[nt][i] = 0.f;
    #pragma unroll
    for (int nt = 0; nt < 8; nt++)
        #pragma unroll
        for (int kc = 0; kc < 4; kc++) {
            const __half* wb = wm + (nt*8 + g)*WSH + kc*16;
            unsigned b0 = *(const unsigned*)&wb[2*t];
            unsigned b1 = *(const unsigned*)&wb[8 + 2*t];
            mma_f16(acc[nt], aq[kc], b0, b1);
        }
}

// ---------------- kA: gather + LN1 + QKV + attention + o@wo + t -----------
// block = patch (722), 512 thr = 16 warps. smem 129 KB:
//   ps  : 256*68 fp32 patch -> h fp16 in place -> reused as K fp16
//   wsh : 3 mats fp16 [64 j][WSH]; mat-0 slot reused for wo fp16
//   vsm : V^T fp16 [64 d][VSH]
__global__ __launch_bounds__(512) void kA(const float* __restrict__ x,
                                          const float* __restrict__ g1,
                                          const float* __restrict__ b1,
                                          const float* __restrict__ wq,
                                          const float* __restrict__ wk,
                                          const float* __restrict__ wv,
                                          const float* __restrict__ wo)
{
    extern __shared__ float sm[];
    float*  ps    = sm;                               // 17408 words
    __half* wsh   = (__half*)(sm + 17408);            // 3*4608 halves = 6912 words
    __half* vsm_h = (__half*)(sm + 17408 + 6912);     // 8704 words
    __half* hsm_h = (__half*)ps;                      // h fp16 in place
    __half* ksm_h = (__half*)ps;                      // K fp16 after barrier A
    __half* woh   = wsh;                              // wo after barrier B

    int tid = threadIdx.x;
    int bn = blockIdx.x;
    int b  = bn / NPAT, n = bn % NPAT;
    int ph = n / NHP,   pw = n % NHP;
    int top  = min(STEP*ph, HH-PP);
    int left = min(STEP*pw, WW-PP);
    const float* xb = x + (size_t)b * CC * HWSZ;

    // weights -> fp16 [j][WSH]
    for (int idx = tid; idx < 3*64*64; idx += 512) {
        int mat = idx >> 12; int rem = idx & 4095;
        int c = rem >> 6, j = rem & 63;
        const float* w = (mat == 0) ? wq : (mat == 1) ? wk : wv;
        wsh[mat*4608 + j*WSH + c] = __float2half(w[rem]);
    }
    for (int idx = tid; idx < CC*LL; idx += 512) {
        int c = idx >> 8, l = idx & 255;
        int li = l >> 4, lj = l & 15;
        ps[l*68 + c] = xb[(size_t)c*HWSZ + (size_t)(top+li)*WW + (left+lj)];
    }
    __syncthreads();

    int lane = tid & 31, warp = tid >> 5;
    {
        float ga = g1[lane], gb = g1[lane+32], ba = b1[lane], bbv = b1[lane+32];
        for (int l = warp; l < LL; l += 16) {
            float v0 = ps[l*68 + lane], v1 = ps[l*68 + lane + 32];
            size_t tb = ((size_t)bn*LL + l) * CC;
            g_t[tb + lane] = v0;  g_t[tb + lane + 32] = v1;
            float s = v0 + v1, ss = v0*v0 + v1*v1;
            #pragma unroll
            for (int o = 16; o; o >>= 1) {
                s  += __shfl_xor_sync(0xffffffffu, s,  o);
                ss += __shfl_xor_sync(0xffffffffu, ss, o);
            }
            float mean = s * (1.f/64.f);
            float var  = ss * (1.f/64.f) - mean*mean;
            float rstd = rsqrtf(var + 1e-5f);
            // in-place fp16 h (shfl above orders all reads before these writes)
            hsm_h[l*HSH + lane]      = __float2half((v0 - mean) * rstd * ga + ba);
            hsm_h[l*HSH + lane + 32] = __float2half((v1 - mean) * rstd * gb + bbv);
        }
    }
    __syncthreads();

    int g = lane >> 2, t = lane & 3;
    unsigned aqh16[4][4];
    {
        int r0 = (warp*16 + g)*HSH;
        #pragma unroll
        for (int kc = 0; kc < 4; kc++) {
            int c0 = kc*16 + 2*t;
            aqh16[kc][0] = *(const unsigned*)&hsm_h[r0 + c0];
            aqh16[kc][1] = *(const unsigned*)&hsm_h[r0 + 8*HSH + c0];
            aqh16[kc][2] = *(const unsigned*)&hsm_h[r0 + c0 + 8];
            aqh16[kc][3] = *(const unsigned*)&hsm_h[r0 + 8*HSH + c0 + 8];
        }
    }
    __syncthreads();   // barrier A: ps free (becomes K fp16)

    {
        float acc[8][4];
        gemm64h(aqh16, wsh + 4608, g, t, acc);   // K -> fp16 [head][tok][KSH]
        #pragma unroll
        for (int nt = 0; nt < 8; nt++) {
            int tok = warp*16 + g;
            int hd  = nt >> 1;
            int d0  = (nt & 1)*8 + 2*t;
            __half* kp = ksm_h + hd*(LL*KSH) + tok*KSH + d0;
            *(__half2*)kp            = __floats2half2_rn(acc[nt][0], acc[nt][1]);
            *(__half2*)(kp + 8*KSH)  = __floats2half2_rn(acc[nt][2], acc[nt][3]);
        }
        gemm64h(aqh16, wsh + 2*4608, g, t, acc); // V -> fp16 V^T [d][tok]
        #pragma unroll
        for (int nt = 0; nt < 8; nt++) {
            int tok = warp*16 + g;
            int d0  = nt*8 + 2*t;
            __half* vp = vsm_h + d0*VSH;
            vp[tok]           = __float2half(acc[nt][0]);
            vp[VSH + tok]     = __float2half(acc[nt][1]);
            vp[tok + 8]       = __float2half(acc[nt][2]);
            vp[VSH + tok + 8] = __float2half(acc[nt][3]);
        }
    }
    float qacc[8][4];
    gemm64h(aqh16, wsh, g, t, qacc);             // Q (registers)
    __syncthreads();   // barrier B: K/V visible; wsh mat-0 writable

    for (int idx = tid; idx < 4096; idx += 512) {
        int c = idx >> 6, j = idx & 63;
        woh[j*WSH + c] = __float2half(wo[idx]);
    }

    float oall[4][2][4];
    #pragma unroll
    for (int head = 0; head < NHEAD; head++) {
        unsigned aqh[4];
        {
            int h2 = head*2;
            aqh[0] = packh2(qacc[h2  ][0]*QSCALE, qacc[h2  ][1]*QSCALE);
            aqh[1] = packh2(qacc[h2  ][2]*QSCALE, qacc[h2  ][3]*QSCALE);
            aqh[2] = packh2(qacc[h2+1][0]*QSCALE, qacc[h2+1][1]*QSCALE);
            aqh[3] = packh2(qacc[h2+1][2]*QSCALE, qacc[h2+1][3]*QSCALE);
        }
        const __half* kh = ksm_h + head*(LL*KSH);
        const __half* vh = vsm_h + head*16*VSH;
        float oh[2][4];
        #pragma unroll
        for (int nd = 0; nd < 2; nd++)
            #pragma unroll
            for (int i = 0; i < 4; i++) oh[nd][i] = 0.f;
        float mrow[2] = {-1e30f, -1e30f};
        float drow[2] = {0.f, 0.f};

        #pragma unroll 1
        for (int jt = 0; jt < 8; jt++) {
            float s[4][4];
            #pragma unroll
            for (int nt = 0; nt < 4; nt++)
                #pragma unroll
                for (int i = 0; i < 4; i++) s[nt][i] = 0.f;
            #pragma unroll
            for (int nt = 0; nt < 4; nt++) {
                const __half* kb = kh + (jt*32 + nt*8 + g)*KSH;
                unsigned b0 = *(const unsigned*)&kb[2*t];
                unsigned b1 = *(const unsigned*)&kb[8 + 2*t];
                mma_f16(s[nt], aqh, b0, b1);
            }
            #pragma unroll
            for (int h = 0; h < 2; h++) {
                float mx = fmaxf(s[0][h*2], s[0][h*2+1]);
                #pragma unroll
                for (int nt = 1; nt < 4; nt++)
                    mx = fmaxf(mx, fmaxf(s[nt][h*2], s[nt][h*2+1]));
                mx = fmaxf(mx, __shfl_xor_sync(0xffffffffu, mx, 1));
                mx = fmaxf(mx, __shfl_xor_sync(0xffffffffu, mx, 2));
                float mn = fmaxf(mrow[h], mx);
                float scale = ex2(mrow[h] - mn);
                mrow[h] = mn;
                drow[h] *= scale;
                #pragma unroll
                for (int nd = 0; nd < 2; nd++) {
                    oh[nd][h*2]   *= scale;
                    oh[nd][h*2+1] *= scale;
                }
                float psum = 0.f;
                #pragma unroll
                for (int nt = 0; nt < 4; nt++) {
                    float e0 = ex2(s[nt][h*2]   - mn);
                    float e1 = ex2(s[nt][h*2+1] - mn);
                    s[nt][h*2] = e0; s[nt][h*2+1] = e1;
                    psum += e0 + e1;
                }
                drow[h] += psum;
            }
            unsigned pa[2][4];
            #pragma unroll
            for (int kc = 0; kc < 2; kc++) {
                pa[kc][0] = packh2(s[2*kc  ][0], s[2*kc  ][1]);
                pa[kc][1] = packh2(s[2*kc  ][2], s[2*kc  ][3]);
                pa[kc][2] = packh2(s[2*kc+1][0], s[2*kc+1][1]);
                pa[kc][3] = packh2(s[2*kc+1][2], s[2*kc+1][3]);
            }
            #pragma unroll
            for (int nd = 0; nd < 2; nd++) {
                #pragma unroll
                for (int kc = 0; kc < 2; kc++) {
                    const __half* vb = vh + (nd*8 + g)*VSH + jt*32 + kc*16;
                    unsigned b0 = *(const unsigned*)&vb[2*t];
                    unsigned b1 = *(const unsigned*)&vb[2*t + 8];
                    mma_f16(oh[nd], pa[kc], b0, b1);
                }
            }
        }
        float inv[2];
        #pragma unroll
        for (int h = 0; h < 2; h++) {
            float d = drow[h];
            d += __shfl_xor_sync(0xffffffffu, d, 1);
            d += __shfl_xor_sync(0xffffffffu, d, 2);
            inv[h] = 1.f / d;
        }
        #pragma unroll
        for (int nd = 0; nd < 2; nd++) {
            oall[head][nd][0] = oh[nd][0]*inv[0];
            oall[head][nd][1] = oh[nd][1]*inv[0];
            oall[head][nd][2] = oh[nd][2]*inv[1];
            oall[head][nd][3] = oh[nd][3]*inv[1];
        }
    }
    __syncthreads();   // barrier C: wo fp16 visible

    {
        float acc[8][4];
        #pragma unroll
        for (int nt = 0; nt < 8; nt++)
            #pragma unroll
            for (int i = 0; i < 4; i++) acc[nt][i] = 0.f;
        #pragma unroll
        for (int kc = 0; kc < 4; kc++) {
            unsigned ao[4];
            ao[0] = packh2(oall[kc][0][0], oall[kc][0][1]);
            ao[1] = packh2(oall[kc][0][2], oall[kc][0][3]);
            ao[2] = packh2(oall[kc][1][0], oall[kc][1][1]);
            ao[3] = packh2(oall[kc][1][2], oall[kc][1][3]);
            #pragma unroll
            for (int nt = 0; nt < 8; nt++) {
                const __half* wb = woh + (nt*8 + g)*WSH + kc*16;
                unsigned b0 = *(const unsigned*)&wb[2*t];
                unsigned b1 = *(const unsigned*)&wb[8 + 2*t];
                mma_f16(acc[nt], ao, b0, b1);
            }
        }
        size_t row0 = (size_t)bn * LL;
        #pragma unroll
        for (int nt = 0; nt < 8; nt++) {
            int row = warp*16 + g, col = nt*8 + 2*t;
            size_t a0 = (row0 + row)*CC + col;
            size_t a1 = (row0 + row + 8)*CC + col;
            float2 t0 = *(const float2*)&g_t[a0];
            float2 t1 = *(const float2*)&g_t[a1];
            float2 w0; w0.x = acc[nt][0] + t0.x; w0.y = acc[nt][1] + t0.y;
            float2 w1; w1.x = acc[nt][2] + t1.x; w1.y = acc[nt][3] + t1.y;
            *(float2*)&g_o[a0] = w0;
            *(float2*)&g_o[a1] = w1;
        }
    }
}

// ---------------- K4: patch_reverse gather + LN2 + fc1 + GELU -------------
__global__ __launch_bounds__(512) void k4(const float* __restrict__ g2,
                                          const float* __restrict__ b2,
                                          const float* __restrict__ fc1w,
                                          const float* __restrict__ fc1b)
{
    extern __shared__ float sm4[];
    float*  xsm = sm4;                        // 256*68 fp32 -> fp16 in place
    __half* fwh = (__half*)(sm4 + 256*68);    // 128 j x WSH halves = 4608 words
    __half* hsm_h = (__half*)xsm;
    int tid = threadIdx.x;
    size_t pix0 = (size_t)blockIdx.x * 256;
    int b4   = (int)(pix0 >> 16);
    int rrow = (int)((pix0 & 65535) >> 8);

    {
        int hc = d_cov_cnt[rrow];
        float idr = d_invdiv[rrow];
        for (int idx = tid; idx < 4096; idx += 512) {
            int row = idx >> 4, c4 = (idx & 15) * 4;
            float4 a4; a4.x = 0.f; a4.y = 0.f; a4.z = 0.f; a4.w = 0.f;
            int wc2 = d_cov_cnt[row];
            for (int i = 0; i < hc; i++) {
                int n0 = d_cov_p[rrow][i]*NHP, l0 = d_cov_o[rrow][i]*PP;
                for (int k = 0; k < wc2; k++) {
                    int n = n0 + d_cov_p[row][k];
                    int l = l0 + d_cov_o[row][k];
                    float4 v = *(const float4*)&g_o[(((size_t)(b4*NPAT + n))*LL + l)*CC + c4];
                    a4.x += v.x; a4.y += v.y; a4.z += v.z; a4.w += v.w;
                }
            }
            float sc = idr * d_invdiv[row];
            a4.x *= sc; a4.y *= sc; a4.z *= sc; a4.w *= sc;
            *(float4*)&xsm[row*68 + c4] = a4;
            *(float4*)&g_xs[(pix0 + row)*CC + c4] = a4;
        }
    }
    for (int idx = tid; idx < 8192; idx += 512) {
        int c = idx >> 7, j = idx & 127;
        fwh[j*WSH + c] = __float2half(fc1w[idx]);
    }
    __syncthreads();

    int lane = tid & 31, warp = tid >> 5;
    float ga = g2[lane], gb = g2[lane+32], ba = b2[lane], bbv = b2[lane+32];
    for (int r = warp; r < 256; r += 16) {
        float v0 = xsm[r*68+lane], v1 = xsm[r*68+lane+32];
        float s = v0+v1, ss = v0*v0+v1*v1;
        #pragma unroll
        for (int o = 16; o; o >>= 1) {
            s  += __shfl_xor_sync(0xffffffffu, s,  o);
            ss += __shfl_xor_sync(0xffffffffu, ss, o);
        }
        float mean = s * (1.f/64.f);
        float var  = ss * (1.f/64.f) - mean*mean;
        float rstd = rsqrtf(var + 1e-5f);
        hsm_h[r*HSH + lane]      = __float2half((v0 - mean) * rstd * ga + ba);
        hsm_h[r*HSH + lane + 32] = __float2half((v1 - mean) * rstd * gb + bbv);
    }
    __syncthreads();

    int g = lane >> 2, t = lane & 3;
    int r0 = (warp*16 + g)*HSH;
    unsigned aq[4][4];
    #pragma unroll
    for (int kc = 0; kc < 4; kc++) {
        int c0 = kc*16 + 2*t;
        aq[kc][0] = *(const unsigned*)&hsm_h[r0 + c0];
        aq[kc][1] = *(const unsigned*)&hsm_h[r0 + 8*HSH + c0];
        aq[kc][2] = *(const unsigned*)&hsm_h[r0 + c0 + 8];
        aq[kc][3] = *(const unsigned*)&hsm_h[r0 + 8*HSH + c0 + 8];
    }
    float acc[16][4];
    #pragma unroll
    for (int nt = 0; nt < 16; nt++) {
        float2 bb = *(const float2*)&fc1b[nt*8 + 2*t];
        acc[nt][0] = bb.x; acc[nt][1] = bb.y; acc[nt][2] = bb.x; acc[nt][3] = bb.y;
    }
    #pragma unroll
    for (int nt = 0; nt < 16; nt++)
        #pragma unroll
        for (int kc = 0; kc < 4; kc++) {
            const __half* wb = fwh + (nt*8 + g)*WSH + kc*16;
            unsigned b0 = *(const unsigned*)&wb[2*t];
            unsigned b1 = *(const unsigned*)&wb[8 + 2*t];
            mma_f16(acc[nt], aq[kc], b0, b1);
        }
    #pragma unroll
    for (int nt = 0; nt < 16; nt++) {
        int row = warp*16 + g, col = nt*8 + 2*t;
        __half2 h0 = __floats2half2_rn(gelu(acc[nt][0]), gelu(acc[nt][1]));
        __half2 h1 = __floats2half2_rn(gelu(acc[nt][2]), gelu(acc[nt][3]));
        *(__half2*)&g_h1[(pix0 + row)*MLP + col]     = h0;
        *(__half2*)&g_h1[(pix0 + row + 8)*MLP + col] = h1;
    }
}

// ---------------- kB: dwconv 5x5 + GELU + residual + fc2 + store ----------
// block = 8x8 tile (2048 blocks), 256 thr, 3 blocks/SM target. smem 71.7 KB.
#define KB_SI_BYTES   36864
#define KB_FSM_BYTES  17408
#define KB_FW_BYTES   17408
#define KB_SMEM (KB_SI_BYTES + KB_FSM_BYTES + KB_FW_BYTES)
__global__ __launch_bounds__(256, 3) void kB(const float* __restrict__ dww,
                                             const float* __restrict__ dwb,
                                             const float* __restrict__ fc2w,
                                             const float* __restrict__ fc2b,
                                             float* __restrict__ out)
{
    extern __shared__ char smB[];
    __half* si  = (__half*)smB;
    __half* fsm = (__half*)(smB + KB_SI_BYTES);
    __half* fwh = (__half*)(smB + KB_SI_BYTES + KB_FSM_BYTES);
    float*  tile = (float*)smB;              // overlay si (dead after conv)

    int tid = threadIdx.x;
    int bx = blockIdx.x;
    int b  = bx >> 10;
    int tr = (bx >> 5) & 31, tc = bx & 31;
    int r0 = tr*8, c0 = tc*8;

    const uint4* h1v = (const uint4*)(g_h1 + (size_t)b * HWSZ * MLP);
    for (int idx = tid; idx < 144*16; idx += 256) {
        int p = idx >> 4, u = idx & 15;
        int hr = p / 12, hc = p % 12;
        int gr = r0 + hr - 2, gc = c0 + hc - 2;
        uint4 v = {0u, 0u, 0u, 0u};
        if (gr >= 0 && gr < 256 && gc >= 0 && gc < 256)
            v = h1v[(size_t)(gr*256 + gc)*16 + u];
        *(uint4*)&si[p*128 + u*8] = v;
    }
    for (int idx = tid; idx < 8192; idx += 256) {
        int c = idx >> 6, j = idx & 63;
        fwh[j*136 + c] = __float2half(fc2w[idx]);
    }
    __syncthreads();

    // conv: row-streaming (low regs): acc8[8] + v[12] + cent[8]
    {
        int ch = tid & 127, q = tid >> 7;
        float wreg[25];
        #pragma unroll
        for (int i = 0; i < 25; i++) wreg[i] = dww[ch*25 + i];
        float bias = dwb[ch];
        for (int r = q*4; r < q*4 + 4; r++) {
            float acc8[8], cent[8];
            #pragma unroll
            for (int k = 0; k < 8; k++) acc8[k] = bias;
            #pragma unroll
            for (int dy = 0; dy < 5; dy++) {
                float v[12];
                int rowbase = ((r + dy)*12)*128 + ch;
                #pragma unroll
                for (int xx = 0; xx < 12; xx++)
                    v[xx] = __half2float(si[rowbase + xx*128]);
                #pragma unroll
                for (int k = 0; k < 8; k++)
                    #pragma unroll
                    for (int dx = 0; dx < 5; dx++)
                        acc8[k] += v[k + dx] * wreg[dy*5 + dx];
                if (dy == 2) {
                    #pragma unroll
                    for (int k = 0; k < 8; k++) cent[k] = v[k + 2];
                }
            }
            #pragma unroll
            for (int k = 0; k < 8; k++)
                fsm[(r*8 + k)*136 + ch] = __float2half(cent[k] + gelu(acc8[k]));
        }
    }
    __syncthreads();

    int lane = tid & 31, w = tid >> 5, g = lane >> 2, t = lane & 3;
    {
        int mt = w >> 1, nh = w & 1;
        int rb = (mt*16 + g)*136;
        float acc[4][4];
        #pragma unroll
        for (int nt = 0; nt < 4; nt++)
            #pragma unroll
            for (int i = 0; i < 4; i++) acc[nt][i] = 0.f;
        #pragma unroll
        for (int kc = 0; kc < 8; kc++) {
            unsigned a[4];
            a[0] = *(const unsigned*)&fsm[rb + kc*16 + 2*t];
            a[1] = *(const unsigned*)&fsm[rb + 8*136 + kc*16 + 2*t];
            a[2] = *(const unsigned*)&fsm[rb + kc*16 + 8 + 2*t];
            a[3] = *(const unsigned*)&fsm[rb + 8*136 + kc*16 + 8 + 2*t];
            #pragma unroll
            for (int nt = 0; nt < 4; nt++) {
                const __half* wb = fwh + (nh*32 + nt*8 + g)*136 + kc*16;
                unsigned b0 = *(const unsigned*)&wb[2*t];
                unsigned b1 = *(const unsigned*)&wb[8 + 2*t];
                mma_f16(acc[nt], a, b0, b1);
            }
        }
        __syncthreads();   // fsm consumed; si overlay becomes out tile
        int p0 = mt*16 + g, p1 = p0 + 8;
        int rr0 = p0 >> 3, kk0 = p0 & 7;
        int rr1 = p1 >> 3, kk1 = p1 & 7;
        size_t base = (size_t)b*HWSZ;
        #pragma unroll
        for (int nt = 0; nt < 4; nt++) {
            int col = nh*32 + nt*8 + 2*t;
            float2 bb = *(const float2*)&fc2b[col];
            float2 x0 = *(const float2*)&g_xs[(base + (size_t)(r0+rr0)*256 + c0 + kk0)*CC + col];
            float2 x1 = *(const float2*)&g_xs[(base + (size_t)(r0+rr1)*256 + c0 + kk1)*CC + col];
            tile[(col  )*68 + p0] = acc[nt][0] + bb.x + x0.x;
            tile[(col+1)*68 + p0] = acc[nt][1] + bb.y + x0.y;
            tile[(col  )*68 + p1] = acc[nt][2] + bb.x + x1.x;
            tile[(col+1)*68 + p1] = acc[nt][3] + bb.y + x1.y;
        }
    }
    __syncthreads();

    for (int idx = tid; idx < 2048; idx += 256) {
        int c = idx >> 5, pp = idx & 31;
        int r = pp >> 2, k2 = (pp & 3) * 2;
        *(float2*)&out[((size_t)(b*CC + c))*HWSZ + (size_t)(r0 + r)*256 + c0 + k2] =
            *(const float2*)&tile[c*68 + r*8 + k2];
    }
}

// ---------------- launch ---------------------------------------------------
#define KA_SMEM ((17408 + 6912 + 8704) * 4)
#define K4_SMEM ((256*68 + 4608) * 4)

extern "C" void kernel_launch(void* const* d_in, const int* in_sizes, int n_in,
                              void* d_out, int out_size)
{
    const float* x    = (const float*)d_in[0];
    const float* ln1g = (const float*)d_in[1];
    const float* ln1b = (const float*)d_in[2];
    const float* wq   = (const float*)d_in[3];
    const float* wk   = (const float*)d_in[4];
    const float* wv   = (const float*)d_in[5];
    const float* wo   = (const float*)d_in[6];
    const float* ln2g = (const float*)d_in[7];
    const float* ln2b = (const float*)d_in[8];
    const float* fc1w = (const float*)d_in[9];
    const float* fc1b = (const float*)d_in[10];
    const float* dww  = (const float*)d_in[11];
    const float* dwb  = (const float*)d_in[12];
    const float* fc2w = (const float*)d_in[13];
    const float* fc2b = (const float*)d_in[14];
    float* out = (float*)d_out;

    static int s_attr = 0;
    if (!s_attr) {
        cudaFuncSetAttribute(kA, cudaFuncAttributeMaxDynamicSharedMemorySize, KA_SMEM);
        cudaFuncSetAttribute(k4, cudaFuncAttributeMaxDynamicSharedMemorySize, K4_SMEM);
        cudaFuncSetAttribute(kB, cudaFuncAttributeMaxDynamicSharedMemorySize, KB_SMEM);
        s_attr = 1;
    }

    k_init<<<1, 256>>>();
    kA<<<BN, 512, KA_SMEM>>>(x, ln1g, ln1b, wq, wk, wv, wo);
    k4<<<(BB*HWSZ)/256, 512, K4_SMEM>>>(ln2g, ln2b, fc1w, fc1b);
    kB<<<BB*1024, 256, KB_SMEM>>>(dww, dwb, fc2w, fc2b, out);
}

// round 16
// speedup vs baseline: 4.9456x; 1.0997x over previous
#include <cuda_runtime.h>
#include <cuda_fp16.h>
#include <cuda_bf16.h>
#include <cstddef>

// ---------------- problem geometry (fixed by setup_inputs) ----------------
#define BB    2
#define CC    64
#define HH    256
#define WW    256
#define PP    16
#define STEP  14
#define NHP   19
#define NPAT  361
#define BN    722
#define LL    256
#define NHEAD 4
#define DHEAD 16
#define MLP   128
#define HWSZ  65536

#define QSCALE 0.36067376022224085f   // 0.25 * log2(e)

#define KSH  24                       // K fp16 row stride (halves)
#define VSH  272                      // V^T fp16 row stride (halves)
#define HSH  136                      // h fp16 row stride (halves) = 68 words
#define WSH  72                       // weight fp16 row stride (halves)

// ---------------- scratch (fp16 interchange everywhere) ----------
__device__ __half g_t [(size_t)BN*LL*CC];
__device__ __half g_o [(size_t)BN*LL*CC];
__device__ __half g_xs[(size_t)BB*HWSZ*CC];
__device__ __half g_h1[(size_t)BB*HWSZ*MLP];

__device__ int   d_cov_cnt[256];
__device__ int   d_cov_p[256][2];
__device__ int   d_cov_o[256][2];
__device__ float d_invdiv[256];

__global__ void k_init()
{
    int r = threadIdx.x;
    if (r < 256) {
        int cnt = 0;
        for (int ph = 0; ph < NHP; ph++) {
            int top = min(STEP*ph, HH-PP);
            if (r >= top && r < top + PP && cnt < 2) {
                d_cov_p[r][cnt] = ph;
                d_cov_o[r][cnt] = r - top;
                cnt++;
            }
        }
        d_cov_cnt[r] = cnt;
    }
    if (threadIdx.x == 0) {
        float div[256];
        for (int i = 0; i < 256; i++) div[i] = 1.f;
        for (int i = STEP; i < HH + STEP - PP; i += STEP) {
            int top = (i + PP > HH) ? (HH - PP) : i;
            for (int r2 = top; r2 < i + PP - STEP; ++r2) div[r2] *= 2.f;
        }
        for (int i = 0; i < 256; i++) d_invdiv[i] = 1.f / div[i];
    }
}

// ---------------- mma helpers ---------------------------------------------
__device__ __forceinline__ float ex2(float x) {
    float r; asm("ex2.approx.ftz.f32 %0, %1;" : "=f"(r) : "f"(x)); return r;
}
__device__ __forceinline__ unsigned packh2(float x, float y) {
    __half2 h = __floats2half2_rn(x, y);
    return *(unsigned*)&h;
}
__device__ __forceinline__ void mma_f16(float* d, const unsigned* a,
                                        unsigned b0, unsigned b1) {
    asm volatile("mma.sync.aligned.m16n8k16.row.col.f32.f16.f16.f32 "
        "{%0,%1,%2,%3},{%4,%5,%6,%7},{%8,%9},{%0,%1,%2,%3};"
        : "+f"(d[0]), "+f"(d[1]), "+f"(d[2]), "+f"(d[3])
        : "r"(a[0]), "r"(a[1]), "r"(a[2]), "r"(a[3]), "r"(b0), "r"(b1));
}
__device__ __forceinline__ float gelu(float x) {
    return 0.5f * x * (1.f + erff(x * 0.70710678118654752f));
}
// fp16 GEMM, warp = 16 rows x 64 cols, K=64: A-frags [4 kc][4], B = wm [j][WSH]
__device__ __forceinline__ void gemm64h(const unsigned aq[4][4],
                                        const __half* __restrict__ wm,
                                        int g, int t, float acc[8][4]) {
    #pragma unroll
    for (int nt = 0; nt < 8; nt++)
        #pragma unroll
        for (int i = 0; i < 4; i++) acc[nt][i] = 0.f;
    #pragma unroll
    for (int nt = 0; nt < 8; nt++)
        #pragma unroll
        for (int kc = 0; kc < 4; kc++) {
            const __half* wb = wm + (nt*8 + g)*WSH + kc*16;
            unsigned b0 = *(const unsigned*)&wb[2*t];
            unsigned b1 = *(const unsigned*)&wb[8 + 2*t];
            mma_f16(acc[nt], aq[kc], b0, b1);
        }
}

// ---------------- kA: gather + LN1 + QKV + attention + o@wo + t -----------
__global__ __launch_bounds__(512) void kA(const float* __restrict__ x,
                                          const float* __restrict__ g1,
                                          const float* __restrict__ b1,
                                          const float* __restrict__ wq,
                                          const float* __restrict__ wk,
                                          const float* __restrict__ wv,
                                          const float* __restrict__ wo)
{
    extern __shared__ float sm[];
    float*  ps    = sm;                               // 17408 words
    __half* wsh   = (__half*)(sm + 17408);            // 3*4608 halves = 6912 words
    __half* vsm_h = (__half*)(sm + 17408 + 6912);     // 8704 words
    __half* hsm_h = (__half*)ps;                      // h fp16 in place
    __half* ksm_h = (__half*)ps;                      // K fp16 after barrier A
    __half* woh   = wsh;                              // wo after barrier B

    int tid = threadIdx.x;
    int bn = blockIdx.x;
    int b  = bn / NPAT, n = bn % NPAT;
    int ph = n / NHP,   pw = n % NHP;
    int top  = min(STEP*ph, HH-PP);
    int left = min(STEP*pw, WW-PP);
    const float* xb = x + (size_t)b * CC * HWSZ;

    for (int idx = tid; idx < 3*64*64; idx += 512) {
        int mat = idx >> 12; int rem = idx & 4095;
        int c = rem >> 6, j = rem & 63;
        const float* w = (mat == 0) ? wq : (mat == 1) ? wk : wv;
        wsh[mat*4608 + j*WSH + c] = __float2half(w[rem]);
    }
    for (int idx = tid; idx < CC*LL; idx += 512) {
        int c = idx >> 8, l = idx & 255;
        int li = l >> 4, lj = l & 15;
        ps[l*68 + c] = xb[(size_t)c*HWSZ + (size_t)(top+li)*WW + (left+lj)];
    }
    __syncthreads();

    int lane = tid & 31, warp = tid >> 5;
    {
        float ga = g1[lane], gb = g1[lane+32], ba = b1[lane], bbv = b1[lane+32];
        for (int l = warp; l < LL; l += 16) {
            float v0 = ps[l*68 + lane], v1 = ps[l*68 + lane + 32];
            size_t tb = ((size_t)bn*LL + l) * CC;
            g_t[tb + lane]      = __float2half(v0);
            g_t[tb + lane + 32] = __float2half(v1);
            float s = v0 + v1, ss = v0*v0 + v1*v1;
            #pragma unroll
            for (int o = 16; o; o >>= 1) {
                s  += __shfl_xor_sync(0xffffffffu, s,  o);
                ss += __shfl_xor_sync(0xffffffffu, ss, o);
            }
            float mean = s * (1.f/64.f);
            float var  = ss * (1.f/64.f) - mean*mean;
            float rstd = rsqrtf(var + 1e-5f);
            hsm_h[l*HSH + lane]      = __float2half((v0 - mean) * rstd * ga + ba);
            hsm_h[l*HSH + lane + 32] = __float2half((v1 - mean) * rstd * gb + bbv);
        }
    }
    __syncthreads();

    int g = lane >> 2, t = lane & 3;
    unsigned aqh16[4][4];
    {
        int r0 = (warp*16 + g)*HSH;
        #pragma unroll
        for (int kc = 0; kc < 4; kc++) {
            int c0 = kc*16 + 2*t;
            aqh16[kc][0] = *(const unsigned*)&hsm_h[r0 + c0];
            aqh16[kc][1] = *(const unsigned*)&hsm_h[r0 + 8*HSH + c0];
            aqh16[kc][2] = *(const unsigned*)&hsm_h[r0 + c0 + 8];
            aqh16[kc][3] = *(const unsigned*)&hsm_h[r0 + 8*HSH + c0 + 8];
        }
    }
    __syncthreads();   // barrier A: ps free (becomes K fp16)

    {
        float acc[8][4];
        gemm64h(aqh16, wsh + 4608, g, t, acc);   // K -> fp16 [head][tok][KSH]
        #pragma unroll
        for (int nt = 0; nt < 8; nt++) {
            int tok = warp*16 + g;
            int hd  = nt >> 1;
            int d0  = (nt & 1)*8 + 2*t;
            __half* kp = ksm_h + hd*(LL*KSH) + tok*KSH + d0;
            *(__half2*)kp            = __floats2half2_rn(acc[nt][0], acc[nt][1]);
            *(__half2*)(kp + 8*KSH)  = __floats2half2_rn(acc[nt][2], acc[nt][3]);
        }
        gemm64h(aqh16, wsh + 2*4608, g, t, acc); // V -> fp16 V^T [d][tok]
        #pragma unroll
        for (int nt = 0; nt < 8; nt++) {
            int tok = warp*16 + g;
            int d0  = nt*8 + 2*t;
            __half* vp = vsm_h + d0*VSH;
            vp[tok]           = __float2half(acc[nt][0]);
            vp[VSH + tok]     = __float2half(acc[nt][1]);
            vp[tok + 8]       = __float2half(acc[nt][2]);
            vp[VSH + tok + 8] = __float2half(acc[nt][3]);
        }
    }
    float qacc[8][4];
    gemm64h(aqh16, wsh, g, t, qacc);             // Q (registers)
    __syncthreads();   // barrier B: K/V visible; wsh mat-0 writable

    for (int idx = tid; idx < 4096; idx += 512) {
        int c = idx >> 6, j = idx & 63;
        woh[j*WSH + c] = __float2half(wo[idx]);
    }

    float oall[4][2][4];
    #pragma unroll
    for (int head = 0; head < NHEAD; head++) {
        unsigned aqh[4];
        {
            int h2 = head*2;
            aqh[0] = packh2(qacc[h2  ][0]*QSCALE, qacc[h2  ][1]*QSCALE);
            aqh[1] = packh2(qacc[h2  ][2]*QSCALE, qacc[h2  ][3]*QSCALE);
            aqh[2] = packh2(qacc[h2+1][0]*QSCALE, qacc[h2+1][1]*QSCALE);
            aqh[3] = packh2(qacc[h2+1][2]*QSCALE, qacc[h2+1][3]*QSCALE);
        }
        const __half* kh = ksm_h + head*(LL*KSH);
        const __half* vh = vsm_h + head*16*VSH;
        float oh[2][4];
        #pragma unroll
        for (int nd = 0; nd < 2; nd++)
            #pragma unroll
            for (int i = 0; i < 4; i++) oh[nd][i] = 0.f;
        float mrow[2] = {-1e30f, -1e30f};
        float drow[2] = {0.f, 0.f};

        #pragma unroll 1
        for (int jt = 0; jt < 8; jt++) {
            float s[4][4];
            #pragma unroll
            for (int nt = 0; nt < 4; nt++)
                #pragma unroll
                for (int i = 0; i < 4; i++) s[nt][i] = 0.f;
            #pragma unroll
            for (int nt = 0; nt < 4; nt++) {
                const __half* kb = kh + (jt*32 + nt*8 + g)*KSH;
                unsigned b0 = *(const unsigned*)&kb[2*t];
                unsigned b1 = *(const unsigned*)&kb[8 + 2*t];
                mma_f16(s[nt], aqh, b0, b1);
            }
            #pragma unroll
            for (int h = 0; h < 2; h++) {
                float mx = fmaxf(s[0][h*2], s[0][h*2+1]);
                #pragma unroll
                for (int nt = 1; nt < 4; nt++)
                    mx = fmaxf(mx, fmaxf(s[nt][h*2], s[nt][h*2+1]));
                mx = fmaxf(mx, __shfl_xor_sync(0xffffffffu, mx, 1));
                mx = fmaxf(mx, __shfl_xor_sync(0xffffffffu, mx, 2));
                float mn = fmaxf(mrow[h], mx);
                float scale = ex2(mrow[h] - mn);
                mrow[h] = mn;
                drow[h] *= scale;
                #pragma unroll
                for (int nd = 0; nd < 2; nd++) {
                    oh[nd][h*2]   *= scale;
                    oh[nd][h*2+1] *= scale;
                }
                float psum = 0.f;
                #pragma unroll
                for (int nt = 0; nt < 4; nt++) {
                    float e0 = ex2(s[nt][h*2]   - mn);
                    float e1 = ex2(s[nt][h*2+1] - mn);
                    s[nt][h*2] = e0; s[nt][h*2+1] = e1;
                    psum += e0 + e1;
                }
                drow[h] += psum;
            }
            unsigned pa[2][4];
            #pragma unroll
            for (int kc = 0; kc < 2; kc++) {
                pa[kc][0] = packh2(s[2*kc  ][0], s[2*kc  ][1]);
                pa[kc][1] = packh2(s[2*kc  ][2], s[2*kc  ][3]);
                pa[kc][2] = packh2(s[2*kc+1][0], s[2*kc+1][1]);
                pa[kc][3] = packh2(s[2*kc+1][2], s[2*kc+1][3]);
            }
            #pragma unroll
            for (int nd = 0; nd < 2; nd++) {
                #pragma unroll
                for (int kc = 0; kc < 2; kc++) {
                    const __half* vb = vh + (nd*8 + g)*VSH + jt*32 + kc*16;
                    unsigned b0 = *(const unsigned*)&vb[2*t];
                    unsigned b1 = *(const unsigned*)&vb[2*t + 8];
                    mma_f16(oh[nd], pa[kc], b0, b1);
                }
            }
        }
        float inv[2];
        #pragma unroll
        for (int h = 0; h < 2; h++) {
            float d = drow[h];
            d += __shfl_xor_sync(0xffffffffu, d, 1);
            d += __shfl_xor_sync(0xffffffffu, d, 2);
            inv[h] = 1.f / d;
        }
        #pragma unroll
        for (int nd = 0; nd < 2; nd++) {
            oall[head][nd][0] = oh[nd][0]*inv[0];
            oall[head][nd][1] = oh[nd][1]*inv[0];
            oall[head][nd][2] = oh[nd][2]*inv[1];
            oall[head][nd][3] = oh[nd][3]*inv[1];
        }
    }
    __syncthreads();   // barrier C: wo fp16 visible

    {
        float acc[8][4];
        #pragma unroll
        for (int nt = 0; nt < 8; nt++)
            #pragma unroll
            for (int i = 0; i < 4; i++) acc[nt][i] = 0.f;
        #pragma unroll
        for (int kc = 0; kc < 4; kc++) {
            unsigned ao[4];
            ao[0] = packh2(oall[kc][0][0], oall[kc][0][1]);
            ao[1] = packh2(oall[kc][0][2], oall[kc][0][3]);
            ao[2] = packh2(oall[kc][1][0], oall[kc][1][1]);
            ao[3] = packh2(oall[kc][1][2], oall[kc][1][3]);
            #pragma unroll
            for (int nt = 0; nt < 8; nt++) {
                const __half* wb = woh + (nt*8 + g)*WSH + kc*16;
                unsigned b0 = *(const unsigned*)&wb[2*t];
                unsigned b1 = *(const unsigned*)&wb[8 + 2*t];
                mma_f16(acc[nt], ao, b0, b1);
            }
        }
        size_t row0 = (size_t)bn * LL;
        #pragma unroll
        for (int nt = 0; nt < 8; nt++) {
            int row = warp*16 + g, col = nt*8 + 2*t;
            size_t a0 = (row0 + row)*CC + col;
            size_t a1 = (row0 + row + 8)*CC + col;
            float2 t0 = __half22float2(*(const __half2*)&g_t[a0]);
            float2 t1 = __half22float2(*(const __half2*)&g_t[a1]);
            *(__half2*)&g_o[a0] = __floats2half2_rn(acc[nt][0] + t0.x, acc[nt][1] + t0.y);
            *(__half2*)&g_o[a1] = __floats2half2_rn(acc[nt][2] + t1.x, acc[nt][3] + t1.y);
        }
    }
}

// ---------------- K4: patch_reverse gather + LN2 + fc1 + GELU -------------
// block = 128 pixels (half image row), 256 thr, 3 blocks/SM. smem 44 KB.
__global__ __launch_bounds__(256, 3) void k4(const float* __restrict__ g2,
                                             const float* __restrict__ b2,
                                             const float* __restrict__ fc1w,
                                             const float* __restrict__ fc1b)
{
    extern __shared__ float sm4[];
    float*  xsm = sm4;                        // 128*68 fp32 -> fp16 in place
    __half* fwh = (__half*)(sm4 + 128*68);    // 128 j x WSH = 9216 halves
    __half* hsm_h = (__half*)xsm;
    int tid = threadIdx.x;
    size_t pix0 = (size_t)blockIdx.x * 128;
    int b4    = (int)(pix0 >> 16);
    int rrow  = (int)((pix0 & 65535) >> 8);
    int cbase = (int)(pix0 & 255);            // 0 or 128

    {
        int hc = d_cov_cnt[rrow];
        float idr = d_invdiv[rrow];
        for (int idx = tid; idx < 2048; idx += 256) {
            int row = idx >> 4, c4 = (idx & 15) * 4;
            int wcol = cbase + row;
            float4 a4; a4.x = 0.f; a4.y = 0.f; a4.z = 0.f; a4.w = 0.f;
            int wc2 = d_cov_cnt[wcol];
            for (int i = 0; i < hc; i++) {
                int n0 = d_cov_p[rrow][i]*NHP, l0 = d_cov_o[rrow][i]*PP;
                for (int k = 0; k < wc2; k++) {
                    int n = n0 + d_cov_p[wcol][k];
                    int l = l0 + d_cov_o[wcol][k];
                    uint2 v = *(const uint2*)&g_o[(((size_t)(b4*NPAT + n))*LL + l)*CC + c4];
                    float2 f0 = __half22float2(*(__half2*)&v.x);
                    float2 f1 = __half22float2(*(__half2*)&v.y);
                    a4.x += f0.x; a4.y += f0.y; a4.z += f1.x; a4.w += f1.y;
                }
            }
            float sc = idr * d_invdiv[wcol];
            a4.x *= sc; a4.y *= sc; a4.z *= sc; a4.w *= sc;
            *(float4*)&xsm[row*68 + c4] = a4;
            uint2 o2;
            *(__half2*)&o2.x = __floats2half2_rn(a4.x, a4.y);
            *(__half2*)&o2.y = __floats2half2_rn(a4.z, a4.w);
            *(uint2*)&g_xs[(pix0 + row)*CC + c4] = o2;
        }
    }
    for (int idx = tid; idx < 8192; idx += 256) {
        int c = idx >> 7, j = idx & 127;
        fwh[j*WSH + c] = __float2half(fc1w[idx]);
    }
    __syncthreads();

    int lane = tid & 31, warp = tid >> 5;
    float ga = g2[lane], gb = g2[lane+32], ba = b2[lane], bbv = b2[lane+32];
    for (int r = warp; r < 128; r += 8) {
        float v0 = xsm[r*68+lane], v1 = xsm[r*68+lane+32];
        float s = v0+v1, ss = v0*v0+v1*v1;
        #pragma unroll
        for (int o = 16; o; o >>= 1) {
            s  += __shfl_xor_sync(0xffffffffu, s,  o);
            ss += __shfl_xor_sync(0xffffffffu, ss, o);
        }
        float mean = s * (1.f/64.f);
        float var  = ss * (1.f/64.f) - mean*mean;
        float rstd = rsqrtf(var + 1e-5f);
        hsm_h[r*HSH + lane]      = __float2half((v0 - mean) * rstd * ga + ba);
        hsm_h[r*HSH + lane + 32] = __float2half((v1 - mean) * rstd * gb + bbv);
    }
    __syncthreads();

    int g = lane >> 2, t = lane & 3;
    int r0 = (warp*16 + g)*HSH;
    unsigned aq[4][4];
    #pragma unroll
    for (int kc = 0; kc < 4; kc++) {
        int c0 = kc*16 + 2*t;
        aq[kc][0] = *(const unsigned*)&hsm_h[r0 + c0];
        aq[kc][1] = *(const unsigned*)&hsm_h[r0 + 8*HSH + c0];
        aq[kc][2] = *(const unsigned*)&hsm_h[r0 + c0 + 8];
        aq[kc][3] = *(const unsigned*)&hsm_h[r0 + 8*HSH + c0 + 8];
    }
    #pragma unroll 1
    for (int pass = 0; pass < 2; pass++) {
        float acc[8][4];
        #pragma unroll
        for (int nt = 0; nt < 8; nt++) {
            float2 bb = *(const float2*)&fc1b[pass*64 + nt*8 + 2*t];
            acc[nt][0] = bb.x; acc[nt][1] = bb.y; acc[nt][2] = bb.x; acc[nt][3] = bb.y;
        }
        #pragma unroll
        for (int nt = 0; nt < 8; nt++)
            #pragma unroll
            for (int kc = 0; kc < 4; kc++) {
                const __half* wb = fwh + (pass*64 + nt*8 + g)*WSH + kc*16;
                unsigned b0 = *(const unsigned*)&wb[2*t];
                unsigned b1 = *(const unsigned*)&wb[8 + 2*t];
                mma_f16(acc[nt], aq[kc], b0, b1);
            }
        #pragma unroll
        for (int nt = 0; nt < 8; nt++) {
            int row = warp*16 + g, col = pass*64 + nt*8 + 2*t;
            __half2 h0 = __floats2half2_rn(gelu(acc[nt][0]), gelu(acc[nt][1]));
            __half2 h1 = __floats2half2_rn(gelu(acc[nt][2]), gelu(acc[nt][3]));
            *(__half2*)&g_h1[(pix0 + row)*MLP + col]     = h0;
            *(__half2*)&g_h1[(pix0 + row + 8)*MLP + col] = h1;
        }
    }
}

// ---------------- kB: dwconv 5x5 + GELU + residual + fc2 + store ----------
#define KB_SI_BYTES   36864
#define KB_FSM_BYTES  17408
#define KB_FW_BYTES   17408
#define KB_SMEM (KB_SI_BYTES + KB_FSM_BYTES + KB_FW_BYTES)
__global__ __launch_bounds__(256, 3) void kB(const float* __restrict__ dww,
                                             const float* __restrict__ dwb,
                                             const float* __restrict__ fc2w,
                                             const float* __restrict__ fc2b,
                                             float* __restrict__ out)
{
    extern __shared__ char smB[];
    __half* si  = (__half*)smB;
    __half* fsm = (__half*)(smB + KB_SI_BYTES);
    __half* fwh = (__half*)(smB + KB_SI_BYTES + KB_FSM_BYTES);
    float*  tile = (float*)smB;              // overlay si (dead after conv)

    int tid = threadIdx.x;
    int bx = blockIdx.x;
    int b  = bx >> 10;
    int tr = (bx >> 5) & 31, tc = bx & 31;
    int r0 = tr*8, c0 = tc*8;

    const uint4* h1v = (const uint4*)(g_h1 + (size_t)b * HWSZ * MLP);
    for (int idx = tid; idx < 144*16; idx += 256) {
        int p = idx >> 4, u = idx & 15;
        int hr = p / 12, hc = p % 12;
        int gr = r0 + hr - 2, gc = c0 + hc - 2;
        uint4 v = {0u, 0u, 0u, 0u};
        if (gr >= 0 && gr < 256 && gc >= 0 && gc < 256)
            v = h1v[(size_t)(gr*256 + gc)*16 + u];
        *(uint4*)&si[p*128 + u*8] = v;
    }
    for (int idx = tid; idx < 8192; idx += 256) {
        int c = idx >> 6, j = idx & 63;
        fwh[j*136 + c] = __float2half(fc2w[idx]);
    }
    __syncthreads();

    {
        int ch = tid & 127, q = tid >> 7;
        float wreg[25];
        #pragma unroll
        for (int i = 0; i < 25; i++) wreg[i] = dww[ch*25 + i];
        float bias = dwb[ch];
        for (int r = q*4; r < q*4 + 4; r++) {
            float acc8[8], cent[8];
            #pragma unroll
            for (int k = 0; k < 8; k++) acc8[k] = bias;
            #pragma unroll
            for (int dy = 0; dy < 5; dy++) {
                float v[12];
                int rowbase = ((r + dy)*12)*128 + ch;
                #pragma unroll
                for (int xx = 0; xx < 12; xx++)
                    v[xx] = __half2float(si[rowbase + xx*128]);
                #pragma unroll
                for (int k = 0; k < 8; k++)
                    #pragma unroll
                    for (int dx = 0; dx < 5; dx++)
                        acc8[k] += v[k + dx] * wreg[dy*5 + dx];
                if (dy == 2) {
                    #pragma unroll
                    for (int k = 0; k < 8; k++) cent[k] = v[k + 2];
                }
            }
            #pragma unroll
            for (int k = 0; k < 8; k++)
                fsm[(r*8 + k)*136 + ch] = __float2half(cent[k] + gelu(acc8[k]));
        }
    }
    __syncthreads();

    int lane = tid & 31, w = tid >> 5, g = lane >> 2, t = lane & 3;
    {
        int mt = w >> 1, nh = w & 1;
        int rb = (mt*16 + g)*136;
        float acc[4][4];
        #pragma unroll
        for (int nt = 0; nt < 4; nt++)
            #pragma unroll
            for (int i = 0; i < 4; i++) acc[nt][i] = 0.f;
        #pragma unroll
        for (int kc = 0; kc < 8; kc++) {
            unsigned a[4];
            a[0] = *(const unsigned*)&fsm[rb + kc*16 + 2*t];
            a[1] = *(const unsigned*)&fsm[rb + 8*136 + kc*16 + 2*t];
            a[2] = *(const unsigned*)&fsm[rb + kc*16 + 8 + 2*t];
            a[3] = *(const unsigned*)&fsm[rb + 8*136 + kc*16 + 8 + 2*t];
            #pragma unroll
            for (int nt = 0; nt < 4; nt++) {
                const __half* wb = fwh + (nh*32 + nt*8 + g)*136 + kc*16;
                unsigned b0 = *(const unsigned*)&wb[2*t];
                unsigned b1 = *(const unsigned*)&wb[8 + 2*t];
                mma_f16(acc[nt], a, b0, b1);
            }
        }
        __syncthreads();   // fsm consumed; si overlay becomes out tile
        int p0 = mt*16 + g, p1 = p0 + 8;
        int rr0 = p0 >> 3, kk0 = p0 & 7;
        int rr1 = p1 >> 3, kk1 = p1 & 7;
        size_t base = (size_t)b*HWSZ;
        #pragma unroll
        for (int nt = 0; nt < 4; nt++) {
            int col = nh*32 + nt*8 + 2*t;
            float2 bb = *(const float2*)&fc2b[col];
            float2 x0 = __half22float2(*(const __half2*)
                &g_xs[(base + (size_t)(r0+rr0)*256 + c0 + kk0)*CC + col]);
            float2 x1 = __half22float2(*(const __half2*)
                &g_xs[(base + (size_t)(r0+rr1)*256 + c0 + kk1)*CC + col]);
            tile[(col  )*68 + p0] = acc[nt][0] + bb.x + x0.x;
            tile[(col+1)*68 + p0] = acc[nt][1] + bb.y + x0.y;
            tile[(col  )*68 + p1] = acc[nt][2] + bb.x + x1.x;
            tile[(col+1)*68 + p1] = acc[nt][3] + bb.y + x1.y;
        }
    }
    __syncthreads();

    for (int idx = tid; idx < 2048; idx += 256) {
        int c = idx >> 5, pp = idx & 31;
        int r = pp >> 2, k2 = (pp & 3) * 2;
        *(float2*)&out[((size_t)(b*CC + c))*HWSZ + (size_t)(r0 + r)*256 + c0 + k2] =
            *(const float2*)&tile[c*68 + r*8 + k2];
    }
}

// ---------------- launch ---------------------------------------------------
#define KA_SMEM ((17408 + 6912 + 8704) * 4)
#define K4_SMEM ((128*68 + 4608) * 4)

extern "C" void kernel_launch(void* const* d_in, const int* in_sizes, int n_in,
                              void* d_out, int out_size)
{
    const float* x    = (const float*)d_in[0];
    const float* ln1g = (const float*)d_in[1];
    const float* ln1b = (const float*)d_in[2];
    const float* wq   = (const float*)d_in[3];
    const float* wk   = (const float*)d_in[4];
    const float* wv   = (const float*)d_in[5];
    const float* wo   = (const float*)d_in[6];
    const float* ln2g = (const float*)d_in[7];
    const float* ln2b = (const float*)d_in[8];
    const float* fc1w = (const float*)d_in[9];
    const float* fc1b = (const float*)d_in[10];
    const float* dww  = (const float*)d_in[11];
    const float* dwb  = (const float*)d_in[12];
    const float* fc2w = (const float*)d_in[13];
    const float* fc2b = (const float*)d_in[14];
    float* out = (float*)d_out;

    static int s_attr = 0;
    if (!s_attr) {
        cudaFuncSetAttribute(kA, cudaFuncAttributeMaxDynamicSharedMemorySize, KA_SMEM);
        cudaFuncSetAttribute(k4, cudaFuncAttributeMaxDynamicSharedMemorySize, K4_SMEM);
        cudaFuncSetAttribute(kB, cudaFuncAttributeMaxDynamicSharedMemorySize, KB_SMEM);
        s_attr = 1;
    }

    k_init<<<1, 256>>>();
    kA<<<BN, 512, KA_SMEM>>>(x, ln1g, ln1b, wq, wk, wv, wo);
    k4<<<(BB*HWSZ)/128, 256, K4_SMEM>>>(ln2g, ln2b, fc1w, fc1b);
    kB<<<BB*1024, 256, KB_SMEM>>>(dww, dwb, fc2w, fc2b, out);
}